// round 1
// baseline (speedup 1.0000x reference)
#include <cuda_runtime.h>
#include <math.h>

#define BB 2
#define NN 2048
#define TT 256
#define DD 128
#define KK 16
#define NTOT (BB*NN)

// ---------------- scratch (no allocations allowed) ----------------
__device__ float g_u   [NTOT*DD];
__device__ float g_u2  [NTOT*DD];
__device__ float g_base[NTOT*DD];
__device__ float g_proj[NTOT*DD];
__device__ float g_loc [NTOT*DD];
__device__ int   g_idx [NTOT*KK];

// ---------------- Kernel 1: TemporalLift (conv1d->relu->mean->fc->relu) ----
__global__ void __launch_bounds__(128) k_lift(
    const float* __restrict__ spikes, const float* __restrict__ conv_w,
    const float* __restrict__ conv_b, const float* __restrict__ fc_w,
    const float* __restrict__ fc_b, float* __restrict__ u)
{
    __shared__ float sp[TT+4];
    __shared__ float xm[DD];
    int node = blockIdx.x;
    int h = threadIdx.x;
    const float* s = spikes + (size_t)node*TT;
    sp[2+h]      = s[h];
    sp[2+h+128]  = s[h+128];
    if (h < 2) { sp[h] = 0.f; sp[TT+2+h] = 0.f; }
    __syncthreads();
    float w0 = conv_w[h*5+0], w1 = conv_w[h*5+1], w2 = conv_w[h*5+2],
          w3 = conv_w[h*5+3], w4 = conv_w[h*5+4];
    float bb = conv_b[h];
    float acc = 0.f;
    #pragma unroll 8
    for (int t = 0; t < TT; t++) {
        float v = fmaf(w0, sp[t],
                  fmaf(w1, sp[t+1],
                  fmaf(w2, sp[t+2],
                  fmaf(w3, sp[t+3],
                  fmaf(w4, sp[t+4], bb)))));
        acc += fmaxf(v, 0.f);
    }
    xm[h] = acc * (1.f/(float)TT);
    __syncthreads();
    float o = fc_b[h];
    #pragma unroll 8
    for (int j = 0; j < DD; j++) o = fmaf(xm[j], __ldg(&fc_w[j*DD+h]), o);
    u[(size_t)node*DD + h] = fmaxf(o, 0.f);
}

// ---------------- Kernel 2: kNN (top-16 smallest dist2, tie-break by index) -
__global__ void __launch_bounds__(256) k_knn(
    const float* __restrict__ coords, int* __restrict__ idx)
{
    __shared__ float c[NN];
    int b = blockIdx.y;
    int i = blockIdx.x*256 + threadIdx.x;
    const float* cb = coords + (size_t)b*NN;
    for (int j = threadIdx.x; j < NN; j += 256) c[j] = cb[j];
    __syncthreads();
    float ci = c[i];
    float d2[KK]; int id[KK];
    #pragma unroll
    for (int p = 0; p < KK; p++) { d2[p] = 3.4e38f; id[p] = 0x7fffffff; }
    for (int j = 0; j < NN; j++) {
        float df = ci - c[j];
        float nd = df*df;
        if (nd < d2[KK-1] || (nd == d2[KK-1] && j < id[KK-1])) {
            d2[KK-1] = nd; id[KK-1] = j;
            #pragma unroll
            for (int p = KK-1; p > 0; --p) {
                bool sw = (d2[p] < d2[p-1]) || (d2[p] == d2[p-1] && id[p] < id[p-1]);
                if (!sw) break;
                float td = d2[p]; d2[p] = d2[p-1]; d2[p-1] = td;
                int   ti = id[p]; id[p] = id[p-1]; id[p-1] = ti;
            }
        }
    }
    int* o = idx + ((size_t)b*NN + i)*KK;
    #pragma unroll
    for (int p = 0; p < KK; p++) o[p] = id[p];
}

// ---------------- Kernel 3: node GEMM Y = X@W (+colbias +xs[n]*rowvec) ------
// 32 rows x 128 cols per block; optionally two W/Y pairs sharing the X tile.
template<bool HAS2>
__global__ void __launch_bounds__(256) k_gemm(
    const float* __restrict__ X, const float* __restrict__ W1,
    const float* __restrict__ W2, const float* __restrict__ cb1,
    const float* __restrict__ rv1, const float* __restrict__ rv2,
    const float* __restrict__ xs,
    float* __restrict__ Y1, float* __restrict__ Y2)
{
    __shared__ float Xs[32*DD];
    __shared__ float xc[32];
    int tid = threadIdx.x;
    int row0 = blockIdx.x * 32;
    const float4* Xg = (const float4*)(X + (size_t)row0*DD);
    float4* Xs4 = (float4*)Xs;
    #pragma unroll
    for (int i = 0; i < 4; i++) Xs4[tid + i*256] = Xg[tid + i*256];
    if (tid < 32) xc[tid] = xs ? xs[row0+tid] : 0.f;
    __syncthreads();
    int tx = tid & 31, ty = tid >> 5;
    float a1[4][4] = {};
    float a2[4][4] = {};
    const float4* W1v = (const float4*)W1;
    const float4* W2v = (const float4*)W2;
    #pragma unroll 4
    for (int k = 0; k < DD; k++) {
        float4 b1 = __ldg(&W1v[k*32 + tx]);
        float4 b2;
        if (HAS2) b2 = __ldg(&W2v[k*32 + tx]);
        #pragma unroll
        for (int i = 0; i < 4; i++) {
            float a = Xs[(ty*4+i)*DD + k];
            a1[i][0] = fmaf(a,b1.x,a1[i][0]);
            a1[i][1] = fmaf(a,b1.y,a1[i][1]);
            a1[i][2] = fmaf(a,b1.z,a1[i][2]);
            a1[i][3] = fmaf(a,b1.w,a1[i][3]);
            if (HAS2) {
                a2[i][0] = fmaf(a,b2.x,a2[i][0]);
                a2[i][1] = fmaf(a,b2.y,a2[i][1]);
                a2[i][2] = fmaf(a,b2.z,a2[i][2]);
                a2[i][3] = fmaf(a,b2.w,a2[i][3]);
            }
        }
    }
    int c0 = tx*4;
    float4 cbv = cb1 ? *(const float4*)(cb1 + c0) : make_float4(0.f,0.f,0.f,0.f);
    float4 r1  = rv1 ? *(const float4*)(rv1 + c0) : make_float4(0.f,0.f,0.f,0.f);
    float4 r2  = make_float4(0.f,0.f,0.f,0.f);
    if (HAS2 && rv2) r2 = *(const float4*)(rv2 + c0);
    #pragma unroll
    for (int i = 0; i < 4; i++) {
        int r = ty*4 + i;
        float xv = xc[r];
        float4 o;
        o.x = a1[i][0] + cbv.x + xv*r1.x;
        o.y = a1[i][1] + cbv.y + xv*r1.y;
        o.z = a1[i][2] + cbv.z + xv*r1.z;
        o.w = a1[i][3] + cbv.w + xv*r1.w;
        *(float4*)(Y1 + (size_t)(row0+r)*DD + c0) = o;
        if (HAS2) {
            float4 o2;
            o2.x = a2[i][0] + xv*r2.x;
            o2.y = a2[i][1] + xv*r2.y;
            o2.z = a2[i][2] + xv*r2.z;
            o2.w = a2[i][3] + xv*r2.w;
            *(float4*)(Y2 + (size_t)(row0+r)*DD + c0) = o2;
        }
    }
}

// ---------------- Kernel 4: edge MLP + aggregation + residual (per layer) ---
// Block = 4 nodes (64 edges). h1 = relu(base_i + proj_j); h2 = relu(h1@k2+b2);
// Kv = (h2@k3 + b3)*0.25; agg = sum_k Kv*u_j; u' = relu(loc + agg + u).
#define EDGE_SMEM_FLOATS (16384 + 8192 + 512 + 2112 + 64 + 64)
__global__ void __launch_bounds__(256) k_edge(
    const float* __restrict__ u_in, float* __restrict__ u_out,
    const float* __restrict__ base, const float* __restrict__ proj,
    const float* __restrict__ loc, const int* __restrict__ idx,
    const float* __restrict__ k2w, const float* __restrict__ k2b,
    const float* __restrict__ k3w, const float* __restrict__ k3b)
{
    extern __shared__ float sm[];
    float* k2s = sm;                 // 16384
    float* h1s = sm + 16384;         // 8192
    float* bss = sm + 24576;         // 512
    float* kvp = sm + 25088;         // 64*33
    float* kvv = sm + 27200;         // 64
    int*   js  = (int*)(sm + 27264); // 64

    int tid = threadIdx.x;
    int node0 = blockIdx.x * 4;
    int bbase = (node0 >> 11) << 11;   // batch start node (N=2048)

    const float4* k2g = (const float4*)k2w;
    float4* k2s4 = (float4*)k2s;
    #pragma unroll
    for (int i = 0; i < 16; i++) k2s4[tid + i*256] = k2g[tid + i*256];
    if (tid < 128)
        ((float4*)bss)[tid] = ((const float4*)(base + (size_t)node0*DD))[tid];
    if (tid < 64) js[tid] = idx[node0*KK + tid];
    __syncthreads();

    // build h1 = relu(base_i + proj_j)
    {
        int lane = tid & 31;
        int wrp  = tid >> 5;
        for (int e = wrp; e < 64; e += 8) {
            int j = js[e];
            float4 p  = ((const float4*)(proj + ((size_t)(bbase + j))*DD))[lane];
            float4 bq = ((float4*)bss)[(e>>4)*32 + lane];
            float4 h;
            h.x = fmaxf(p.x+bq.x, 0.f);
            h.y = fmaxf(p.y+bq.y, 0.f);
            h.z = fmaxf(p.z+bq.z, 0.f);
            h.w = fmaxf(p.w+bq.w, 0.f);
            ((float4*)h1s)[e*32 + lane] = h;
        }
    }
    __syncthreads();

    // GEMM: [64 edges x 128] @ [128 x 128]
    int tx = tid & 31, ty = tid >> 5;
    float acc[8][4] = {};
    #pragma unroll 4
    for (int k = 0; k < DD; k++) {
        float4 b4 = ((float4*)k2s)[k*32 + tx];
        #pragma unroll
        for (int i = 0; i < 8; i++) {
            float a = h1s[(ty*8+i)*DD + k];
            acc[i][0] = fmaf(a,b4.x,acc[i][0]);
            acc[i][1] = fmaf(a,b4.y,acc[i][1]);
            acc[i][2] = fmaf(a,b4.z,acc[i][2]);
            acc[i][3] = fmaf(a,b4.w,acc[i][3]);
        }
    }
    int c0 = tx*4;
    float4 b2v = *(const float4*)(k2b + c0);
    float4 k3v = *(const float4*)(k3w + c0);
    #pragma unroll
    for (int i = 0; i < 8; i++) {
        float kp = fmaxf(acc[i][0]+b2v.x,0.f)*k3v.x
                 + fmaxf(acc[i][1]+b2v.y,0.f)*k3v.y
                 + fmaxf(acc[i][2]+b2v.z,0.f)*k3v.z
                 + fmaxf(acc[i][3]+b2v.w,0.f)*k3v.w;
        kvp[(ty*8+i)*33 + tx] = kp;
    }
    __syncthreads();
    if (tid < 64) {
        float s = 0.f;
        #pragma unroll
        for (int x = 0; x < 32; x++) s += kvp[tid*33+x];
        kvv[tid] = (s + k3b[0]) * 0.25f;   // * 1/sqrt(16)
    }
    __syncthreads();

    // agg + residual + relu
    int d  = tid & 127;
    int gh = tid >> 7;
    #pragma unroll
    for (int gg = 0; gg < 4; gg += 2) {
        int g = gg + gh;
        int n = node0 + g;
        float a = 0.f;
        #pragma unroll
        for (int kk = 0; kk < KK; kk++) {
            int j = js[g*KK + kk];
            a = fmaf(kvv[g*KK+kk], u_in[((size_t)(bbase+j))*DD + d], a);
        }
        float o = loc[(size_t)n*DD + d] + a + u_in[(size_t)n*DD + d];
        u_out[(size_t)n*DD + d] = fmaxf(o, 0.f);
    }
}

// ---------------- Kernel 5: decoder tile GEMM + sigmoid/softplus epilogue ---
#define DEC_SMEM_FLOATS (8192*3)
__global__ void __launch_bounds__(256) k_dec(
    const float* __restrict__ v, const float* __restrict__ w,
    const float* __restrict__ u, float* __restrict__ out)
{
    extern __shared__ float sm[];
    float* vs = sm;            // [64][128]
    float* ws = sm + 8192;     // [64][128]
    float* ut = sm + 16384;    // transposed [128][64]
    int tid = threadIdx.x;
    int bx = blockIdx.x, by = blockIdx.y, bz = blockIdx.z;
    size_t nb = (size_t)bz * NN;

    const float4* vg = (const float4*)(v + (nb + by*64)*DD);
    const float4* wg = (const float4*)(w + (nb + by*64)*DD);
    #pragma unroll
    for (int i = 0; i < 8; i++) {
        ((float4*)vs)[tid + i*256] = vg[tid + i*256];
        ((float4*)ws)[tid + i*256] = wg[tid + i*256];
    }
    #pragma unroll
    for (int i = 0; i < 8; i++) {
        int ii = tid + i*256;
        int m = ii >> 5, kq = ii & 31;
        float4 t = ((const float4*)(u + (nb + bx*64 + m)*DD))[kq];
        ut[(kq*4+0)*64 + m] = t.x;
        ut[(kq*4+1)*64 + m] = t.y;
        ut[(kq*4+2)*64 + m] = t.z;
        ut[(kq*4+3)*64 + m] = t.w;
    }
    __syncthreads();

    int tx = tid & 15, ty = tid >> 4;
    float aV[4][4] = {};
    float aW[4][4] = {};
    #pragma unroll 2
    for (int kq = 0; kq < 32; kq++) {
        float4 bb[4];
        #pragma unroll
        for (int kk = 0; kk < 4; kk++) bb[kk] = ((float4*)ut)[(kq*4+kk)*16 + tx];
        #pragma unroll
        for (int i = 0; i < 4; i++) {
            float4 x1 = ((float4*)vs)[(ty*4+i)*32 + kq];
            float4 x2 = ((float4*)ws)[(ty*4+i)*32 + kq];
            #pragma unroll
            for (int j = 0; j < 4; j++) {
                float bj;
                bj = (&bb[0].x)[j];
                aV[i][j] = fmaf(x1.x, bj, aV[i][j]);
                aW[i][j] = fmaf(x2.x, bj, aW[i][j]);
                bj = (&bb[1].x)[j];
                aV[i][j] = fmaf(x1.y, bj, aV[i][j]);
                aW[i][j] = fmaf(x2.y, bj, aW[i][j]);
                bj = (&bb[2].x)[j];
                aV[i][j] = fmaf(x1.z, bj, aV[i][j]);
                aW[i][j] = fmaf(x2.z, bj, aW[i][j]);
                bj = (&bb[3].x)[j];
                aV[i][j] = fmaf(x1.w, bj, aV[i][j]);
                aW[i][j] = fmaf(x2.w, bj, aW[i][j]);
            }
        }
    }

    size_t N2 = (size_t)NN*NN;
    size_t S  = (size_t)BB*N2;
    #pragma unroll
    for (int i = 0; i < 4; i++) {
        int rn = by*64 + ty*4 + i;
        size_t o = (size_t)bz*N2 + (size_t)rn*NN + bx*64 + tx*4;
        float4 lg = make_float4(aV[i][0], aV[i][1], aV[i][2], aV[i][3]);
        *(float4*)(out + o) = lg;
        float4 pr;
        pr.x = 1.f/(1.f+expf(-lg.x));
        pr.y = 1.f/(1.f+expf(-lg.y));
        pr.z = 1.f/(1.f+expf(-lg.z));
        pr.w = 1.f/(1.f+expf(-lg.w));
        *(float4*)(out + S + o) = pr;
        float4 wt;
        wt.x = fmaxf(aW[i][0],0.f) + log1pf(expf(-fabsf(aW[i][0])));
        wt.y = fmaxf(aW[i][1],0.f) + log1pf(expf(-fabsf(aW[i][1])));
        wt.z = fmaxf(aW[i][2],0.f) + log1pf(expf(-fabsf(aW[i][2])));
        wt.w = fmaxf(aW[i][3],0.f) + log1pf(expf(-fabsf(aW[i][3])));
        *(float4*)(out + 2*S + o) = wt;
    }
}

// ---------------- launch -----------------------------------------------------
extern "C" void kernel_launch(void* const* d_in, const int* in_sizes, int n_in,
                              void* d_out, int out_size)
{
    const float* spikes   = (const float*)d_in[0];
    const float* coords   = (const float*)d_in[1];
    const float* conv_w   = (const float*)d_in[2];
    const float* conv_b   = (const float*)d_in[3];
    const float* fc_w     = (const float*)d_in[4];
    const float* fc_b     = (const float*)d_in[5];
    const float* local_w  = (const float*)d_in[6];
    const float* local_b  = (const float*)d_in[7];
    const float* k1_w     = (const float*)d_in[8];
    const float* k1_b     = (const float*)d_in[9];
    const float* k2_w     = (const float*)d_in[10];
    const float* k2_b     = (const float*)d_in[11];
    const float* k3_w     = (const float*)d_in[12];
    const float* k3_b     = (const float*)d_in[13];
    const float* W_logits = (const float*)d_in[14];
    const float* W_weight = (const float*)d_in[15];
    float* out = (float*)d_out;

    float *u0, *u1, *pb, *pp, *pl; int* pix;
    cudaGetSymbolAddress((void**)&u0,  g_u);
    cudaGetSymbolAddress((void**)&u1,  g_u2);
    cudaGetSymbolAddress((void**)&pb,  g_base);
    cudaGetSymbolAddress((void**)&pp,  g_proj);
    cudaGetSymbolAddress((void**)&pl,  g_loc);
    cudaGetSymbolAddress((void**)&pix, g_idx);

    const int EDGE_SMEM = EDGE_SMEM_FLOATS * 4;
    const int DEC_SMEM  = DEC_SMEM_FLOATS * 4;
    cudaFuncSetAttribute(k_edge, cudaFuncAttributeMaxDynamicSharedMemorySize, EDGE_SMEM);
    cudaFuncSetAttribute(k_dec,  cudaFuncAttributeMaxDynamicSharedMemorySize, DEC_SMEM);

    k_lift<<<NTOT, 128>>>(spikes, conv_w, conv_b, fc_w, fc_b, u0);
    k_knn<<<dim3(NN/256, BB), 256>>>(coords, pix);

    float* ucur = u0;
    float* unext = u1;
    for (int l = 0; l < 3; l++) {
        const float* W1 = k1_w + (size_t)l*258*DD;
        // base = x*row0 + u@W[2:130] + b1 ; proj = x*row1 + u@W[130:258]
        k_gemm<true><<<NTOT/32, 256>>>(ucur, W1 + 2*DD, W1 + 130*DD,
                                       k1_b + l*DD, W1, W1 + DD, coords, pb, pp);
        // loc = u@local_w + local_b
        k_gemm<false><<<NTOT/32, 256>>>(ucur, local_w + (size_t)l*DD*DD, nullptr,
                                        local_b + l*DD, nullptr, nullptr, nullptr,
                                        pl, nullptr);
        k_edge<<<NTOT/4, 256, EDGE_SMEM>>>(ucur, unext, pb, pp, pl, pix,
                                           k2_w + (size_t)l*DD*DD, k2_b + l*DD,
                                           k3_w + (size_t)l*DD, k3_b + l);
        float* t = ucur; ucur = unext; unext = t;
    }

    // decoder stage 1: v = u@W_logits, w = u@W_weight (shared X tile)
    k_gemm<true><<<NTOT/32, 256>>>(ucur, W_logits, W_weight,
                                   nullptr, nullptr, nullptr, nullptr, pb, pp);
    // decoder stage 2 + epilogue
    k_dec<<<dim3(NN/64, NN/64, BB), 256, DEC_SMEM>>>(pb, pp, ucur, out);
}

// round 2
// speedup vs baseline: 1.0190x; 1.0190x over previous
#include <cuda_runtime.h>
#include <math.h>

#define BB 2
#define NN 2048
#define TT 256
#define DD 128
#define KK 16
#define NTOT (BB*NN)

typedef unsigned long long ull;

__device__ __forceinline__ ull ffma2(ull a, ull b, ull c){
    ull d; asm("fma.rn.f32x2 %0, %1, %2, %3;" : "=l"(d) : "l"(a), "l"(b), "l"(c));
    return d;
}
__device__ __forceinline__ float usum(ull v){
    float lo, hi; asm("mov.b64 {%0,%1}, %2;" : "=f"(lo), "=f"(hi) : "l"(v));
    return lo + hi;
}

// ---------------- scratch ----------------
__device__ float g_u   [NTOT*DD];
__device__ float g_u2  [NTOT*DD];
__device__ float g_base[NTOT*DD];
__device__ float g_proj[NTOT*DD];
__device__ float g_loc [NTOT*DD];
__device__ int   g_idx [NTOT*KK];
__device__ ull   g_wpack[14*64*128];   // 14 matrices, k-pair packed

// ---------------- Kernel 0: weight repack into k-pair-interleaved layout ----
// dst[m][kp][c] = (W[2kp][c], W[2kp+1][c])
struct WP { const float* p[14]; };
__global__ void __launch_bounds__(256) k_pack(WP wp, float2* __restrict__ dst){
    int m = blockIdx.y;
    const float* W = wp.p[m];
    int i = blockIdx.x*256 + threadIdx.x;     // 0..8191
    int kp = i >> 7, c = i & 127;
    dst[(size_t)m*8192 + i] = make_float2(W[(2*kp)*DD + c], W[(2*kp+1)*DD + c]);
}

// ---------------- Kernel 1: TemporalLift ----
__global__ void __launch_bounds__(128) k_lift(
    const float* __restrict__ spikes, const float* __restrict__ conv_w,
    const float* __restrict__ conv_b, const float* __restrict__ fc_w,
    const float* __restrict__ fc_b, float* __restrict__ u)
{
    __shared__ float sp[TT+4];
    __shared__ float xm[DD];
    int node = blockIdx.x;
    int h = threadIdx.x;
    const float* s = spikes + (size_t)node*TT;
    sp[2+h]      = s[h];
    sp[2+h+128]  = s[h+128];
    if (h < 2) { sp[h] = 0.f; sp[TT+2+h] = 0.f; }
    __syncthreads();
    float w0 = conv_w[h*5+0], w1 = conv_w[h*5+1], w2 = conv_w[h*5+2],
          w3 = conv_w[h*5+3], w4 = conv_w[h*5+4];
    float bb = conv_b[h];
    float acc = 0.f;
    #pragma unroll 8
    for (int t = 0; t < TT; t++) {
        float v = fmaf(w0, sp[t],
                  fmaf(w1, sp[t+1],
                  fmaf(w2, sp[t+2],
                  fmaf(w3, sp[t+3],
                  fmaf(w4, sp[t+4], bb)))));
        acc += fmaxf(v, 0.f);
    }
    xm[h] = acc * (1.f/(float)TT);
    __syncthreads();
    float o = fc_b[h];
    #pragma unroll 8
    for (int j = 0; j < DD; j++) o = fmaf(xm[j], __ldg(&fc_w[j*DD+h]), o);
    u[(size_t)node*DD + h] = fmaxf(o, 0.f);
}

// ---------------- Kernel 2: kNN ----
__global__ void __launch_bounds__(256) k_knn(
    const float* __restrict__ coords, int* __restrict__ idx)
{
    __shared__ float c[NN];
    int b = blockIdx.y;
    int i = blockIdx.x*256 + threadIdx.x;
    const float* cb = coords + (size_t)b*NN;
    for (int j = threadIdx.x; j < NN; j += 256) c[j] = cb[j];
    __syncthreads();
    float ci = c[i];
    float d2[KK]; int id[KK];
    #pragma unroll
    for (int p = 0; p < KK; p++) { d2[p] = 3.4e38f; id[p] = 0x7fffffff; }
    for (int j = 0; j < NN; j++) {
        float df = ci - c[j];
        float nd = df*df;
        if (nd < d2[KK-1] || (nd == d2[KK-1] && j < id[KK-1])) {
            d2[KK-1] = nd; id[KK-1] = j;
            #pragma unroll
            for (int p = KK-1; p > 0; --p) {
                bool sw = (d2[p] < d2[p-1]) || (d2[p] == d2[p-1] && id[p] < id[p-1]);
                if (!sw) break;
                float td = d2[p]; d2[p] = d2[p-1]; d2[p-1] = td;
                int   ti = id[p]; id[p] = id[p-1]; id[p-1] = ti;
            }
        }
    }
    int* o = idx + ((size_t)b*NN + i)*KK;
    #pragma unroll
    for (int p = 0; p < KK; p++) o[p] = id[p];
}

// ---------------- Kernel 3: fused node GEMM, up to 3 B-matrices -------------
// Block: 32 rows x 128 cols. Warp w owns rows w*4..w*4+3 (broadcast A from smem),
// lane l owns cols {2l,2l+1,2l+64,2l+65}. B read from packed global (coalesced).
template<int NMAT, bool EX>
__global__ void __launch_bounds__(256) k_node(
    const float* __restrict__ X,
    const ull* __restrict__ W0, const ull* __restrict__ W1, const ull* __restrict__ W2,
    const float* __restrict__ cb0, const float* __restrict__ cb2,
    const float* __restrict__ rv0, const float* __restrict__ rv1,
    const float* __restrict__ xs,
    float* __restrict__ Y0, float* __restrict__ Y1, float* __restrict__ Y2)
{
    __shared__ float Xs[32*DD];
    __shared__ float xc[32];
    int tid = threadIdx.x;
    int row0 = blockIdx.x*32;
    const float4* Xg = (const float4*)(X + (size_t)row0*DD);
    #pragma unroll
    for (int i = 0; i < 4; i++) ((float4*)Xs)[tid + i*256] = Xg[tid + i*256];
    if (EX && tid < 32) xc[tid] = xs[row0 + tid];
    __syncthreads();

    int l = tid & 31, w = tid >> 5;
    const ull* Ws[3] = {W0, W1, (NMAT > 2) ? W2 : W0};
    ull acc[NMAT][4][4];
    #pragma unroll
    for (int m = 0; m < NMAT; m++)
        #pragma unroll
        for (int r = 0; r < 4; r++)
            #pragma unroll
            for (int cc = 0; cc < 4; cc++) acc[m][r][cc] = 0ull;

    #pragma unroll 2
    for (int kp = 0; kp < 64; kp++) {
        ull a[4];
        #pragma unroll
        for (int r = 0; r < 4; r++)
            a[r] = *(const ull*)&Xs[(w*4+r)*DD + 2*kp];
        #pragma unroll
        for (int m = 0; m < NMAT; m++) {
            ulonglong2 blo = *(const ulonglong2*)(Ws[m] + kp*DD + 2*l);
            ulonglong2 bhi = *(const ulonglong2*)(Ws[m] + kp*DD + 64 + 2*l);
            #pragma unroll
            for (int r = 0; r < 4; r++) {
                acc[m][r][0] = ffma2(a[r], blo.x, acc[m][r][0]);
                acc[m][r][1] = ffma2(a[r], blo.y, acc[m][r][1]);
                acc[m][r][2] = ffma2(a[r], bhi.x, acc[m][r][2]);
                acc[m][r][3] = ffma2(a[r], bhi.y, acc[m][r][3]);
            }
        }
    }

    int cols[4] = {2*l, 2*l+1, 2*l+64, 2*l+65};
    float cb0v[4], cb2v[4], r0v[4], r1v[4];
    if (EX) {
        #pragma unroll
        for (int cc = 0; cc < 4; cc++) {
            cb0v[cc] = cb0[cols[cc]];
            cb2v[cc] = cb2[cols[cc]];
            r0v[cc]  = rv0[cols[cc]];
            r1v[cc]  = rv1[cols[cc]];
        }
    }
    float* Ys[3] = {Y0, Y1, (NMAT > 2) ? Y2 : Y0};
    #pragma unroll
    for (int r = 0; r < 4; r++) {
        int n = row0 + w*4 + r;
        float xv = EX ? xc[w*4+r] : 0.f;
        #pragma unroll
        for (int m = 0; m < NMAT; m++) {
            float res[4];
            #pragma unroll
            for (int cc = 0; cc < 4; cc++) {
                float s = usum(acc[m][r][cc]);
                if (EX) {
                    if (m == 0) s += cb0v[cc] + xv*r0v[cc];
                    if (m == 1) s += xv*r1v[cc];
                    if (m == 2) s += cb2v[cc];
                }
                res[cc] = s;
            }
            *(float2*)(Ys[m] + (size_t)n*DD + 2*l)      = make_float2(res[0], res[1]);
            *(float2*)(Ys[m] + (size_t)n*DD + 64 + 2*l) = make_float2(res[2], res[3]);
        }
    }
}

// ---------------- Kernel 4: edge MLP + aggregation + residual ---------------
// Block = 4 nodes (64 edges). Warp w owns edges w*8..w*8+8 (broadcast A from h1s),
// lane l owns cols {2l,2l+1,2l+64,2l+65}. k2 read packed from global (L1-resident).
__global__ void __launch_bounds__(256) k_edge(
    const float* __restrict__ u_in, float* __restrict__ u_out,
    const float* __restrict__ base, const float* __restrict__ proj,
    const float* __restrict__ loc, const int* __restrict__ idx,
    const ull* __restrict__ k2p, const float* __restrict__ k2b,
    const float* __restrict__ k3w, const float* __restrict__ k3b)
{
    __shared__ float h1s[64*DD];
    __shared__ float bss[4*DD];
    __shared__ int   js[64];
    __shared__ float kvv[64];

    int tid = threadIdx.x;
    int node0 = blockIdx.x * 4;
    int bbase = node0 & ~(NN-1);

    if (tid < 128)
        ((float4*)bss)[tid] = ((const float4*)(base + (size_t)node0*DD))[tid];
    if (tid < 64) js[tid] = idx[node0*KK + tid];
    __syncthreads();

    int l = tid & 31, w = tid >> 5;
    // h1 = relu(base_i + proj_j)
    #pragma unroll
    for (int r = 0; r < 8; r++) {
        int e = w*8 + r;
        int j = js[e];
        float4 p  = ((const float4*)(proj + (size_t)(bbase + j)*DD))[l];
        float4 bq = ((const float4*)bss)[(e>>4)*32 + l];
        float4 h;
        h.x = fmaxf(p.x+bq.x, 0.f);
        h.y = fmaxf(p.y+bq.y, 0.f);
        h.z = fmaxf(p.z+bq.z, 0.f);
        h.w = fmaxf(p.w+bq.w, 0.f);
        ((float4*)h1s)[e*32 + l] = h;
    }
    __syncthreads();

    ull acc[8][4];
    #pragma unroll
    for (int r = 0; r < 8; r++)
        #pragma unroll
        for (int cc = 0; cc < 4; cc++) acc[r][cc] = 0ull;

    #pragma unroll 2
    for (int kp = 0; kp < 64; kp++) {
        ulonglong2 blo = *(const ulonglong2*)(k2p + kp*DD + 2*l);
        ulonglong2 bhi = *(const ulonglong2*)(k2p + kp*DD + 64 + 2*l);
        #pragma unroll
        for (int r = 0; r < 8; r++) {
            ull a = *(const ull*)&h1s[(w*8+r)*DD + 2*kp];
            acc[r][0] = ffma2(a, blo.x, acc[r][0]);
            acc[r][1] = ffma2(a, blo.y, acc[r][1]);
            acc[r][2] = ffma2(a, bhi.x, acc[r][2]);
            acc[r][3] = ffma2(a, bhi.y, acc[r][3]);
        }
    }

    float b2v[4] = {k2b[2*l], k2b[2*l+1], k2b[2*l+64], k2b[2*l+65]};
    float k3v[4] = {k3w[2*l], k3w[2*l+1], k3w[2*l+64], k3w[2*l+65]};
    float k3b0 = k3b[0];
    #pragma unroll
    for (int r = 0; r < 8; r++) {
        float part = fmaxf(usum(acc[r][0]) + b2v[0], 0.f)*k3v[0]
                   + fmaxf(usum(acc[r][1]) + b2v[1], 0.f)*k3v[1]
                   + fmaxf(usum(acc[r][2]) + b2v[2], 0.f)*k3v[2]
                   + fmaxf(usum(acc[r][3]) + b2v[3], 0.f)*k3v[3];
        #pragma unroll
        for (int s = 16; s > 0; s >>= 1)
            part += __shfl_xor_sync(0xffffffffu, part, s);
        if (l == 0) kvv[w*8 + r] = (part + k3b0) * 0.25f;   // * 1/sqrt(16)
    }
    __syncthreads();

    // agg + residual + relu
    int d  = tid & 127;
    int gh = tid >> 7;
    #pragma unroll
    for (int gg = 0; gg < 4; gg += 2) {
        int g = gg + gh;
        int n = node0 + g;
        float a = 0.f;
        #pragma unroll
        for (int kk = 0; kk < KK; kk++) {
            int j = js[g*KK + kk];
            a = fmaf(kvv[g*KK+kk], u_in[((size_t)(bbase+j))*DD + d], a);
        }
        float o = loc[(size_t)n*DD + d] + a + u_in[(size_t)n*DD + d];
        u_out[(size_t)n*DD + d] = fmaxf(o, 0.f);
    }
}

// ---------------- Kernel 5: decoder 64x64 tile, dual GEMM + epilogue --------
// Warp w owns rows w*8..w*8+8 (uniform LDG from global v/w, L1-resident tile),
// lane l owns cols {2l, 2l+1}. B side (u^T) staged in smem as k-pair float2s.
__global__ void __launch_bounds__(256) k_dec(
    const float* __restrict__ v, const float* __restrict__ wmat,
    const float* __restrict__ u, float* __restrict__ out)
{
    __shared__ float2 utp[64*65];   // [kp][m], padded stride 65
    int tid = threadIdx.x;
    int bx = blockIdx.x, by = blockIdx.y, bz = blockIdx.z;
    size_t nb = (size_t)bz * NN;

    #pragma unroll
    for (int i = 0; i < 16; i++) {
        int idx = tid + i*256;
        int m = idx >> 6, kp = idx & 63;
        utp[kp*65 + m] = *(const float2*)&u[(nb + (size_t)bx*64 + m)*DD + 2*kp];
    }
    __syncthreads();

    int l = tid & 31, w = tid >> 5;
    const float* vrow = v    + (nb + (size_t)by*64 + w*8)*DD;
    const float* wrow = wmat + (nb + (size_t)by*64 + w*8)*DD;

    ull aV[8][2], aW[8][2];
    #pragma unroll
    for (int r = 0; r < 8; r++) { aV[r][0]=aV[r][1]=aW[r][0]=aW[r][1]=0ull; }

    for (int k2i = 0; k2i < 32; k2i++) {
        ull be0 = *(const ull*)&utp[(2*k2i)*65   + 2*l];
        ull be1 = *(const ull*)&utp[(2*k2i)*65   + 2*l+1];
        ull bo0 = *(const ull*)&utp[(2*k2i+1)*65 + 2*l];
        ull bo1 = *(const ull*)&utp[(2*k2i+1)*65 + 2*l+1];
        #pragma unroll
        for (int r = 0; r < 8; r++) {
            ulonglong2 av = *(const ulonglong2*)&vrow[r*DD + 4*k2i];
            ulonglong2 aw = *(const ulonglong2*)&wrow[r*DD + 4*k2i];
            aV[r][0] = ffma2(av.x, be0, aV[r][0]);
            aV[r][0] = ffma2(av.y, bo0, aV[r][0]);
            aV[r][1] = ffma2(av.x, be1, aV[r][1]);
            aV[r][1] = ffma2(av.y, bo1, aV[r][1]);
            aW[r][0] = ffma2(aw.x, be0, aW[r][0]);
            aW[r][0] = ffma2(aw.y, bo0, aW[r][0]);
            aW[r][1] = ffma2(aw.x, be1, aW[r][1]);
            aW[r][1] = ffma2(aw.y, bo1, aW[r][1]);
        }
    }

    size_t N2 = (size_t)NN*NN;
    size_t S  = (size_t)BB*N2;
    #pragma unroll
    for (int r = 0; r < 8; r++) {
        int row = by*64 + w*8 + r;
        size_t o = (size_t)bz*N2 + (size_t)row*NN + bx*64 + 2*l;
        float lg0 = usum(aV[r][0]);
        float lg1 = usum(aV[r][1]);
        *(float2*)(out + o) = make_float2(lg0, lg1);
        float pr0 = __fdividef(1.f, 1.f + __expf(-lg0));
        float pr1 = __fdividef(1.f, 1.f + __expf(-lg1));
        *(float2*)(out + S + o) = make_float2(pr0, pr1);
        float w0 = usum(aW[r][0]);
        float w1 = usum(aW[r][1]);
        float sp0 = fmaxf(w0, 0.f) + __logf(1.f + __expf(-fabsf(w0)));
        float sp1 = fmaxf(w1, 0.f) + __logf(1.f + __expf(-fabsf(w1)));
        *(float2*)(out + 2*S + o) = make_float2(sp0, sp1);
    }
}

// ---------------- launch -----------------------------------------------------
extern "C" void kernel_launch(void* const* d_in, const int* in_sizes, int n_in,
                              void* d_out, int out_size)
{
    const float* spikes   = (const float*)d_in[0];
    const float* coords   = (const float*)d_in[1];
    const float* conv_w   = (const float*)d_in[2];
    const float* conv_b   = (const float*)d_in[3];
    const float* fc_w     = (const float*)d_in[4];
    const float* fc_b     = (const float*)d_in[5];
    const float* local_w  = (const float*)d_in[6];
    const float* local_b  = (const float*)d_in[7];
    const float* k1_w     = (const float*)d_in[8];
    const float* k1_b     = (const float*)d_in[9];
    const float* k2_w     = (const float*)d_in[10];
    const float* k2_b     = (const float*)d_in[11];
    const float* k3_w     = (const float*)d_in[12];
    const float* k3_b     = (const float*)d_in[13];
    const float* W_logits = (const float*)d_in[14];
    const float* W_weight = (const float*)d_in[15];
    float* out = (float*)d_out;

    float *u0, *u1, *pb, *pp, *pl; int* pix; ull* wpk;
    cudaGetSymbolAddress((void**)&u0,  g_u);
    cudaGetSymbolAddress((void**)&u1,  g_u2);
    cudaGetSymbolAddress((void**)&pb,  g_base);
    cudaGetSymbolAddress((void**)&pp,  g_proj);
    cudaGetSymbolAddress((void**)&pl,  g_loc);
    cudaGetSymbolAddress((void**)&pix, g_idx);
    cudaGetSymbolAddress((void**)&wpk, g_wpack);

    // pack order: per layer l: [4l+0]=Wui, [4l+1]=Wuj, [4l+2]=local, [4l+3]=k2
    //             [12]=W_logits, [13]=W_weight
    WP wp;
    for (int lyr = 0; lyr < 3; lyr++) {
        wp.p[4*lyr+0] = k1_w + (size_t)lyr*258*DD + 2*DD;
        wp.p[4*lyr+1] = k1_w + (size_t)lyr*258*DD + 130*DD;
        wp.p[4*lyr+2] = local_w + (size_t)lyr*DD*DD;
        wp.p[4*lyr+3] = k2_w + (size_t)lyr*DD*DD;
    }
    wp.p[12] = W_logits;
    wp.p[13] = W_weight;
    k_pack<<<dim3(32,14), 256>>>(wp, (float2*)wpk);

    k_lift<<<NTOT, 128>>>(spikes, conv_w, conv_b, fc_w, fc_b, u0);
    k_knn<<<dim3(NN/256, BB), 256>>>(coords, pix);

    float* ucur = u0;
    float* unext = u1;
    for (int lyr = 0; lyr < 3; lyr++) {
        const float* W1 = k1_w + (size_t)lyr*258*DD;
        // base = u@Wui + k1_b + x*row0 ; proj = u@Wuj + x*row1 ; loc = u@local + local_b
        k_node<3, true><<<NTOT/32, 256>>>(ucur,
            wpk + (size_t)(4*lyr+0)*8192, wpk + (size_t)(4*lyr+1)*8192,
            wpk + (size_t)(4*lyr+2)*8192,
            k1_b + lyr*DD, local_b + lyr*DD,
            W1, W1 + DD, coords,
            pb, pp, pl);
        k_edge<<<NTOT/4, 256>>>(ucur, unext, pb, pp, pl, pix,
                                wpk + (size_t)(4*lyr+3)*8192,
                                k2_b + lyr*DD, k3_w + (size_t)lyr*DD, k3_b + lyr);
        float* t = ucur; ucur = unext; unext = t;
    }

    // decoder stage 1: v = u@W_logits, w = u@W_weight
    k_node<2, false><<<NTOT/32, 256>>>(ucur,
        wpk + (size_t)12*8192, wpk + (size_t)13*8192, wpk,
        nullptr, nullptr, nullptr, nullptr, nullptr,
        pb, pp, pb);
    // decoder stage 2 + epilogue
    k_dec<<<dim3(NN/64, NN/64, BB), 256>>>(pb, pp, ucur, out);
}

// round 3
// speedup vs baseline: 1.0634x; 1.0436x over previous
#include <cuda_runtime.h>
#include <math.h>

#define BB 2
#define NN 2048
#define TT 256
#define DD 128
#define KK 16
#define NTOT (BB*NN)

typedef unsigned long long ull;

__device__ __forceinline__ ull ffma2(ull a, ull b, ull c){
    ull d; asm("fma.rn.f32x2 %0, %1, %2, %3;" : "=l"(d) : "l"(a), "l"(b), "l"(c));
    return d;
}
__device__ __forceinline__ float usum(ull v){
    float lo, hi; asm("mov.b64 {%0,%1}, %2;" : "=f"(lo), "=f"(hi) : "l"(v));
    return lo + hi;
}

// ---------------- scratch ----------------
__device__ float g_u   [NTOT*DD];
__device__ float g_u2  [NTOT*DD];
__device__ float g_base[NTOT*DD];
__device__ float g_proj[NTOT*DD];
__device__ float g_loc [NTOT*DD];
__device__ int   g_idx [NTOT*KK];
__device__ __align__(16) ull g_wpack[15*64*128];   // 15 matrices, k-pair packed

// ---------------- Kernel 0: weight repack into k-pair-interleaved layout ----
// dst[m][kp][c] = (W[2kp][c], W[2kp+1][c])
struct WP { const float* p[15]; };
__global__ void __launch_bounds__(256) k_pack(WP wp, float2* __restrict__ dst){
    int m = blockIdx.y;
    const float* W = wp.p[m];
    int i = blockIdx.x*256 + threadIdx.x;     // 0..8191
    int kp = i >> 7, c = i & 127;
    dst[(size_t)m*8192 + i] = make_float2(W[(2*kp)*DD + c], W[(2*kp+1)*DD + c]);
}

// ---------------- Kernel 1: TemporalLift ----
__global__ void __launch_bounds__(128) k_lift(
    const float* __restrict__ spikes, const float* __restrict__ conv_w,
    const float* __restrict__ conv_b, const ull* __restrict__ fcp,
    const float* __restrict__ fc_b, float* __restrict__ u)
{
    __shared__ __align__(16) float sp[TT+4];
    __shared__ __align__(16) float xm[DD];
    int node = blockIdx.x;
    int h = threadIdx.x;
    const float* s = spikes + (size_t)node*TT;
    sp[2+h]      = s[h];
    sp[2+h+128]  = s[h+128];
    if (h < 2) { sp[h] = 0.f; sp[TT+2+h] = 0.f; }
    __syncthreads();
    float w0 = conv_w[h*5+0], w1 = conv_w[h*5+1], w2 = conv_w[h*5+2],
          w3 = conv_w[h*5+3], w4 = conv_w[h*5+4];
    float bb = conv_b[h];
    float acc = 0.f;
    #pragma unroll 8
    for (int t = 0; t < TT; t++) {
        float v = fmaf(w0, sp[t],
                  fmaf(w1, sp[t+1],
                  fmaf(w2, sp[t+2],
                  fmaf(w3, sp[t+3],
                  fmaf(w4, sp[t+4], bb)))));
        acc += fmaxf(v, 0.f);
    }
    xm[h] = acc * (1.f/(float)TT);
    __syncthreads();
    ull o2 = 0ull;
    #pragma unroll 8
    for (int kp = 0; kp < 64; kp++)
        o2 = ffma2(*(const ull*)&xm[2*kp], __ldg(&fcp[kp*DD + h]), o2);
    float o = usum(o2) + fc_b[h];
    u[(size_t)node*DD + h] = fmaxf(o, 0.f);
}

// ---------------- Kernel 2: kNN ----
__global__ void __launch_bounds__(256) k_knn(
    const float* __restrict__ coords, int* __restrict__ idx)
{
    __shared__ float c[NN];
    int b = blockIdx.y;
    int i = blockIdx.x*256 + threadIdx.x;
    const float* cb = coords + (size_t)b*NN;
    for (int j = threadIdx.x; j < NN; j += 256) c[j] = cb[j];
    __syncthreads();
    float ci = c[i];
    float d2[KK]; int id[KK];
    #pragma unroll
    for (int p = 0; p < KK; p++) { d2[p] = 3.4e38f; id[p] = 0x7fffffff; }
    for (int j = 0; j < NN; j++) {
        float df = ci - c[j];
        float nd = df*df;
        if (nd < d2[KK-1] || (nd == d2[KK-1] && j < id[KK-1])) {
            d2[KK-1] = nd; id[KK-1] = j;
            #pragma unroll
            for (int p = KK-1; p > 0; --p) {
                bool sw = (d2[p] < d2[p-1]) || (d2[p] == d2[p-1] && id[p] < id[p-1]);
                if (!sw) break;
                float td = d2[p]; d2[p] = d2[p-1]; d2[p-1] = td;
                int   ti = id[p]; id[p] = id[p-1]; id[p-1] = ti;
            }
        }
    }
    int* o = idx + ((size_t)b*NN + i)*KK;
    #pragma unroll
    for (int p = 0; p < KK; p++) o[p] = id[p];
}

// ---------------- Kernel 3: fused node GEMM, up to 3 B-matrices -------------
// Block = 32 rows x 64 cols (grid.y = col half). Warp w: rows w*4..w*4+3.
// Lane l: cols cb+2l, cb+2l+1. K processed in pairs-of-pairs (LDS.128/LDG.128).
template<int NMAT, bool EX>
__global__ void __launch_bounds__(256) k_node(
    const float* __restrict__ X,
    const ull* __restrict__ W0, const ull* __restrict__ W1, const ull* __restrict__ W2,
    const float* __restrict__ cb0, const float* __restrict__ cb2,
    const float* __restrict__ rv0, const float* __restrict__ rv1,
    const float* __restrict__ xs,
    float* __restrict__ Y0, float* __restrict__ Y1, float* __restrict__ Y2)
{
    __shared__ __align__(16) float Xs[32*DD];
    __shared__ float xc[32];
    int tid = threadIdx.x;
    int row0 = blockIdx.x*32;
    int cb = blockIdx.y*64;
    const float4* Xg = (const float4*)(X + (size_t)row0*DD);
    #pragma unroll
    for (int i = 0; i < 4; i++) ((float4*)Xs)[tid + i*256] = Xg[tid + i*256];
    if (EX && tid < 32) xc[tid] = xs[row0 + tid];
    __syncthreads();

    int l = tid & 31, w = tid >> 5;
    const ull* Ws[3] = {W0, W1, (NMAT > 2) ? W2 : W0};
    ull acc[NMAT][4][2];
    #pragma unroll
    for (int m = 0; m < NMAT; m++)
        #pragma unroll
        for (int r = 0; r < 4; r++) { acc[m][r][0] = 0ull; acc[m][r][1] = 0ull; }

    int coff = cb + 2*l;
    #pragma unroll 2
    for (int kpp = 0; kpp < 32; kpp++) {
        ulonglong2 a2[4];
        #pragma unroll
        for (int r = 0; r < 4; r++)
            a2[r] = *(const ulonglong2*)&Xs[(w*4+r)*DD + 4*kpp];
        #pragma unroll
        for (int m = 0; m < NMAT; m++) {
            ulonglong2 b0 = *(const ulonglong2*)(Ws[m] + (size_t)(2*kpp)*DD + coff);
            ulonglong2 b1 = *(const ulonglong2*)(Ws[m] + (size_t)(2*kpp+1)*DD + coff);
            #pragma unroll
            for (int r = 0; r < 4; r++) {
                acc[m][r][0] = ffma2(a2[r].x, b0.x, acc[m][r][0]);
                acc[m][r][1] = ffma2(a2[r].x, b0.y, acc[m][r][1]);
                acc[m][r][0] = ffma2(a2[r].y, b1.x, acc[m][r][0]);
                acc[m][r][1] = ffma2(a2[r].y, b1.y, acc[m][r][1]);
            }
        }
    }

    int c0 = coff;
    float2 cb0v = make_float2(0.f,0.f), cb2v = cb0v, r0v = cb0v, r1v = cb0v;
    if (EX) {
        cb0v = *(const float2*)(cb0 + c0);
        cb2v = *(const float2*)(cb2 + c0);
        r0v  = *(const float2*)(rv0 + c0);
        r1v  = *(const float2*)(rv1 + c0);
    }
    float* Ys[3] = {Y0, Y1, (NMAT > 2) ? Y2 : Y0};
    #pragma unroll
    for (int r = 0; r < 4; r++) {
        int n = row0 + w*4 + r;
        float xv = EX ? xc[w*4+r] : 0.f;
        #pragma unroll
        for (int m = 0; m < NMAT; m++) {
            float s0 = usum(acc[m][r][0]);
            float s1 = usum(acc[m][r][1]);
            if (EX) {
                if (m == 0) { s0 += cb0v.x + xv*r0v.x; s1 += cb0v.y + xv*r0v.y; }
                if (m == 1) { s0 += xv*r1v.x;          s1 += xv*r1v.y; }
                if (m == 2) { s0 += cb2v.x;            s1 += cb2v.y; }
            }
            *(float2*)(Ys[m] + (size_t)n*DD + c0) = make_float2(s0, s1);
        }
    }
}

// ---------------- Kernel 4: edge MLP + aggregation + residual ---------------
// Block = 4 nodes (64 edges), 512 threads (16 warps).
// GEMM: warp = 8 edges x 64-col half; lane = 2 cols.
__global__ void __launch_bounds__(512) k_edge(
    const float* __restrict__ u_in, float* __restrict__ u_out,
    const float* __restrict__ base, const float* __restrict__ proj,
    const float* __restrict__ loc, const int* __restrict__ idx,
    const ull* __restrict__ k2p, const float* __restrict__ k2b,
    const float* __restrict__ k3w, const float* __restrict__ k3b)
{
    __shared__ __align__(16) float h1s[64*DD];
    __shared__ __align__(16) float bss[4*DD];
    __shared__ int   js[64];
    __shared__ float kvs[64][2];
    __shared__ float kvv[64];

    int tid = threadIdx.x;
    int node0 = blockIdx.x * 4;
    int bbase = node0 & ~(NN-1);

    if (tid < 128)
        ((float4*)bss)[tid] = ((const float4*)(base + (size_t)node0*DD))[tid];
    if (tid < 64) js[tid] = idx[node0*KK + tid];
    __syncthreads();

    int l = tid & 31, w = tid >> 5;
    // h1 = relu(base_i + proj_j): warp w builds edges w*4..w*4+3
    #pragma unroll
    for (int r = 0; r < 4; r++) {
        int e = w*4 + r;
        int j = js[e];
        float4 p  = ((const float4*)(proj + (size_t)(bbase + j)*DD))[l];
        float4 bq = ((const float4*)bss)[(e>>4)*32 + l];
        float4 h;
        h.x = fmaxf(p.x+bq.x, 0.f);
        h.y = fmaxf(p.y+bq.y, 0.f);
        h.z = fmaxf(p.z+bq.z, 0.f);
        h.w = fmaxf(p.w+bq.w, 0.f);
        ((float4*)h1s)[e*32 + l] = h;
    }
    __syncthreads();

    int g = w >> 1, ch = w & 1;
    const ull* k2c = k2p + ch*64 + 2*l;
    ull acc[8][2];
    #pragma unroll
    for (int r = 0; r < 8; r++) { acc[r][0] = 0ull; acc[r][1] = 0ull; }

    #pragma unroll 2
    for (int kpp = 0; kpp < 32; kpp++) {
        ulonglong2 b0 = *(const ulonglong2*)(k2c + (size_t)(2*kpp)*DD);
        ulonglong2 b1 = *(const ulonglong2*)(k2c + (size_t)(2*kpp+1)*DD);
        #pragma unroll
        for (int r = 0; r < 8; r++) {
            ulonglong2 a2 = *(const ulonglong2*)&h1s[(g*8+r)*DD + 4*kpp];
            acc[r][0] = ffma2(a2.x, b0.x, acc[r][0]);
            acc[r][1] = ffma2(a2.x, b0.y, acc[r][1]);
            acc[r][0] = ffma2(a2.y, b1.x, acc[r][0]);
            acc[r][1] = ffma2(a2.y, b1.y, acc[r][1]);
        }
    }

    int c0 = ch*64 + 2*l;
    float b2a = k2b[c0], b2b = k2b[c0+1];
    float k3a = k3w[c0], k3c = k3w[c0+1];
    #pragma unroll
    for (int r = 0; r < 8; r++) {
        float part = fmaxf(usum(acc[r][0]) + b2a, 0.f)*k3a
                   + fmaxf(usum(acc[r][1]) + b2b, 0.f)*k3c;
        #pragma unroll
        for (int s = 16; s > 0; s >>= 1)
            part += __shfl_xor_sync(0xffffffffu, part, s);
        if (l == 0) kvs[g*8 + r][ch] = part;
    }
    __syncthreads();
    if (tid < 64) kvv[tid] = (kvs[tid][0] + kvs[tid][1] + k3b[0]) * 0.25f;
    __syncthreads();

    // agg + residual + relu: 512 threads = 4 nodes x 128 dims
    int d  = tid & 127;
    int gg = tid >> 7;
    int n = node0 + gg;
    float a = 0.f;
    #pragma unroll
    for (int kk = 0; kk < KK; kk++) {
        int j = js[gg*KK + kk];
        a = fmaf(kvv[gg*KK+kk], u_in[((size_t)(bbase+j))*DD + d], a);
    }
    float o = loc[(size_t)n*DD + d] + a + u_in[(size_t)n*DD + d];
    u_out[(size_t)n*DD + d] = fmaxf(o, 0.f);
}

// ---------------- Kernel 5: decoder 64x64 tile, dual GEMM + epilogue --------
// 512 threads. Warp = 4 rows x 64 cols; lane = cols {l, l+32}.
// B tile (u rows) in smem row-major, stride 130 floats (conflict-free LDS.64).
__global__ void __launch_bounds__(512) k_dec(
    const float* __restrict__ v, const float* __restrict__ wmat,
    const float* __restrict__ u, float* __restrict__ out)
{
    __shared__ __align__(16) float us[64*130];
    int tid = threadIdx.x;
    int bx = blockIdx.x, by = blockIdx.y, bz = blockIdx.z;
    size_t nb = (size_t)bz * NN;

    #pragma unroll
    for (int i = 0; i < 8; i++) {
        int ii = tid + i*512;
        int m = ii >> 6, kp = ii & 63;
        *(float2*)&us[m*130 + 2*kp] =
            *(const float2*)&u[(nb + (size_t)bx*64 + m)*DD + 2*kp];
    }
    __syncthreads();

    int l = tid & 31, w = tid >> 5;
    const float* vrow = v    + (nb + (size_t)by*64 + w*4)*DD;
    const float* wrow = wmat + (nb + (size_t)by*64 + w*4)*DD;
    int m0 = l, m1 = l + 32;

    ull aV[4][2], aW[4][2];
    #pragma unroll
    for (int r = 0; r < 4; r++) { aV[r][0]=aV[r][1]=aW[r][0]=aW[r][1]=0ull; }

    #pragma unroll 2
    for (int kpp = 0; kpp < 32; kpp++) {
        ull b00 = *(const ull*)&us[m0*130 + 4*kpp];
        ull b01 = *(const ull*)&us[m0*130 + 4*kpp + 2];
        ull b10 = *(const ull*)&us[m1*130 + 4*kpp];
        ull b11 = *(const ull*)&us[m1*130 + 4*kpp + 2];
        #pragma unroll
        for (int r = 0; r < 4; r++) {
            ulonglong2 av = *(const ulonglong2*)&vrow[r*DD + 4*kpp];
            ulonglong2 aw = *(const ulonglong2*)&wrow[r*DD + 4*kpp];
            aV[r][0] = ffma2(av.x, b00, aV[r][0]);
            aV[r][0] = ffma2(av.y, b01, aV[r][0]);
            aV[r][1] = ffma2(av.x, b10, aV[r][1]);
            aV[r][1] = ffma2(av.y, b11, aV[r][1]);
            aW[r][0] = ffma2(aw.x, b00, aW[r][0]);
            aW[r][0] = ffma2(aw.y, b01, aW[r][0]);
            aW[r][1] = ffma2(aw.x, b10, aW[r][1]);
            aW[r][1] = ffma2(aw.y, b11, aW[r][1]);
        }
    }

    size_t N2 = (size_t)NN*NN;
    size_t S  = (size_t)BB*N2;
    #pragma unroll
    for (int r = 0; r < 4; r++) {
        int row = by*64 + w*4 + r;
        size_t o = (size_t)bz*N2 + (size_t)row*NN + bx*64 + l;
        float lg0 = usum(aV[r][0]);
        float lg1 = usum(aV[r][1]);
        out[o]      = lg0;
        out[o + 32] = lg1;
        out[S + o]      = __fdividef(1.f, 1.f + __expf(-lg0));
        out[S + o + 32] = __fdividef(1.f, 1.f + __expf(-lg1));
        float w0 = usum(aW[r][0]);
        float w1 = usum(aW[r][1]);
        out[2*S + o]      = fmaxf(w0, 0.f) + __logf(1.f + __expf(-fabsf(w0)));
        out[2*S + o + 32] = fmaxf(w1, 0.f) + __logf(1.f + __expf(-fabsf(w1)));
    }
}

// ---------------- launch -----------------------------------------------------
extern "C" void kernel_launch(void* const* d_in, const int* in_sizes, int n_in,
                              void* d_out, int out_size)
{
    const float* spikes   = (const float*)d_in[0];
    const float* coords   = (const float*)d_in[1];
    const float* conv_w   = (const float*)d_in[2];
    const float* conv_b   = (const float*)d_in[3];
    const float* fc_w     = (const float*)d_in[4];
    const float* fc_b     = (const float*)d_in[5];
    const float* local_w  = (const float*)d_in[6];
    const float* local_b  = (const float*)d_in[7];
    const float* k1_w     = (const float*)d_in[8];
    const float* k1_b     = (const float*)d_in[9];
    const float* k2_w     = (const float*)d_in[10];
    const float* k2_b     = (const float*)d_in[11];
    const float* k3_w     = (const float*)d_in[12];
    const float* k3_b     = (const float*)d_in[13];
    const float* W_logits = (const float*)d_in[14];
    const float* W_weight = (const float*)d_in[15];
    float* out = (float*)d_out;

    float *u0, *u1, *pb, *pp, *pl; int* pix; ull* wpk;
    cudaGetSymbolAddress((void**)&u0,  g_u);
    cudaGetSymbolAddress((void**)&u1,  g_u2);
    cudaGetSymbolAddress((void**)&pb,  g_base);
    cudaGetSymbolAddress((void**)&pp,  g_proj);
    cudaGetSymbolAddress((void**)&pl,  g_loc);
    cudaGetSymbolAddress((void**)&pix, g_idx);
    cudaGetSymbolAddress((void**)&wpk, g_wpack);

    // pack: per layer l: [4l+0]=Wui, [4l+1]=Wuj, [4l+2]=local, [4l+3]=k2
    //       [12]=W_logits, [13]=W_weight, [14]=fc_w
    WP wp;
    for (int lyr = 0; lyr < 3; lyr++) {
        wp.p[4*lyr+0] = k1_w + (size_t)lyr*258*DD + 2*DD;
        wp.p[4*lyr+1] = k1_w + (size_t)lyr*258*DD + 130*DD;
        wp.p[4*lyr+2] = local_w + (size_t)lyr*DD*DD;
        wp.p[4*lyr+3] = k2_w + (size_t)lyr*DD*DD;
    }
    wp.p[12] = W_logits;
    wp.p[13] = W_weight;
    wp.p[14] = fc_w;
    k_pack<<<dim3(32,15), 256>>>(wp, (float2*)wpk);

    k_lift<<<NTOT, 128>>>(spikes, conv_w, conv_b, wpk + (size_t)14*8192, fc_b, u0);
    k_knn<<<dim3(NN/256, BB), 256>>>(coords, pix);

    float* ucur = u0;
    float* unext = u1;
    for (int lyr = 0; lyr < 3; lyr++) {
        const float* W1 = k1_w + (size_t)lyr*258*DD;
        k_node<3, true><<<dim3(NTOT/32, 2), 256>>>(ucur,
            wpk + (size_t)(4*lyr+0)*8192, wpk + (size_t)(4*lyr+1)*8192,
            wpk + (size_t)(4*lyr+2)*8192,
            k1_b + lyr*DD, local_b + lyr*DD,
            W1, W1 + DD, coords,
            pb, pp, pl);
        k_edge<<<NTOT/4, 512>>>(ucur, unext, pb, pp, pl, pix,
                                wpk + (size_t)(4*lyr+3)*8192,
                                k2_b + lyr*DD, k3_w + (size_t)lyr*DD, k3_b + lyr);
        float* t = ucur; ucur = unext; unext = t;
    }

    k_node<2, false><<<dim3(NTOT/32, 2), 256>>>(ucur,
        wpk + (size_t)12*8192, wpk + (size_t)13*8192, wpk,
        nullptr, nullptr, nullptr, nullptr, nullptr,
        pb, pp, pb);
    k_dec<<<dim3(NN/64, NN/64, BB), 512>>>(pb, pp, ucur, out);
}

// round 4
// speedup vs baseline: 1.1826x; 1.1120x over previous
#include <cuda_runtime.h>
#include <math.h>

#define BB 2
#define NN 2048
#define TT 256
#define DD 128
#define KK 16
#define NTOT (BB*NN)

typedef unsigned long long ull;

__device__ __forceinline__ ull ffma2(ull a, ull b, ull c){
    ull d; asm("fma.rn.f32x2 %0, %1, %2, %3;" : "=l"(d) : "l"(a), "l"(b), "l"(c));
    return d;
}
__device__ __forceinline__ float usum(ull v){
    float lo, hi; asm("mov.b64 {%0,%1}, %2;" : "=f"(lo), "=f"(hi) : "l"(v));
    return lo + hi;
}

// ---------------- scratch ----------------
__device__ float g_u   [NTOT*DD];
__device__ float g_u2  [NTOT*DD];
__device__ float g_base[NTOT*DD];
__device__ float g_proj[NTOT*DD];
__device__ float g_loc [NTOT*DD];
__device__ int   g_idx [NTOT*KK];
__device__ __align__(16) ull g_wpack[15*64*128];   // 15 matrices, k-pair packed

// ---------------- Kernel 0: weight repack into k-pair-interleaved layout ----
struct WP { const float* p[15]; };
__global__ void __launch_bounds__(256) k_pack(WP wp, float2* __restrict__ dst){
    int m = blockIdx.y;
    const float* W = wp.p[m];
    int i = blockIdx.x*256 + threadIdx.x;     // 0..8191
    int kp = i >> 7, c = i & 127;
    dst[(size_t)m*8192 + i] = make_float2(W[(2*kp)*DD + c], W[(2*kp+1)*DD + c]);
}

// ---------------- Kernel 1: TemporalLift ----
__global__ void __launch_bounds__(128) k_lift(
    const float* __restrict__ spikes, const float* __restrict__ conv_w,
    const float* __restrict__ conv_b, const ull* __restrict__ fcp,
    const float* __restrict__ fc_b, float* __restrict__ u)
{
    __shared__ __align__(16) float sp[TT+8];
    __shared__ __align__(16) float xm[DD];
    int node = blockIdx.x;
    int h = threadIdx.x;
    const float* s = spikes + (size_t)node*TT;
    sp[2+h]      = s[h];
    sp[2+h+128]  = s[h+128];
    if (h < 2) sp[h] = 0.f;
    if (h < 6) sp[TT+2+h] = 0.f;
    __syncthreads();
    float w0 = conv_w[h*5+0], w1 = conv_w[h*5+1], w2 = conv_w[h*5+2],
          w3 = conv_w[h*5+3], w4 = conv_w[h*5+4];
    float bb = conv_b[h];
    float acc = 0.f;
    #pragma unroll 4
    for (int t = 0; t < TT; t += 4) {
        float4 a = *(const float4*)&sp[t];
        float4 b = *(const float4*)&sp[t+4];
        float o0 = fmaf(w4,b.x, fmaf(w3,a.w, fmaf(w2,a.z, fmaf(w1,a.y, fmaf(w0,a.x, bb)))));
        float o1 = fmaf(w4,b.y, fmaf(w3,b.x, fmaf(w2,a.w, fmaf(w1,a.z, fmaf(w0,a.y, bb)))));
        float o2 = fmaf(w4,b.z, fmaf(w3,b.y, fmaf(w2,b.x, fmaf(w1,a.w, fmaf(w0,a.z, bb)))));
        float o3 = fmaf(w4,b.w, fmaf(w3,b.z, fmaf(w2,b.y, fmaf(w1,b.x, fmaf(w0,a.w, bb)))));
        acc += fmaxf(o0,0.f) + fmaxf(o1,0.f) + fmaxf(o2,0.f) + fmaxf(o3,0.f);
    }
    xm[h] = acc * (1.f/(float)TT);
    __syncthreads();
    ull o2 = 0ull;
    #pragma unroll 8
    for (int kp = 0; kp < 64; kp++)
        o2 = ffma2(*(const ull*)&xm[2*kp], __ldg(&fcp[kp*DD + h]), o2);
    float o = usum(o2) + fc_b[h];
    u[(size_t)node*DD + h] = fmaxf(o, 0.f);
}

// ---------------- Kernel 2: kNN ----
__global__ void __launch_bounds__(64) k_knn(
    const float* __restrict__ coords, int* __restrict__ idx)
{
    __shared__ float c[NN];
    int b = blockIdx.y;
    int i = blockIdx.x*64 + threadIdx.x;
    const float* cb = coords + (size_t)b*NN;
    for (int j = threadIdx.x; j < NN; j += 64) c[j] = cb[j];
    __syncthreads();
    float ci = c[i];
    float d2[KK]; int id[KK];
    #pragma unroll
    for (int p = 0; p < KK; p++) { d2[p] = 3.4e38f; id[p] = 0x7fffffff; }
    for (int j = 0; j < NN; j++) {
        float df = ci - c[j];
        float nd = df*df;
        if (nd < d2[KK-1] || (nd == d2[KK-1] && j < id[KK-1])) {
            d2[KK-1] = nd; id[KK-1] = j;
            #pragma unroll
            for (int p = KK-1; p > 0; --p) {
                bool sw = (d2[p] < d2[p-1]) || (d2[p] == d2[p-1] && id[p] < id[p-1]);
                if (!sw) break;
                float td = d2[p]; d2[p] = d2[p-1]; d2[p-1] = td;
                int   ti = id[p]; id[p] = id[p-1]; id[p-1] = ti;
            }
        }
    }
    int* o = idx + ((size_t)b*NN + i)*KK;
    #pragma unroll
    for (int p = 0; p < KK; p++) o[p] = id[p];
}

// ---------------- Kernel 3: fused node GEMM, up to 3 B-matrices -------------
// Block = 8 rows x 128 cols, 256 threads (8 warps).
// Warp w: col-half ch=w&1, rows (w>>1)*2 .. +1. Lane l: 2 cols.
template<int NMAT, bool EX>
__global__ void __launch_bounds__(256, 4) k_node(
    const float* __restrict__ X,
    const ull* __restrict__ W0, const ull* __restrict__ W1, const ull* __restrict__ W2,
    const float* __restrict__ cb0, const float* __restrict__ cb2,
    const float* __restrict__ rv0, const float* __restrict__ rv1,
    const float* __restrict__ xs,
    float* __restrict__ Y0, float* __restrict__ Y1, float* __restrict__ Y2)
{
    __shared__ __align__(16) float Xs[8*DD];
    __shared__ float xc[8];
    int tid = threadIdx.x;
    int row0 = blockIdx.x*8;
    ((float4*)Xs)[tid] = ((const float4*)(X + (size_t)row0*DD))[tid];
    if (EX && tid < 8) xc[tid] = xs[row0 + tid];
    __syncthreads();

    int l = tid & 31, w = tid >> 5;
    int ch = w & 1, r0 = (w >> 1)*2;
    int coff = ch*64 + 2*l;
    const ull* Ws[3] = {W0, W1, (NMAT > 2) ? W2 : W0};
    ull acc[NMAT][2][2];
    #pragma unroll
    for (int m = 0; m < NMAT; m++)
        #pragma unroll
        for (int r = 0; r < 2; r++) { acc[m][r][0] = 0ull; acc[m][r][1] = 0ull; }

    #pragma unroll 2
    for (int kpp = 0; kpp < 32; kpp++) {
        ulonglong2 a0 = *(const ulonglong2*)&Xs[(r0  )*DD + 4*kpp];
        ulonglong2 a1 = *(const ulonglong2*)&Xs[(r0+1)*DD + 4*kpp];
        #pragma unroll
        for (int m = 0; m < NMAT; m++) {
            ulonglong2 b0 = *(const ulonglong2*)(Ws[m] + (size_t)(2*kpp)*DD + coff);
            ulonglong2 b1 = *(const ulonglong2*)(Ws[m] + (size_t)(2*kpp+1)*DD + coff);
            acc[m][0][0] = ffma2(a0.x, b0.x, acc[m][0][0]);
            acc[m][0][1] = ffma2(a0.x, b0.y, acc[m][0][1]);
            acc[m][0][0] = ffma2(a0.y, b1.x, acc[m][0][0]);
            acc[m][0][1] = ffma2(a0.y, b1.y, acc[m][0][1]);
            acc[m][1][0] = ffma2(a1.x, b0.x, acc[m][1][0]);
            acc[m][1][1] = ffma2(a1.x, b0.y, acc[m][1][1]);
            acc[m][1][0] = ffma2(a1.y, b1.x, acc[m][1][0]);
            acc[m][1][1] = ffma2(a1.y, b1.y, acc[m][1][1]);
        }
    }

    float2 cb0v = make_float2(0.f,0.f), cb2v = cb0v, r0v = cb0v, r1v = cb0v;
    if (EX) {
        cb0v = *(const float2*)(cb0 + coff);
        cb2v = *(const float2*)(cb2 + coff);
        r0v  = *(const float2*)(rv0 + coff);
        r1v  = *(const float2*)(rv1 + coff);
    }
    float* Ys[3] = {Y0, Y1, (NMAT > 2) ? Y2 : Y0};
    #pragma unroll
    for (int r = 0; r < 2; r++) {
        int n = row0 + r0 + r;
        float xv = EX ? xc[r0 + r] : 0.f;
        #pragma unroll
        for (int m = 0; m < NMAT; m++) {
            float s0 = usum(acc[m][r][0]);
            float s1 = usum(acc[m][r][1]);
            if (EX) {
                if (m == 0) { s0 += cb0v.x + xv*r0v.x; s1 += cb0v.y + xv*r0v.y; }
                if (m == 1) { s0 += xv*r1v.x;          s1 += xv*r1v.y; }
                if (m == 2) { s0 += cb2v.x;            s1 += cb2v.y; }
            }
            *(float2*)(Ys[m] + (size_t)n*DD + coff) = make_float2(s0, s1);
        }
    }
}

// ---------------- Kernel 4: edge MLP + aggregation + residual ---------------
// Block = 2 nodes (32 edges), 256 threads (8 warps).
// GEMM: warp = 8 edges x 64-col half; lane = 2 cols.
__global__ void __launch_bounds__(256, 4) k_edge(
    const float* __restrict__ u_in, float* __restrict__ u_out,
    const float* __restrict__ base, const float* __restrict__ proj,
    const float* __restrict__ loc, const int* __restrict__ idx,
    const ull* __restrict__ k2p, const float* __restrict__ k2b,
    const float* __restrict__ k3w, const float* __restrict__ k3b)
{
    __shared__ __align__(16) float h1s[32*DD];
    __shared__ __align__(16) float bss[2*DD];
    __shared__ int   js[32];
    __shared__ float kvs[32][2];
    __shared__ float kvv[32];

    int tid = threadIdx.x;
    int node0 = blockIdx.x * 2;
    int bbase = node0 & ~(NN-1);

    if (tid < 64)
        ((float4*)bss)[tid] = ((const float4*)(base + (size_t)node0*DD))[tid];
    if (tid < 32) js[tid] = idx[node0*KK + tid];
    __syncthreads();

    int l = tid & 31, w = tid >> 5;
    // h1 = relu(base_i + proj_j): warp w builds edges w*4..w*4+3
    #pragma unroll
    for (int r = 0; r < 4; r++) {
        int e = w*4 + r;
        int j = js[e];
        float4 p  = ((const float4*)(proj + (size_t)(bbase + j)*DD))[l];
        float4 bq = ((const float4*)bss)[(e>>4)*32 + l];
        float4 h;
        h.x = fmaxf(p.x+bq.x, 0.f);
        h.y = fmaxf(p.y+bq.y, 0.f);
        h.z = fmaxf(p.z+bq.z, 0.f);
        h.w = fmaxf(p.w+bq.w, 0.f);
        ((float4*)h1s)[e*32 + l] = h;
    }
    __syncthreads();

    int ch = w & 1, eg = (w >> 1)*8;
    const ull* k2c = k2p + ch*64 + 2*l;
    ull acc[8][2];
    #pragma unroll
    for (int r = 0; r < 8; r++) { acc[r][0] = 0ull; acc[r][1] = 0ull; }

    #pragma unroll 2
    for (int kpp = 0; kpp < 32; kpp++) {
        ulonglong2 b0 = *(const ulonglong2*)(k2c + (size_t)(2*kpp)*DD);
        ulonglong2 b1 = *(const ulonglong2*)(k2c + (size_t)(2*kpp+1)*DD);
        #pragma unroll
        for (int r = 0; r < 8; r++) {
            ulonglong2 a2 = *(const ulonglong2*)&h1s[(eg+r)*DD + 4*kpp];
            acc[r][0] = ffma2(a2.x, b0.x, acc[r][0]);
            acc[r][1] = ffma2(a2.x, b0.y, acc[r][1]);
            acc[r][0] = ffma2(a2.y, b1.x, acc[r][0]);
            acc[r][1] = ffma2(a2.y, b1.y, acc[r][1]);
        }
    }

    int c0 = ch*64 + 2*l;
    float b2a = k2b[c0], b2b = k2b[c0+1];
    float k3a = k3w[c0], k3c = k3w[c0+1];
    #pragma unroll
    for (int r = 0; r < 8; r++) {
        float part = fmaxf(usum(acc[r][0]) + b2a, 0.f)*k3a
                   + fmaxf(usum(acc[r][1]) + b2b, 0.f)*k3c;
        #pragma unroll
        for (int s = 16; s > 0; s >>= 1)
            part += __shfl_xor_sync(0xffffffffu, part, s);
        if (l == 0) kvs[eg + r][ch] = part;
    }
    __syncthreads();
    if (tid < 32) kvv[tid] = (kvs[tid][0] + kvs[tid][1] + k3b[0]) * 0.25f;
    __syncthreads();

    // agg + residual + relu: 256 threads = 2 nodes x 128 dims
    int d  = tid & 127;
    int g  = tid >> 7;
    int n = node0 + g;
    float a = 0.f;
    #pragma unroll
    for (int kk = 0; kk < KK; kk++) {
        int j = js[g*KK + kk];
        a = fmaf(kvv[g*KK+kk], u_in[((size_t)(bbase+j))*DD + d], a);
    }
    float o = loc[(size_t)n*DD + d] + a + u_in[(size_t)n*DD + d];
    u_out[(size_t)n*DD + d] = fmaxf(o, 0.f);
}

// ---------------- Kernel 5: decoder 64x64 tile, dual GEMM + epilogue --------
// 512 threads, 2 blocks/SM forced. Warp = 4 rows x 64 cols; lane = cols {l, l+32}.
// B tile (u) in smem k-major float2, stride 67 (conflict-free LDS.64).
__global__ void __launch_bounds__(512, 2) k_dec(
    const float* __restrict__ v, const float* __restrict__ wmat,
    const float* __restrict__ u, float* __restrict__ out)
{
    __shared__ __align__(16) float2 us2[64*67];   // [kp][m]
    int tid = threadIdx.x;
    int bx = blockIdx.x, by = blockIdx.y, bz = blockIdx.z;
    size_t nb = (size_t)bz * NN;

    #pragma unroll
    for (int i = 0; i < 8; i++) {
        int ii = tid + i*512;
        int m = ii >> 6, kp = ii & 63;
        us2[kp*67 + m] = *(const float2*)&u[(nb + (size_t)bx*64 + m)*DD + 2*kp];
    }
    __syncthreads();

    int l = tid & 31, w = tid >> 5;
    const float* vrow = v    + (nb + (size_t)by*64 + w*4)*DD;
    const float* wrow = wmat + (nb + (size_t)by*64 + w*4)*DD;

    ull aV[4][2], aW[4][2];
    #pragma unroll
    for (int r = 0; r < 4; r++) { aV[r][0]=aV[r][1]=aW[r][0]=aW[r][1]=0ull; }

    for (int kpp = 0; kpp < 32; kpp++) {
        ull b00 = *(const ull*)&us2[(2*kpp  )*67 + l];
        ull b01 = *(const ull*)&us2[(2*kpp+1)*67 + l];
        ull b10 = *(const ull*)&us2[(2*kpp  )*67 + l + 32];
        ull b11 = *(const ull*)&us2[(2*kpp+1)*67 + l + 32];
        #pragma unroll
        for (int r = 0; r < 4; r++) {
            ulonglong2 av = *(const ulonglong2*)&vrow[r*DD + 4*kpp];
            ulonglong2 aw = *(const ulonglong2*)&wrow[r*DD + 4*kpp];
            aV[r][0] = ffma2(av.x, b00, aV[r][0]);
            aV[r][0] = ffma2(av.y, b01, aV[r][0]);
            aV[r][1] = ffma2(av.x, b10, aV[r][1]);
            aV[r][1] = ffma2(av.y, b11, aV[r][1]);
            aW[r][0] = ffma2(aw.x, b00, aW[r][0]);
            aW[r][0] = ffma2(aw.y, b01, aW[r][0]);
            aW[r][1] = ffma2(aw.x, b10, aW[r][1]);
            aW[r][1] = ffma2(aw.y, b11, aW[r][1]);
        }
    }

    size_t N2 = (size_t)NN*NN;
    size_t S  = (size_t)BB*N2;
    #pragma unroll
    for (int r = 0; r < 4; r++) {
        int row = by*64 + w*4 + r;
        size_t o = (size_t)bz*N2 + (size_t)row*NN + bx*64 + l;
        float lg0 = usum(aV[r][0]);
        float lg1 = usum(aV[r][1]);
        out[o]      = lg0;
        out[o + 32] = lg1;
        out[S + o]      = __fdividef(1.f, 1.f + __expf(-lg0));
        out[S + o + 32] = __fdividef(1.f, 1.f + __expf(-lg1));
        float w0 = usum(aW[r][0]);
        float w1 = usum(aW[r][1]);
        out[2*S + o]      = fmaxf(w0, 0.f) + __logf(1.f + __expf(-fabsf(w0)));
        out[2*S + o + 32] = fmaxf(w1, 0.f) + __logf(1.f + __expf(-fabsf(w1)));
    }
}

// ---------------- launch -----------------------------------------------------
extern "C" void kernel_launch(void* const* d_in, const int* in_sizes, int n_in,
                              void* d_out, int out_size)
{
    const float* spikes   = (const float*)d_in[0];
    const float* coords   = (const float*)d_in[1];
    const float* conv_w   = (const float*)d_in[2];
    const float* conv_b   = (const float*)d_in[3];
    const float* fc_w     = (const float*)d_in[4];
    const float* fc_b     = (const float*)d_in[5];
    const float* local_w  = (const float*)d_in[6];
    const float* local_b  = (const float*)d_in[7];
    const float* k1_w     = (const float*)d_in[8];
    const float* k1_b     = (const float*)d_in[9];
    const float* k2_w     = (const float*)d_in[10];
    const float* k2_b     = (const float*)d_in[11];
    const float* k3_w     = (const float*)d_in[12];
    const float* k3_b     = (const float*)d_in[13];
    const float* W_logits = (const float*)d_in[14];
    const float* W_weight = (const float*)d_in[15];
    float* out = (float*)d_out;

    float *u0, *u1, *pb, *pp, *pl; int* pix; ull* wpk;
    cudaGetSymbolAddress((void**)&u0,  g_u);
    cudaGetSymbolAddress((void**)&u1,  g_u2);
    cudaGetSymbolAddress((void**)&pb,  g_base);
    cudaGetSymbolAddress((void**)&pp,  g_proj);
    cudaGetSymbolAddress((void**)&pl,  g_loc);
    cudaGetSymbolAddress((void**)&pix, g_idx);
    cudaGetSymbolAddress((void**)&wpk, g_wpack);

    // pack: per layer l: [4l+0]=Wui, [4l+1]=Wuj, [4l+2]=local, [4l+3]=k2
    //       [12]=W_logits, [13]=W_weight, [14]=fc_w
    WP wp;
    for (int lyr = 0; lyr < 3; lyr++) {
        wp.p[4*lyr+0] = k1_w + (size_t)lyr*258*DD + 2*DD;
        wp.p[4*lyr+1] = k1_w + (size_t)lyr*258*DD + 130*DD;
        wp.p[4*lyr+2] = local_w + (size_t)lyr*DD*DD;
        wp.p[4*lyr+3] = k2_w + (size_t)lyr*DD*DD;
    }
    wp.p[12] = W_logits;
    wp.p[13] = W_weight;
    wp.p[14] = fc_w;
    k_pack<<<dim3(32,15), 256>>>(wp, (float2*)wpk);

    k_lift<<<NTOT, 128>>>(spikes, conv_w, conv_b, wpk + (size_t)14*8192, fc_b, u0);
    k_knn<<<dim3(NN/64, BB), 64>>>(coords, pix);

    float* ucur = u0;
    float* unext = u1;
    for (int lyr = 0; lyr < 3; lyr++) {
        const float* W1 = k1_w + (size_t)lyr*258*DD;
        k_node<3, true><<<NTOT/8, 256>>>(ucur,
            wpk + (size_t)(4*lyr+0)*8192, wpk + (size_t)(4*lyr+1)*8192,
            wpk + (size_t)(4*lyr+2)*8192,
            k1_b + lyr*DD, local_b + lyr*DD,
            W1, W1 + DD, coords,
            pb, pp, pl);
        k_edge<<<NTOT/2, 256>>>(ucur, unext, pb, pp, pl, pix,
                                wpk + (size_t)(4*lyr+3)*8192,
                                k2_b + lyr*DD, k3_w + (size_t)lyr*DD, k3_b + lyr);
        float* t = ucur; ucur = unext; unext = t;
    }

    k_node<2, false><<<NTOT/8, 256>>>(ucur,
        wpk + (size_t)12*8192, wpk + (size_t)13*8192, wpk,
        nullptr, nullptr, nullptr, nullptr, nullptr,
        pb, pp, pb);
    k_dec<<<dim3(NN/64, NN/64, BB), 512>>>(pb, pp, ucur, out);
}

// round 5
// speedup vs baseline: 1.5498x; 1.3105x over previous
#include <cuda_runtime.h>
#include <cuda_bf16.h>
#include <math.h>

#define BB 2
#define NN 2048
#define TT 256
#define DD 128
#define KK 16
#define NTOT (BB*NN)

typedef unsigned long long ull;
typedef unsigned int u32;

// ---------------- scalar f32x2 helpers ----------------
__device__ __forceinline__ ull ffma2(ull a, ull b, ull c){
    ull d; asm("fma.rn.f32x2 %0, %1, %2, %3;" : "=l"(d) : "l"(a), "l"(b), "l"(c));
    return d;
}
__device__ __forceinline__ float usum(ull v){
    float lo, hi; asm("mov.b64 {%0,%1}, %2;" : "=f"(lo), "=f"(hi) : "l"(v));
    return lo + hi;
}

// ---------------- mma helpers ----------------
__device__ __forceinline__ u32 smaddr(const void* p){
    return (u32)__cvta_generic_to_shared(p);
}
__device__ __forceinline__ void ldsm4(u32 &r0,u32 &r1,u32 &r2,u32 &r3, u32 a){
    asm volatile("ldmatrix.sync.aligned.m8n8.x4.shared.b16 {%0,%1,%2,%3}, [%4];"
                 : "=r"(r0),"=r"(r1),"=r"(r2),"=r"(r3) : "r"(a));
}
__device__ __forceinline__ void mma_bf16(float* c, const u32* a, u32 b0, u32 b1){
    asm volatile("mma.sync.aligned.m16n8k16.row.col.f32.bf16.bf16.f32 "
        "{%0,%1,%2,%3},{%4,%5,%6,%7},{%8,%9},{%0,%1,%2,%3};"
        : "+f"(c[0]),"+f"(c[1]),"+f"(c[2]),"+f"(c[3])
        : "r"(a[0]),"r"(a[1]),"r"(a[2]),"r"(a[3]),"r"(b0),"r"(b1));
}
// A tile (row-major [row][k], stride sB bytes): 16x16 fragment at (row0, k0)
__device__ __forceinline__ u32 a_addr(u32 base, int row0, int k0, int lane, int sB){
    int g = lane >> 3, r = lane & 7;
    return base + (u32)((row0 + r + (g & 1)*8)*sB + (k0 + (g >> 1)*8)*2);
}
// B tile stored [n][k] rows (== col-major kxn), 16 n-cols at (n0, k0) -> 2 n8 chunks
__device__ __forceinline__ u32 b_addr(u32 base, int n0, int k0, int lane, int sB){
    int g = lane >> 3, r = lane & 7;
    return base + (u32)((n0 + r + (g >> 1)*8)*sB + (k0 + (g & 1)*8)*2);
}
__device__ __forceinline__ void split_bf(float x, __nv_bfloat16 &h, __nv_bfloat16 &l){
    h = __float2bfloat16(x);
    l = __float2bfloat16(x - __bfloat162float(h));
}

// ---------------- scratch ----------------
__device__ float g_u   [NTOT*DD];
__device__ float g_u2  [NTOT*DD];
__device__ float g_base[NTOT*DD];
__device__ float g_proj[NTOT*DD];
__device__ float g_loc [NTOT*DD];
__device__ int   g_idx [NTOT*KK];
__device__ __align__(16) ull g_wpack[15*64*128];             // node-gemm k-pair packs
__device__ __align__(16) __nv_bfloat16 g_spl[6*NTOT*DD];     // vh,vl,wh,wl,uh,ul
__device__ __align__(16) __nv_bfloat16 g_k2th[3*DD*DD];      // k2^T hi
__device__ __align__(16) __nv_bfloat16 g_k2tl[3*DD*DD];      // k2^T lo

// ---------------- Kernel 0a: scalar weight repack (node GEMMs) ----------------
struct WP { const float* p[15]; };
__global__ void __launch_bounds__(256) k_pack(WP wp, float2* __restrict__ dst){
    int m = blockIdx.y;
    const float* W = wp.p[m];
    int i = blockIdx.x*256 + threadIdx.x;     // 0..8191
    int kp = i >> 7, c = i & 127;
    dst[(size_t)m*8192 + i] = make_float2(W[(2*kp)*DD + c], W[(2*kp+1)*DD + c]);
}

// ---------------- Kernel 0b: k2 transposed + split to bf16 hi/lo --------------
__global__ void __launch_bounds__(256) k_packt(const float* __restrict__ k2w,
        __nv_bfloat16* __restrict__ th, __nv_bfloat16* __restrict__ tl){
    int lyr = blockIdx.y;
    int i = blockIdx.x*256 + threadIdx.x;     // 0..16383
    int c = i >> 7, k = i & 127;
    float v = k2w[(size_t)lyr*DD*DD + k*DD + c];
    __nv_bfloat16 h, l; split_bf(v, h, l);
    th[(size_t)lyr*DD*DD + c*DD + k] = h;
    tl[(size_t)lyr*DD*DD + c*DD + k] = l;
}

// ---------------- Kernel 0c: fp32 -> bf16 hi/lo split --------------------------
struct SP { const float* s[3]; };
__global__ void __launch_bounds__(256) k_split(SP sp, __nv_bfloat16* __restrict__ dst){
    int a = blockIdx.y;
    int i = (blockIdx.x*256 + threadIdx.x)*4;
    float4 v = *(const float4*)(sp.s[a] + i);
    __nv_bfloat16 h0,h1,h2,h3,l0,l1,l2,l3;
    split_bf(v.x,h0,l0); split_bf(v.y,h1,l1); split_bf(v.z,h2,l2); split_bf(v.w,h3,l3);
    __nv_bfloat162 hp0, hp1, lp0, lp1;
    hp0.x=h0; hp0.y=h1; hp1.x=h2; hp1.y=h3;
    lp0.x=l0; lp0.y=l1; lp1.x=l2; lp1.y=l3;
    __nv_bfloat162* H = (__nv_bfloat162*)(dst + (size_t)(2*a  )*NTOT*DD);
    __nv_bfloat162* L = (__nv_bfloat162*)(dst + (size_t)(2*a+1)*NTOT*DD);
    H[i/2] = hp0; H[i/2+1] = hp1;
    L[i/2] = lp0; L[i/2+1] = lp1;
}

// ---------------- Kernel 1: TemporalLift ----
__global__ void __launch_bounds__(128) k_lift(
    const float* __restrict__ spikes, const float* __restrict__ conv_w,
    const float* __restrict__ conv_b, const ull* __restrict__ fcp,
    const float* __restrict__ fc_b, float* __restrict__ u)
{
    __shared__ __align__(16) float sp[TT+8];
    __shared__ __align__(16) float xm[DD];
    int node = blockIdx.x;
    int h = threadIdx.x;
    const float* s = spikes + (size_t)node*TT;
    sp[2+h]      = s[h];
    sp[2+h+128]  = s[h+128];
    if (h < 2) sp[h] = 0.f;
    if (h < 6) sp[TT+2+h] = 0.f;
    __syncthreads();
    float w0 = conv_w[h*5+0], w1 = conv_w[h*5+1], w2 = conv_w[h*5+2],
          w3 = conv_w[h*5+3], w4 = conv_w[h*5+4];
    float bb = conv_b[h];
    float acc = 0.f;
    #pragma unroll 4
    for (int t = 0; t < TT; t += 4) {
        float4 a = *(const float4*)&sp[t];
        float4 b = *(const float4*)&sp[t+4];
        float o0 = fmaf(w4,b.x, fmaf(w3,a.w, fmaf(w2,a.z, fmaf(w1,a.y, fmaf(w0,a.x, bb)))));
        float o1 = fmaf(w4,b.y, fmaf(w3,b.x, fmaf(w2,a.w, fmaf(w1,a.z, fmaf(w0,a.y, bb)))));
        float o2 = fmaf(w4,b.z, fmaf(w3,b.y, fmaf(w2,b.x, fmaf(w1,a.w, fmaf(w0,a.z, bb)))));
        float o3 = fmaf(w4,b.w, fmaf(w3,b.z, fmaf(w2,b.y, fmaf(w1,b.x, fmaf(w0,a.w, bb)))));
        acc += fmaxf(o0,0.f) + fmaxf(o1,0.f) + fmaxf(o2,0.f) + fmaxf(o3,0.f);
    }
    xm[h] = acc * (1.f/(float)TT);
    __syncthreads();
    ull o2 = 0ull;
    #pragma unroll 8
    for (int kp = 0; kp < 64; kp++)
        o2 = ffma2(*(const ull*)&xm[2*kp], __ldg(&fcp[kp*DD + h]), o2);
    float o = usum(o2) + fc_b[h];
    u[(size_t)node*DD + h] = fmaxf(o, 0.f);
}

// ---------------- Kernel 2: kNN ----
__global__ void __launch_bounds__(64) k_knn(
    const float* __restrict__ coords, int* __restrict__ idx)
{
    __shared__ float c[NN];
    int b = blockIdx.y;
    int i = blockIdx.x*64 + threadIdx.x;
    const float* cb = coords + (size_t)b*NN;
    for (int j = threadIdx.x; j < NN; j += 64) c[j] = cb[j];
    __syncthreads();
    float ci = c[i];
    float d2[KK]; int id[KK];
    #pragma unroll
    for (int p = 0; p < KK; p++) { d2[p] = 3.4e38f; id[p] = 0x7fffffff; }
    for (int j = 0; j < NN; j++) {
        float df = ci - c[j];
        float nd = df*df;
        if (nd < d2[KK-1] || (nd == d2[KK-1] && j < id[KK-1])) {
            d2[KK-1] = nd; id[KK-1] = j;
            #pragma unroll
            for (int p = KK-1; p > 0; --p) {
                bool sw = (d2[p] < d2[p-1]) || (d2[p] == d2[p-1] && id[p] < id[p-1]);
                if (!sw) break;
                float td = d2[p]; d2[p] = d2[p-1]; d2[p-1] = td;
                int   ti = id[p]; id[p] = id[p-1]; id[p-1] = ti;
            }
        }
    }
    int* o = idx + ((size_t)b*NN + i)*KK;
    #pragma unroll
    for (int p = 0; p < KK; p++) o[p] = id[p];
}

// ---------------- Kernel 3: fused node GEMM (scalar f32x2) -------------------
template<int NMAT, bool EX>
__global__ void __launch_bounds__(256, 4) k_node(
    const float* __restrict__ X,
    const ull* __restrict__ W0, const ull* __restrict__ W1, const ull* __restrict__ W2,
    const float* __restrict__ cb0, const float* __restrict__ cb2,
    const float* __restrict__ rv0, const float* __restrict__ rv1,
    const float* __restrict__ xs,
    float* __restrict__ Y0, float* __restrict__ Y1, float* __restrict__ Y2)
{
    __shared__ __align__(16) float Xs[8*DD];
    __shared__ float xc[8];
    int tid = threadIdx.x;
    int row0 = blockIdx.x*8;
    ((float4*)Xs)[tid] = ((const float4*)(X + (size_t)row0*DD))[tid];
    if (EX && tid < 8) xc[tid] = xs[row0 + tid];
    __syncthreads();

    int l = tid & 31, w = tid >> 5;
    int ch = w & 1, r0 = (w >> 1)*2;
    int coff = ch*64 + 2*l;
    const ull* Ws[3] = {W0, W1, (NMAT > 2) ? W2 : W0};
    ull acc[NMAT][2][2];
    #pragma unroll
    for (int m = 0; m < NMAT; m++)
        #pragma unroll
        for (int r = 0; r < 2; r++) { acc[m][r][0] = 0ull; acc[m][r][1] = 0ull; }

    #pragma unroll 2
    for (int kpp = 0; kpp < 32; kpp++) {
        ulonglong2 a0 = *(const ulonglong2*)&Xs[(r0  )*DD + 4*kpp];
        ulonglong2 a1 = *(const ulonglong2*)&Xs[(r0+1)*DD + 4*kpp];
        #pragma unroll
        for (int m = 0; m < NMAT; m++) {
            ulonglong2 b0 = *(const ulonglong2*)(Ws[m] + (size_t)(2*kpp)*DD + coff);
            ulonglong2 b1 = *(const ulonglong2*)(Ws[m] + (size_t)(2*kpp+1)*DD + coff);
            acc[m][0][0] = ffma2(a0.x, b0.x, acc[m][0][0]);
            acc[m][0][1] = ffma2(a0.x, b0.y, acc[m][0][1]);
            acc[m][0][0] = ffma2(a0.y, b1.x, acc[m][0][0]);
            acc[m][0][1] = ffma2(a0.y, b1.y, acc[m][0][1]);
            acc[m][1][0] = ffma2(a1.x, b0.x, acc[m][1][0]);
            acc[m][1][1] = ffma2(a1.x, b0.y, acc[m][1][1]);
            acc[m][1][0] = ffma2(a1.y, b1.x, acc[m][1][0]);
            acc[m][1][1] = ffma2(a1.y, b1.y, acc[m][1][1]);
        }
    }

    float2 cb0v = make_float2(0.f,0.f), cb2v = cb0v, r0v = cb0v, r1v = cb0v;
    if (EX) {
        cb0v = *(const float2*)(cb0 + coff);
        cb2v = *(const float2*)(cb2 + coff);
        r0v  = *(const float2*)(rv0 + coff);
        r1v  = *(const float2*)(rv1 + coff);
    }
    float* Ys[3] = {Y0, Y1, (NMAT > 2) ? Y2 : Y0};
    #pragma unroll
    for (int r = 0; r < 2; r++) {
        int n = row0 + r0 + r;
        float xv = EX ? xc[r0 + r] : 0.f;
        #pragma unroll
        for (int m = 0; m < NMAT; m++) {
            float s0 = usum(acc[m][r][0]);
            float s1 = usum(acc[m][r][1]);
            if (EX) {
                if (m == 0) { s0 += cb0v.x + xv*r0v.x; s1 += cb0v.y + xv*r0v.y; }
                if (m == 1) { s0 += xv*r1v.x;          s1 += xv*r1v.y; }
                if (m == 2) { s0 += cb2v.x;            s1 += cb2v.y; }
            }
            *(float2*)(Ys[m] + (size_t)n*DD + coff) = make_float2(s0, s1);
        }
    }
}

// ---------------- Kernel 4: edge MLP via tensor cores ------------------------
// Block = 4 nodes (64 edges), 256 threads. Warp (mg = edges of node mg, nh = 64-col half).
// h2 GEMM: split-bf16 3-MMA. Then Kv reduce + aggregation + residual.
__global__ void __launch_bounds__(256) k_edge_mma(
    const float* __restrict__ u_in, float* __restrict__ u_out,
    const float* __restrict__ base_, const float* __restrict__ proj,
    const float* __restrict__ loc, const int* __restrict__ idx,
    const __nv_bfloat16* __restrict__ k2th, const __nv_bfloat16* __restrict__ k2tl,
    const float* __restrict__ k2b, const float* __restrict__ k3w,
    const float* __restrict__ k3b)
{
    extern __shared__ __align__(16) unsigned char dynraw[];
    __nv_bfloat16* sHh = (__nv_bfloat16*)dynraw;      // 64 x 72 (stride 144B)
    __nv_bfloat16* sHl = sHh + 64*72;
    __nv_bfloat16* sBh = sHl + 64*72;                 // 128 x 72
    __nv_bfloat16* sBl = sBh + 128*72;
    __shared__ __align__(16) float bss[4*DD];
    __shared__ int   js[64];
    __shared__ float kvp[64][2];
    __shared__ float kvv[64];

    int tid = threadIdx.x;
    int node0 = blockIdx.x*4;
    int bbase = node0 & ~(NN-1);
    if (tid < 128) ((float4*)bss)[tid] = ((const float4*)(base_ + (size_t)node0*DD))[tid];
    if (tid < 64) js[tid] = idx[node0*KK + tid];
    __syncthreads();

    int l = tid & 31, w = tid >> 5;
    int mg = w >> 1, nh = w & 1;
    int row0 = mg*16, n0 = nh*64;
    const int SBH = 144;
    u32 bH  = smaddr(sHh), bHl2 = smaddr(sHl);
    u32 bBh = smaddr(sBh), bBl  = smaddr(sBl);

    float C[8][4] = {};
    for (int kc = 0; kc < 128; kc += 64) {
        if (kc) __syncthreads();
        // stage h1 = relu(base_i + proj_j), split to hi/lo bf16
        #pragma unroll
        for (int it = 0; it < 4; it++) {
            int id2 = tid + it*256;
            int e = id2 >> 4, q = id2 & 15;
            int j = js[e];
            float4 p = *(const float4*)(proj + (size_t)(bbase+j)*DD + kc + q*4);
            const float* bp = &bss[(e>>4)*DD + kc + q*4];
            float h0 = fmaxf(p.x + bp[0], 0.f);
            float h1 = fmaxf(p.y + bp[1], 0.f);
            float h2 = fmaxf(p.z + bp[2], 0.f);
            float h3 = fmaxf(p.w + bp[3], 0.f);
            __nv_bfloat16 a0,a1,a2,a3,c0,c1,c2,c3;
            split_bf(h0,a0,c0); split_bf(h1,a1,c1); split_bf(h2,a2,c2); split_bf(h3,a3,c3);
            __nv_bfloat162 hp0, hp1, lp0, lp1;
            hp0.x=a0; hp0.y=a1; hp1.x=a2; hp1.y=a3;
            lp0.x=c0; lp0.y=c1; lp1.x=c2; lp1.y=c3;
            __nv_bfloat162* dh = (__nv_bfloat162*)&sHh[e*72 + q*4];
            dh[0] = hp0; dh[1] = hp1;
            __nv_bfloat162* dl = (__nv_bfloat162*)&sHl[e*72 + q*4];
            dl[0] = lp0; dl[1] = lp1;
        }
        // stage k2t slice (128 cols x 64 k)
        #pragma unroll
        for (int it = 0; it < 8; it++) {
            int id2 = tid + it*256;
            int c = id2 >> 4, q = id2 & 15;
            ((ull*)sBh)[c*18 + q] = *((const ull*)k2th + ((c*DD + kc) >> 2) + q);
            ((ull*)sBl)[c*18 + q] = *((const ull*)k2tl + ((c*DD + kc) >> 2) + q);
        }
        __syncthreads();
        // mma over 4 k-steps of this slice
        #pragma unroll
        for (int k0 = 0; k0 < 64; k0 += 16) {
            u32 ah[4], al[4], bh[16], bl[16];
            ldsm4(ah[0],ah[1],ah[2],ah[3], a_addr(bH,   row0, k0, l, SBH));
            ldsm4(al[0],al[1],al[2],al[3], a_addr(bHl2, row0, k0, l, SBH));
            #pragma unroll
            for (int nc = 0; nc < 4; nc++) {
                ldsm4(bh[4*nc],bh[4*nc+1],bh[4*nc+2],bh[4*nc+3],
                      b_addr(bBh, n0 + nc*16, k0, l, SBH));
                ldsm4(bl[4*nc],bl[4*nc+1],bl[4*nc+2],bl[4*nc+3],
                      b_addr(bBl, n0 + nc*16, k0, l, SBH));
            }
            #pragma unroll
            for (int c = 0; c < 8; c++) {
                mma_bf16(C[c], ah, bh[2*c], bh[2*c+1]);
                mma_bf16(C[c], ah, bl[2*c], bl[2*c+1]);
                mma_bf16(C[c], al, bh[2*c], bh[2*c+1]);
            }
        }
    }

    // Kv reduction: kp[e] = sum_c relu(h2+b2)*k3
    float pr0 = 0.f, pr1 = 0.f;
    int ccl = 2*(l & 3);
    #pragma unroll
    for (int c = 0; c < 8; c++) {
        int col = n0 + c*8 + ccl;
        float b20 = __ldg(k2b+col), b21 = __ldg(k2b+col+1);
        float k30 = __ldg(k3w+col), k31 = __ldg(k3w+col+1);
        pr0 += fmaxf(C[c][0]+b20,0.f)*k30 + fmaxf(C[c][1]+b21,0.f)*k31;
        pr1 += fmaxf(C[c][2]+b20,0.f)*k30 + fmaxf(C[c][3]+b21,0.f)*k31;
    }
    pr0 += __shfl_xor_sync(0xffffffffu, pr0, 1);
    pr0 += __shfl_xor_sync(0xffffffffu, pr0, 2);
    pr1 += __shfl_xor_sync(0xffffffffu, pr1, 1);
    pr1 += __shfl_xor_sync(0xffffffffu, pr1, 2);
    if ((l & 3) == 0) {
        kvp[row0 + (l>>2)    ][nh] = pr0;
        kvp[row0 + (l>>2) + 8][nh] = pr1;
    }
    __syncthreads();
    if (tid < 64) kvv[tid] = (kvp[tid][0] + kvp[tid][1] + k3b[0])*0.25f;
    __syncthreads();

    // agg + residual + relu: 4 nodes x 128 dims on 256 threads
    int d = tid & 127;
    #pragma unroll
    for (int gg = 0; gg < 4; gg += 2) {
        int g = gg + (tid >> 7);
        int n = node0 + g;
        float a = 0.f;
        #pragma unroll
        for (int kk = 0; kk < KK; kk++)
            a = fmaf(kvv[g*KK+kk], u_in[(size_t)(bbase+js[g*KK+kk])*DD + d], a);
        float o = loc[(size_t)n*DD + d] + a + u_in[(size_t)n*DD + d];
        u_out[(size_t)n*DD + d] = fmaxf(o, 0.f);
    }
}

// ---------------- Kernel 5: decoder 64x64 tile via tensor cores --------------
// Warp (mg 0-3, nh 0-1): 16 rows x 32 cols, both V and W outputs.
__global__ void __launch_bounds__(256) k_dec_mma(
    const __nv_bfloat16* __restrict__ spl, float* __restrict__ out)
{
    extern __shared__ __align__(16) unsigned char dynraw[];
    __nv_bfloat16* sm = (__nv_bfloat16*)dynraw;   // 6 tiles of 64 x 136 (stride 272B)
    const int SB = 272;
    int tid = threadIdx.x;
    int bx = blockIdx.x, by = blockIdx.y, bz = blockIdx.z;
    size_t nb = (size_t)bz*NN;

    #pragma unroll
    for (int a2 = 0; a2 < 6; a2++) {
        size_t rowbase = nb + (size_t)((a2 < 4) ? by : bx)*64;
        const ull* src = (const ull*)(spl + (size_t)a2*NTOT*DD) + rowbase*32;
        ull* dst = (ull*)(sm + a2*64*136);
        #pragma unroll
        for (int it = 0; it < 8; it++) {
            int idx = tid + it*256;
            int r = idx >> 5, q = idx & 31;
            dst[r*34 + q] = src[r*32 + q];
        }
    }
    __syncthreads();

    int l = tid & 31, w = tid >> 5;
    int mg = w >> 1, nh = w & 1;
    int row0 = mg*16, n0 = nh*32;
    u32 base = smaddr(sm);
    u32 bVh = base, bVl = base + 17408, bWh = base + 2*17408,
        bWl = base + 3*17408, bUh = base + 4*17408, bUl = base + 5*17408;

    float cV[4][4] = {}, cW[4][4] = {};
    #pragma unroll
    for (int k0 = 0; k0 < 128; k0 += 16) {
        u32 vh[4], vl[4], wh[4], wl[4], uh[8], ul[8];
        ldsm4(vh[0],vh[1],vh[2],vh[3], a_addr(bVh, row0, k0, l, SB));
        ldsm4(vl[0],vl[1],vl[2],vl[3], a_addr(bVl, row0, k0, l, SB));
        ldsm4(wh[0],wh[1],wh[2],wh[3], a_addr(bWh, row0, k0, l, SB));
        ldsm4(wl[0],wl[1],wl[2],wl[3], a_addr(bWl, row0, k0, l, SB));
        ldsm4(uh[0],uh[1],uh[2],uh[3], b_addr(bUh, n0,    k0, l, SB));
        ldsm4(uh[4],uh[5],uh[6],uh[7], b_addr(bUh, n0+16, k0, l, SB));
        ldsm4(ul[0],ul[1],ul[2],ul[3], b_addr(bUl, n0,    k0, l, SB));
        ldsm4(ul[4],ul[5],ul[6],ul[7], b_addr(bUl, n0+16, k0, l, SB));
        #pragma unroll
        for (int c = 0; c < 4; c++) {
            mma_bf16(cV[c], vh, uh[2*c], uh[2*c+1]);
            mma_bf16(cV[c], vh, ul[2*c], ul[2*c+1]);
            mma_bf16(cV[c], vl, uh[2*c], uh[2*c+1]);
            mma_bf16(cW[c], wh, uh[2*c], uh[2*c+1]);
            mma_bf16(cW[c], wh, ul[2*c], ul[2*c+1]);
            mma_bf16(cW[c], wl, uh[2*c], uh[2*c+1]);
        }
    }

    size_t N2 = (size_t)NN*NN, S = (size_t)BB*N2;
    int r1 = by*64 + row0 + (l >> 2);
    int ccl = 2*(l & 3);
    #pragma unroll
    for (int c = 0; c < 4; c++) {
        int col = bx*64 + n0 + c*8 + ccl;
        #pragma unroll
        for (int hr = 0; hr < 2; hr++) {
            int row = r1 + hr*8;
            size_t o = (size_t)bz*N2 + (size_t)row*NN + col;
            float lg0 = cV[c][hr*2+0], lg1 = cV[c][hr*2+1];
            *(float2*)(out + o) = make_float2(lg0, lg1);
            float p0 = __fdividef(1.f, 1.f + __expf(-lg0));
            float p1 = __fdividef(1.f, 1.f + __expf(-lg1));
            *(float2*)(out + S + o) = make_float2(p0, p1);
            float w0 = cW[c][hr*2+0], w1 = cW[c][hr*2+1];
            float s0 = fmaxf(w0,0.f) + __logf(1.f + __expf(-fabsf(w0)));
            float s1 = fmaxf(w1,0.f) + __logf(1.f + __expf(-fabsf(w1)));
            *(float2*)(out + 2*S + o) = make_float2(s0, s1);
        }
    }
}

// ---------------- launch -----------------------------------------------------
extern "C" void kernel_launch(void* const* d_in, const int* in_sizes, int n_in,
                              void* d_out, int out_size)
{
    const float* spikes   = (const float*)d_in[0];
    const float* coords   = (const float*)d_in[1];
    const float* conv_w   = (const float*)d_in[2];
    const float* conv_b   = (const float*)d_in[3];
    const float* fc_w     = (const float*)d_in[4];
    const float* fc_b     = (const float*)d_in[5];
    const float* local_w  = (const float*)d_in[6];
    const float* local_b  = (const float*)d_in[7];
    const float* k1_w     = (const float*)d_in[8];
    const float* k1_b     = (const float*)d_in[9];
    const float* k2_w     = (const float*)d_in[10];
    const float* k2_b     = (const float*)d_in[11];
    const float* k3_w     = (const float*)d_in[12];
    const float* k3_b     = (const float*)d_in[13];
    const float* W_logits = (const float*)d_in[14];
    const float* W_weight = (const float*)d_in[15];
    float* out = (float*)d_out;

    float *u0, *u1, *pb, *pp, *pl; int* pix; ull* wpk;
    __nv_bfloat16 *spl, *k2th, *k2tl;
    cudaGetSymbolAddress((void**)&u0,   g_u);
    cudaGetSymbolAddress((void**)&u1,   g_u2);
    cudaGetSymbolAddress((void**)&pb,   g_base);
    cudaGetSymbolAddress((void**)&pp,   g_proj);
    cudaGetSymbolAddress((void**)&pl,   g_loc);
    cudaGetSymbolAddress((void**)&pix,  g_idx);
    cudaGetSymbolAddress((void**)&wpk,  g_wpack);
    cudaGetSymbolAddress((void**)&spl,  g_spl);
    cudaGetSymbolAddress((void**)&k2th, g_k2th);
    cudaGetSymbolAddress((void**)&k2tl, g_k2tl);

    static int attr_done = 0;
    if (!attr_done) {
        cudaFuncSetAttribute(k_edge_mma, cudaFuncAttributeMaxDynamicSharedMemorySize, 55296);
        cudaFuncSetAttribute(k_dec_mma,  cudaFuncAttributeMaxDynamicSharedMemorySize, 104448);
        attr_done = 1;
    }

    // packs
    WP wp;
    for (int lyr = 0; lyr < 3; lyr++) {
        wp.p[4*lyr+0] = k1_w + (size_t)lyr*258*DD + 2*DD;
        wp.p[4*lyr+1] = k1_w + (size_t)lyr*258*DD + 130*DD;
        wp.p[4*lyr+2] = local_w + (size_t)lyr*DD*DD;
        wp.p[4*lyr+3] = k2_w + (size_t)lyr*DD*DD;   // unused by mma path; harmless
    }
    wp.p[12] = W_logits;
    wp.p[13] = W_weight;
    wp.p[14] = fc_w;
    k_pack<<<dim3(32,15), 256>>>(wp, (float2*)wpk);
    k_packt<<<dim3(64,3), 256>>>(k2_w, k2th, k2tl);

    k_lift<<<NTOT, 128>>>(spikes, conv_w, conv_b, wpk + (size_t)14*8192, fc_b, u0);
    k_knn<<<dim3(NN/64, BB), 64>>>(coords, pix);

    float* ucur = u0;
    float* unext = u1;
    for (int lyr = 0; lyr < 3; lyr++) {
        const float* W1 = k1_w + (size_t)lyr*258*DD;
        k_node<3, true><<<NTOT/8, 256>>>(ucur,
            wpk + (size_t)(4*lyr+0)*8192, wpk + (size_t)(4*lyr+1)*8192,
            wpk + (size_t)(4*lyr+2)*8192,
            k1_b + lyr*DD, local_b + lyr*DD,
            W1, W1 + DD, coords,
            pb, pp, pl);
        k_edge_mma<<<NTOT/4, 256, 55296>>>(ucur, unext, pb, pp, pl, pix,
            k2th + (size_t)lyr*DD*DD, k2tl + (size_t)lyr*DD*DD,
            k2_b + lyr*DD, k3_w + (size_t)lyr*DD, k3_b + lyr);
        float* t = ucur; ucur = unext; unext = t;
    }

    // decoder stage 1: v = u@W_logits, w = u@W_weight (fp32)
    k_node<2, false><<<NTOT/8, 256>>>(ucur,
        wpk + (size_t)12*8192, wpk + (size_t)13*8192, wpk,
        nullptr, nullptr, nullptr, nullptr, nullptr,
        pb, pp, pb);
    // split v, w, u to bf16 hi/lo
    SP sp; sp.s[0] = pb; sp.s[1] = pp; sp.s[2] = ucur;
    k_split<<<dim3(NTOT*DD/1024, 3), 256>>>(sp, spl);
    // decoder stage 2 + epilogue (tensor)
    k_dec_mma<<<dim3(NN/64, NN/64, BB), 256, 104448>>>(spl, out);
}

// round 6
// speedup vs baseline: 2.6664x; 1.7204x over previous
#include <cuda_runtime.h>
#include <cuda_bf16.h>
#include <math.h>

#define BB 2
#define NN 2048
#define TT 256
#define DD 128
#define KK 16
#define NTOT (BB*NN)

typedef unsigned long long ull;
typedef unsigned int u32;

// ---------------- scalar f32x2 helpers ----------------
__device__ __forceinline__ ull ffma2(ull a, ull b, ull c){
    ull d; asm("fma.rn.f32x2 %0, %1, %2, %3;" : "=l"(d) : "l"(a), "l"(b), "l"(c));
    return d;
}
__device__ __forceinline__ float usum(ull v){
    float lo, hi; asm("mov.b64 {%0,%1}, %2;" : "=f"(lo), "=f"(hi) : "l"(v));
    return lo + hi;
}

// ---------------- mma helpers ----------------
__device__ __forceinline__ u32 smaddr(const void* p){
    return (u32)__cvta_generic_to_shared(p);
}
__device__ __forceinline__ void ldsm4(u32 &r0,u32 &r1,u32 &r2,u32 &r3, u32 a){
    asm volatile("ldmatrix.sync.aligned.m8n8.x4.shared.b16 {%0,%1,%2,%3}, [%4];"
                 : "=r"(r0),"=r"(r1),"=r"(r2),"=r"(r3) : "r"(a));
}
__device__ __forceinline__ void mma_bf16(float* c, const u32* a, u32 b0, u32 b1){
    asm volatile("mma.sync.aligned.m16n8k16.row.col.f32.bf16.bf16.f32 "
        "{%0,%1,%2,%3},{%4,%5,%6,%7},{%8,%9},{%0,%1,%2,%3};"
        : "+f"(c[0]),"+f"(c[1]),"+f"(c[2]),"+f"(c[3])
        : "r"(a[0]),"r"(a[1]),"r"(a[2]),"r"(a[3]),"r"(b0),"r"(b1));
}
__device__ __forceinline__ u32 a_addr(u32 base, int row0, int k0, int lane, int sB){
    int g = lane >> 3, r = lane & 7;
    return base + (u32)((row0 + r + (g & 1)*8)*sB + (k0 + (g >> 1)*8)*2);
}
__device__ __forceinline__ u32 b_addr(u32 base, int n0, int k0, int lane, int sB){
    int g = lane >> 3, r = lane & 7;
    return base + (u32)((n0 + r + (g >> 1)*8)*sB + (k0 + (g & 1)*8)*2);
}
__device__ __forceinline__ void split_bf(float x, __nv_bfloat16 &h, __nv_bfloat16 &l){
    h = __float2bfloat16(x);
    l = __float2bfloat16(x - __bfloat162float(h));
}

// ---------------- scratch ----------------
__device__ float g_u   [NTOT*DD];
__device__ float g_u2  [NTOT*DD];
__device__ float g_base[NTOT*DD];
__device__ float g_proj[NTOT*DD];
__device__ float g_loc [NTOT*DD];
__device__ int   g_idx [NTOT*KK];
__device__ __align__(16) ull g_wpack[15*64*128];             // node-gemm k-pair packs
__device__ __align__(16) __nv_bfloat16 g_spl[6*NTOT*DD];     // vh,vl,wh,wl,uh,ul
__device__ __align__(16) __nv_bfloat16 g_k2th[3*DD*DD];      // k2^T hi
__device__ __align__(16) __nv_bfloat16 g_k2tl[3*DD*DD];      // k2^T lo

// ---------------- Kernel 0a: scalar weight repack (node GEMMs) ----------------
struct WP { const float* p[15]; };
__global__ void __launch_bounds__(256) k_pack(WP wp, float2* __restrict__ dst){
    int m = blockIdx.y;
    const float* W = wp.p[m];
    int i = blockIdx.x*256 + threadIdx.x;     // 0..8191
    int kp = i >> 7, c = i & 127;
    dst[(size_t)m*8192 + i] = make_float2(W[(2*kp)*DD + c], W[(2*kp+1)*DD + c]);
}

// ---------------- Kernel 0b: k2 transposed + split to bf16 hi/lo --------------
__global__ void __launch_bounds__(256) k_packt(const float* __restrict__ k2w,
        __nv_bfloat16* __restrict__ th, __nv_bfloat16* __restrict__ tl){
    int lyr = blockIdx.y;
    int i = blockIdx.x*256 + threadIdx.x;     // 0..16383
    int c = i >> 7, k = i & 127;
    float v = k2w[(size_t)lyr*DD*DD + k*DD + c];
    __nv_bfloat16 h, l; split_bf(v, h, l);
    th[(size_t)lyr*DD*DD + c*DD + k] = h;
    tl[(size_t)lyr*DD*DD + c*DD + k] = l;
}

// ---------------- Kernel 0c: fp32 -> bf16 hi/lo split --------------------------
struct SP { const float* s[3]; };
__global__ void __launch_bounds__(256) k_split(SP sp, __nv_bfloat16* __restrict__ dst){
    int a = blockIdx.y;
    int i = (blockIdx.x*256 + threadIdx.x)*4;
    float4 v = *(const float4*)(sp.s[a] + i);
    __nv_bfloat16 h0,h1,h2,h3,l0,l1,l2,l3;
    split_bf(v.x,h0,l0); split_bf(v.y,h1,l1); split_bf(v.z,h2,l2); split_bf(v.w,h3,l3);
    __nv_bfloat162 hp0, hp1, lp0, lp1;
    hp0.x=h0; hp0.y=h1; hp1.x=h2; hp1.y=h3;
    lp0.x=l0; lp0.y=l1; lp1.x=l2; lp1.y=l3;
    __nv_bfloat162* H = (__nv_bfloat162*)(dst + (size_t)(2*a  )*NTOT*DD);
    __nv_bfloat162* L = (__nv_bfloat162*)(dst + (size_t)(2*a+1)*NTOT*DD);
    H[i/2] = hp0; H[i/2+1] = hp1;
    L[i/2] = lp0; L[i/2+1] = lp1;
}

// ---------------- Kernel 1: TemporalLift ----
__global__ void __launch_bounds__(128) k_lift(
    const float* __restrict__ spikes, const float* __restrict__ conv_w,
    const float* __restrict__ conv_b, const ull* __restrict__ fcp,
    const float* __restrict__ fc_b, float* __restrict__ u)
{
    __shared__ __align__(16) float sp[TT+8];
    __shared__ __align__(16) float xm[DD];
    int node = blockIdx.x;
    int h = threadIdx.x;
    const float* s = spikes + (size_t)node*TT;
    sp[2+h]      = s[h];
    sp[2+h+128]  = s[h+128];
    if (h < 2) sp[h] = 0.f;
    if (h < 6) sp[TT+2+h] = 0.f;
    __syncthreads();
    float w0 = conv_w[h*5+0], w1 = conv_w[h*5+1], w2 = conv_w[h*5+2],
          w3 = conv_w[h*5+3], w4 = conv_w[h*5+4];
    float bb = conv_b[h];
    float acc = 0.f;
    #pragma unroll 4
    for (int t = 0; t < TT; t += 4) {
        float4 a = *(const float4*)&sp[t];
        float4 b = *(const float4*)&sp[t+4];
        float o0 = fmaf(w4,b.x, fmaf(w3,a.w, fmaf(w2,a.z, fmaf(w1,a.y, fmaf(w0,a.x, bb)))));
        float o1 = fmaf(w4,b.y, fmaf(w3,b.x, fmaf(w2,a.w, fmaf(w1,a.z, fmaf(w0,a.y, bb)))));
        float o2 = fmaf(w4,b.z, fmaf(w3,b.y, fmaf(w2,b.x, fmaf(w1,a.w, fmaf(w0,a.z, bb)))));
        float o3 = fmaf(w4,b.w, fmaf(w3,b.z, fmaf(w2,b.y, fmaf(w1,b.x, fmaf(w0,a.w, bb)))));
        acc += fmaxf(o0,0.f) + fmaxf(o1,0.f) + fmaxf(o2,0.f) + fmaxf(o3,0.f);
    }
    xm[h] = acc * (1.f/(float)TT);
    __syncthreads();
    ull o2 = 0ull;
    #pragma unroll 8
    for (int kp = 0; kp < 64; kp++)
        o2 = ffma2(*(const ull*)&xm[2*kp], __ldg(&fcp[kp*DD + h]), o2);
    float o = usum(o2) + fc_b[h];
    u[(size_t)node*DD + h] = fmaxf(o, 0.f);
}

// ---------------- Kernel 2: kNN, warp-per-node --------------------------------
// Lane scans 64 candidates (stride-32, bank-conflict-free), keeps sorted top-16
// of packed keys (d2_bits<<32)|j. Then 16 rounds of warp u64-min extraction.
// Output order is irrelevant downstream (permutation-invariant aggregation).
__global__ void __launch_bounds__(256) k_knn(
    const float* __restrict__ coords, int* __restrict__ idx)
{
    __shared__ float c[NN];
    int b = blockIdx.y;
    const float* cb = coords + (size_t)b*NN;
    for (int j = threadIdx.x; j < NN; j += 256) c[j] = cb[j];
    __syncthreads();

    int w = threadIdx.x >> 5, l = threadIdx.x & 31;
    int i = blockIdx.x*8 + w;
    float ci = c[i];

    ull p[KK];
    #pragma unroll
    for (int t = 0; t < KK; t++) p[t] = ~0ull;

    #pragma unroll 4
    for (int t = 0; t < NN/32; t++) {
        int j = t*32 + l;
        float df = ci - c[j];
        float nd = df*df;
        ull q = ((ull)__float_as_uint(nd) << 32) | (u32)j;
        if (q < p[KK-1]) {
            p[KK-1] = q;
            #pragma unroll
            for (int s = KK-1; s > 0; --s) {
                if (p[s] < p[s-1]) { ull tmp = p[s]; p[s] = p[s-1]; p[s-1] = tmp; }
                else break;
            }
        }
    }

    int* o = idx + ((size_t)b*NN + i)*KK;
    #pragma unroll
    for (int r = 0; r < KK; r++) {
        ull m = p[0];
        #pragma unroll
        for (int s = 16; s > 0; s >>= 1) {
            ull other = __shfl_xor_sync(0xffffffffu, m, s);
            if (other < m) m = other;
        }
        if (p[0] == m) {   // unique winner (keys contain distinct j)
            #pragma unroll
            for (int s = 0; s < KK-1; s++) p[s] = p[s+1];
            p[KK-1] = ~0ull;
        }
        if (l == r) o[r] = (int)(m & 0xffffffffu);
    }
}

// ---------------- Kernel 3: fused node GEMM (scalar f32x2) -------------------
template<int NMAT, bool EX>
__global__ void __launch_bounds__(256, 4) k_node(
    const float* __restrict__ X,
    const ull* __restrict__ W0, const ull* __restrict__ W1, const ull* __restrict__ W2,
    const float* __restrict__ cb0, const float* __restrict__ cb2,
    const float* __restrict__ rv0, const float* __restrict__ rv1,
    const float* __restrict__ xs,
    float* __restrict__ Y0, float* __restrict__ Y1, float* __restrict__ Y2)
{
    __shared__ __align__(16) float Xs[8*DD];
    __shared__ float xc[8];
    int tid = threadIdx.x;
    int row0 = blockIdx.x*8;
    ((float4*)Xs)[tid] = ((const float4*)(X + (size_t)row0*DD))[tid];
    if (EX && tid < 8) xc[tid] = xs[row0 + tid];
    __syncthreads();

    int l = tid & 31, w = tid >> 5;
    int ch = w & 1, r0 = (w >> 1)*2;
    int coff = ch*64 + 2*l;
    const ull* Ws[3] = {W0, W1, (NMAT > 2) ? W2 : W0};
    ull acc[NMAT][2][2];
    #pragma unroll
    for (int m = 0; m < NMAT; m++)
        #pragma unroll
        for (int r = 0; r < 2; r++) { acc[m][r][0] = 0ull; acc[m][r][1] = 0ull; }

    #pragma unroll 2
    for (int kpp = 0; kpp < 32; kpp++) {
        ulonglong2 a0 = *(const ulonglong2*)&Xs[(r0  )*DD + 4*kpp];
        ulonglong2 a1 = *(const ulonglong2*)&Xs[(r0+1)*DD + 4*kpp];
        #pragma unroll
        for (int m = 0; m < NMAT; m++) {
            ulonglong2 b0 = *(const ulonglong2*)(Ws[m] + (size_t)(2*kpp)*DD + coff);
            ulonglong2 b1 = *(const ulonglong2*)(Ws[m] + (size_t)(2*kpp+1)*DD + coff);
            acc[m][0][0] = ffma2(a0.x, b0.x, acc[m][0][0]);
            acc[m][0][1] = ffma2(a0.x, b0.y, acc[m][0][1]);
            acc[m][0][0] = ffma2(a0.y, b1.x, acc[m][0][0]);
            acc[m][0][1] = ffma2(a0.y, b1.y, acc[m][0][1]);
            acc[m][1][0] = ffma2(a1.x, b0.x, acc[m][1][0]);
            acc[m][1][1] = ffma2(a1.x, b0.y, acc[m][1][1]);
            acc[m][1][0] = ffma2(a1.y, b1.x, acc[m][1][0]);
            acc[m][1][1] = ffma2(a1.y, b1.y, acc[m][1][1]);
        }
    }

    float2 cb0v = make_float2(0.f,0.f), cb2v = cb0v, r0v = cb0v, r1v = cb0v;
    if (EX) {
        cb0v = *(const float2*)(cb0 + coff);
        cb2v = *(const float2*)(cb2 + coff);
        r0v  = *(const float2*)(rv0 + coff);
        r1v  = *(const float2*)(rv1 + coff);
    }
    float* Ys[3] = {Y0, Y1, (NMAT > 2) ? Y2 : Y0};
    #pragma unroll
    for (int r = 0; r < 2; r++) {
        int n = row0 + r0 + r;
        float xv = EX ? xc[r0 + r] : 0.f;
        #pragma unroll
        for (int m = 0; m < NMAT; m++) {
            float s0 = usum(acc[m][r][0]);
            float s1 = usum(acc[m][r][1]);
            if (EX) {
                if (m == 0) { s0 += cb0v.x + xv*r0v.x; s1 += cb0v.y + xv*r0v.y; }
                if (m == 1) { s0 += xv*r1v.x;          s1 += xv*r1v.y; }
                if (m == 2) { s0 += cb2v.x;            s1 += cb2v.y; }
            }
            *(float2*)(Ys[m] + (size_t)n*DD + coff) = make_float2(s0, s1);
        }
    }
}

// ---------------- Kernel 4: edge MLP via tensor cores ------------------------
__global__ void __launch_bounds__(256) k_edge_mma(
    const float* __restrict__ u_in, float* __restrict__ u_out,
    const float* __restrict__ base_, const float* __restrict__ proj,
    const float* __restrict__ loc, const int* __restrict__ idx,
    const __nv_bfloat16* __restrict__ k2th, const __nv_bfloat16* __restrict__ k2tl,
    const float* __restrict__ k2b, const float* __restrict__ k3w,
    const float* __restrict__ k3b)
{
    extern __shared__ __align__(16) unsigned char dynraw[];
    __nv_bfloat16* sHh = (__nv_bfloat16*)dynraw;      // 64 x 72 (stride 144B)
    __nv_bfloat16* sHl = sHh + 64*72;
    __nv_bfloat16* sBh = sHl + 64*72;                 // 128 x 72
    __nv_bfloat16* sBl = sBh + 128*72;
    __shared__ __align__(16) float bss[4*DD];
    __shared__ int   js[64];
    __shared__ float kvp[64][2];
    __shared__ float kvv[64];

    int tid = threadIdx.x;
    int node0 = blockIdx.x*4;
    int bbase = node0 & ~(NN-1);
    if (tid < 128) ((float4*)bss)[tid] = ((const float4*)(base_ + (size_t)node0*DD))[tid];
    if (tid < 64) js[tid] = idx[node0*KK + tid];
    __syncthreads();

    int l = tid & 31, w = tid >> 5;
    int mg = w >> 1, nh = w & 1;
    int row0 = mg*16, n0 = nh*64;
    const int SBH = 144;
    u32 bH  = smaddr(sHh), bHl2 = smaddr(sHl);
    u32 bBh = smaddr(sBh), bBl  = smaddr(sBl);

    float C[8][4] = {};
    for (int kc = 0; kc < 128; kc += 64) {
        if (kc) __syncthreads();
        #pragma unroll
        for (int it = 0; it < 4; it++) {
            int id2 = tid + it*256;
            int e = id2 >> 4, q = id2 & 15;
            int j = js[e];
            float4 p = *(const float4*)(proj + (size_t)(bbase+j)*DD + kc + q*4);
            const float* bp = &bss[(e>>4)*DD + kc + q*4];
            float h0 = fmaxf(p.x + bp[0], 0.f);
            float h1 = fmaxf(p.y + bp[1], 0.f);
            float h2 = fmaxf(p.z + bp[2], 0.f);
            float h3 = fmaxf(p.w + bp[3], 0.f);
            __nv_bfloat16 a0,a1,a2,a3,c0,c1,c2,c3;
            split_bf(h0,a0,c0); split_bf(h1,a1,c1); split_bf(h2,a2,c2); split_bf(h3,a3,c3);
            __nv_bfloat162 hp0, hp1, lp0, lp1;
            hp0.x=a0; hp0.y=a1; hp1.x=a2; hp1.y=a3;
            lp0.x=c0; lp0.y=c1; lp1.x=c2; lp1.y=c3;
            __nv_bfloat162* dh = (__nv_bfloat162*)&sHh[e*72 + q*4];
            dh[0] = hp0; dh[1] = hp1;
            __nv_bfloat162* dl = (__nv_bfloat162*)&sHl[e*72 + q*4];
            dl[0] = lp0; dl[1] = lp1;
        }
        #pragma unroll
        for (int it = 0; it < 8; it++) {
            int id2 = tid + it*256;
            int c = id2 >> 4, q = id2 & 15;
            ((ull*)sBh)[c*18 + q] = *((const ull*)k2th + ((c*DD + kc) >> 2) + q);
            ((ull*)sBl)[c*18 + q] = *((const ull*)k2tl + ((c*DD + kc) >> 2) + q);
        }
        __syncthreads();
        #pragma unroll
        for (int k0 = 0; k0 < 64; k0 += 16) {
            u32 ah[4], al[4], bh[16], bl[16];
            ldsm4(ah[0],ah[1],ah[2],ah[3], a_addr(bH,   row0, k0, l, SBH));
            ldsm4(al[0],al[1],al[2],al[3], a_addr(bHl2, row0, k0, l, SBH));
            #pragma unroll
            for (int nc = 0; nc < 4; nc++) {
                ldsm4(bh[4*nc],bh[4*nc+1],bh[4*nc+2],bh[4*nc+3],
                      b_addr(bBh, n0 + nc*16, k0, l, SBH));
                ldsm4(bl[4*nc],bl[4*nc+1],bl[4*nc+2],bl[4*nc+3],
                      b_addr(bBl, n0 + nc*16, k0, l, SBH));
            }
            #pragma unroll
            for (int c = 0; c < 8; c++) {
                mma_bf16(C[c], ah, bh[2*c], bh[2*c+1]);
                mma_bf16(C[c], ah, bl[2*c], bl[2*c+1]);
                mma_bf16(C[c], al, bh[2*c], bh[2*c+1]);
            }
        }
    }

    float pr0 = 0.f, pr1 = 0.f;
    int ccl = 2*(l & 3);
    #pragma unroll
    for (int c = 0; c < 8; c++) {
        int col = n0 + c*8 + ccl;
        float b20 = __ldg(k2b+col), b21 = __ldg(k2b+col+1);
        float k30 = __ldg(k3w+col), k31 = __ldg(k3w+col+1);
        pr0 += fmaxf(C[c][0]+b20,0.f)*k30 + fmaxf(C[c][1]+b21,0.f)*k31;
        pr1 += fmaxf(C[c][2]+b20,0.f)*k30 + fmaxf(C[c][3]+b21,0.f)*k31;
    }
    pr0 += __shfl_xor_sync(0xffffffffu, pr0, 1);
    pr0 += __shfl_xor_sync(0xffffffffu, pr0, 2);
    pr1 += __shfl_xor_sync(0xffffffffu, pr1, 1);
    pr1 += __shfl_xor_sync(0xffffffffu, pr1, 2);
    if ((l & 3) == 0) {
        kvp[row0 + (l>>2)    ][nh] = pr0;
        kvp[row0 + (l>>2) + 8][nh] = pr1;
    }
    __syncthreads();
    if (tid < 64) kvv[tid] = (kvp[tid][0] + kvp[tid][1] + k3b[0])*0.25f;
    __syncthreads();

    int d = tid & 127;
    #pragma unroll
    for (int gg = 0; gg < 4; gg += 2) {
        int g = gg + (tid >> 7);
        int n = node0 + g;
        float a = 0.f;
        #pragma unroll
        for (int kk = 0; kk < KK; kk++)
            a = fmaf(kvv[g*KK+kk], u_in[(size_t)(bbase+js[g*KK+kk])*DD + d], a);
        float o = loc[(size_t)n*DD + d] + a + u_in[(size_t)n*DD + d];
        u_out[(size_t)n*DD + d] = fmaxf(o, 0.f);
    }
}

// ---------------- Kernel 5: decoder 64x64 tile via tensor cores --------------
__global__ void __launch_bounds__(256) k_dec_mma(
    const __nv_bfloat16* __restrict__ spl, float* __restrict__ out)
{
    extern __shared__ __align__(16) unsigned char dynraw[];
    __nv_bfloat16* sm = (__nv_bfloat16*)dynraw;   // 6 tiles of 64 x 136 (stride 272B)
    const int SB = 272;
    int tid = threadIdx.x;
    int bx = blockIdx.x, by = blockIdx.y, bz = blockIdx.z;
    size_t nb = (size_t)bz*NN;

    #pragma unroll
    for (int a2 = 0; a2 < 6; a2++) {
        size_t rowbase = nb + (size_t)((a2 < 4) ? by : bx)*64;
        const ull* src = (const ull*)(spl + (size_t)a2*NTOT*DD) + rowbase*32;
        ull* dst = (ull*)(sm + a2*64*136);
        #pragma unroll
        for (int it = 0; it < 8; it++) {
            int idx = tid + it*256;
            int r = idx >> 5, q = idx & 31;
            dst[r*34 + q] = src[r*32 + q];
        }
    }
    __syncthreads();

    int l = tid & 31, w = tid >> 5;
    int mg = w >> 1, nh = w & 1;
    int row0 = mg*16, n0 = nh*32;
    u32 base = smaddr(sm);
    u32 bVh = base, bVl = base + 17408, bWh = base + 2*17408,
        bWl = base + 3*17408, bUh = base + 4*17408, bUl = base + 5*17408;

    float cV[4][4] = {}, cW[4][4] = {};
    #pragma unroll
    for (int k0 = 0; k0 < 128; k0 += 16) {
        u32 vh[4], vl[4], wh[4], wl[4], uh[8], ul[8];
        ldsm4(vh[0],vh[1],vh[2],vh[3], a_addr(bVh, row0, k0, l, SB));
        ldsm4(vl[0],vl[1],vl[2],vl[3], a_addr(bVl, row0, k0, l, SB));
        ldsm4(wh[0],wh[1],wh[2],wh[3], a_addr(bWh, row0, k0, l, SB));
        ldsm4(wl[0],wl[1],wl[2],wl[3], a_addr(bWl, row0, k0, l, SB));
        ldsm4(uh[0],uh[1],uh[2],uh[3], b_addr(bUh, n0,    k0, l, SB));
        ldsm4(uh[4],uh[5],uh[6],uh[7], b_addr(bUh, n0+16, k0, l, SB));
        ldsm4(ul[0],ul[1],ul[2],ul[3], b_addr(bUl, n0,    k0, l, SB));
        ldsm4(ul[4],ul[5],ul[6],ul[7], b_addr(bUl, n0+16, k0, l, SB));
        #pragma unroll
        for (int c = 0; c < 4; c++) {
            mma_bf16(cV[c], vh, uh[2*c], uh[2*c+1]);
            mma_bf16(cV[c], vh, ul[2*c], ul[2*c+1]);
            mma_bf16(cV[c], vl, uh[2*c], uh[2*c+1]);
            mma_bf16(cW[c], wh, uh[2*c], uh[2*c+1]);
            mma_bf16(cW[c], wh, ul[2*c], ul[2*c+1]);
            mma_bf16(cW[c], wl, uh[2*c], uh[2*c+1]);
        }
    }

    size_t N2 = (size_t)NN*NN, S = (size_t)BB*N2;
    int r1 = by*64 + row0 + (l >> 2);
    int ccl = 2*(l & 3);
    #pragma unroll
    for (int c = 0; c < 4; c++) {
        int col = bx*64 + n0 + c*8 + ccl;
        #pragma unroll
        for (int hr = 0; hr < 2; hr++) {
            int row = r1 + hr*8;
            size_t o = (size_t)bz*N2 + (size_t)row*NN + col;
            float lg0 = cV[c][hr*2+0], lg1 = cV[c][hr*2+1];
            *(float2*)(out + o) = make_float2(lg0, lg1);
            float p0 = __fdividef(1.f, 1.f + __expf(-lg0));
            float p1 = __fdividef(1.f, 1.f + __expf(-lg1));
            *(float2*)(out + S + o) = make_float2(p0, p1);
            float w0 = cW[c][hr*2+0], w1 = cW[c][hr*2+1];
            float s0 = fmaxf(w0,0.f) + __logf(1.f + __expf(-fabsf(w0)));
            float s1 = fmaxf(w1,0.f) + __logf(1.f + __expf(-fabsf(w1)));
            *(float2*)(out + 2*S + o) = make_float2(s0, s1);
        }
    }
}

// ---------------- launch -----------------------------------------------------
extern "C" void kernel_launch(void* const* d_in, const int* in_sizes, int n_in,
                              void* d_out, int out_size)
{
    const float* spikes   = (const float*)d_in[0];
    const float* coords   = (const float*)d_in[1];
    const float* conv_w   = (const float*)d_in[2];
    const float* conv_b   = (const float*)d_in[3];
    const float* fc_w     = (const float*)d_in[4];
    const float* fc_b     = (const float*)d_in[5];
    const float* local_w  = (const float*)d_in[6];
    const float* local_b  = (const float*)d_in[7];
    const float* k1_w     = (const float*)d_in[8];
    const float* k1_b     = (const float*)d_in[9];
    const float* k2_w     = (const float*)d_in[10];
    const float* k2_b     = (const float*)d_in[11];
    const float* k3_w     = (const float*)d_in[12];
    const float* k3_b     = (const float*)d_in[13];
    const float* W_logits = (const float*)d_in[14];
    const float* W_weight = (const float*)d_in[15];
    float* out = (float*)d_out;

    float *u0, *u1, *pb, *pp, *pl; int* pix; ull* wpk;
    __nv_bfloat16 *spl, *k2th, *k2tl;
    cudaGetSymbolAddress((void**)&u0,   g_u);
    cudaGetSymbolAddress((void**)&u1,   g_u2);
    cudaGetSymbolAddress((void**)&pb,   g_base);
    cudaGetSymbolAddress((void**)&pp,   g_proj);
    cudaGetSymbolAddress((void**)&pl,   g_loc);
    cudaGetSymbolAddress((void**)&pix,  g_idx);
    cudaGetSymbolAddress((void**)&wpk,  g_wpack);
    cudaGetSymbolAddress((void**)&spl,  g_spl);
    cudaGetSymbolAddress((void**)&k2th, g_k2th);
    cudaGetSymbolAddress((void**)&k2tl, g_k2tl);

    cudaFuncSetAttribute(k_edge_mma, cudaFuncAttributeMaxDynamicSharedMemorySize, 55296);
    cudaFuncSetAttribute(k_dec_mma,  cudaFuncAttributeMaxDynamicSharedMemorySize, 104448);

    // packs
    WP wp;
    for (int lyr = 0; lyr < 3; lyr++) {
        wp.p[4*lyr+0] = k1_w + (size_t)lyr*258*DD + 2*DD;
        wp.p[4*lyr+1] = k1_w + (size_t)lyr*258*DD + 130*DD;
        wp.p[4*lyr+2] = local_w + (size_t)lyr*DD*DD;
        wp.p[4*lyr+3] = k2_w + (size_t)lyr*DD*DD;
    }
    wp.p[12] = W_logits;
    wp.p[13] = W_weight;
    wp.p[14] = fc_w;
    k_pack<<<dim3(32,15), 256>>>(wp, (float2*)wpk);
    k_packt<<<dim3(64,3), 256>>>(k2_w, k2th, k2tl);

    k_lift<<<NTOT, 128>>>(spikes, conv_w, conv_b, wpk + (size_t)14*8192, fc_b, u0);
    k_knn<<<dim3(NN/8, BB), 256>>>(coords, pix);

    float* ucur = u0;
    float* unext = u1;
    for (int lyr = 0; lyr < 3; lyr++) {
        const float* W1 = k1_w + (size_t)lyr*258*DD;
        k_node<3, true><<<NTOT/8, 256>>>(ucur,
            wpk + (size_t)(4*lyr+0)*8192, wpk + (size_t)(4*lyr+1)*8192,
            wpk + (size_t)(4*lyr+2)*8192,
            k1_b + lyr*DD, local_b + lyr*DD,
            W1, W1 + DD, coords,
            pb, pp, pl);
        k_edge_mma<<<NTOT/4, 256, 55296>>>(ucur, unext, pb, pp, pl, pix,
            k2th + (size_t)lyr*DD*DD, k2tl + (size_t)lyr*DD*DD,
            k2_b + lyr*DD, k3_w + (size_t)lyr*DD, k3_b + lyr);
        float* t = ucur; ucur = unext; unext = t;
    }

    k_node<2, false><<<NTOT/8, 256>>>(ucur,
        wpk + (size_t)12*8192, wpk + (size_t)13*8192, wpk,
        nullptr, nullptr, nullptr, nullptr, nullptr,
        pb, pp, pb);
    SP sp; sp.s[0] = pb; sp.s[1] = pp; sp.s[2] = ucur;
    k_split<<<dim3(NTOT*DD/1024, 3), 256>>>(sp, spl);
    k_dec_mma<<<dim3(NN/64, NN/64, BB), 256, 104448>>>(spl, out);
}

// round 7
// speedup vs baseline: 3.9821x; 1.4934x over previous
#include <cuda_runtime.h>
#include <cuda_bf16.h>
#include <math.h>

#define BB 2
#define NN 2048
#define TT 256
#define DD 128
#define KK 16
#define NTOT (BB*NN)

typedef unsigned long long ull;
typedef unsigned int u32;

// ---------------- scalar f32x2 helpers ----------------
__device__ __forceinline__ ull ffma2(ull a, ull b, ull c){
    ull d; asm("fma.rn.f32x2 %0, %1, %2, %3;" : "=l"(d) : "l"(a), "l"(b), "l"(c));
    return d;
}
__device__ __forceinline__ float usum(ull v){
    float lo, hi; asm("mov.b64 {%0,%1}, %2;" : "=f"(lo), "=f"(hi) : "l"(v));
    return lo + hi;
}

// ---------------- mma helpers ----------------
__device__ __forceinline__ u32 smaddr(const void* p){
    return (u32)__cvta_generic_to_shared(p);
}
__device__ __forceinline__ void ldsm4(u32 &r0,u32 &r1,u32 &r2,u32 &r3, u32 a){
    asm volatile("ldmatrix.sync.aligned.m8n8.x4.shared.b16 {%0,%1,%2,%3}, [%4];"
                 : "=r"(r0),"=r"(r1),"=r"(r2),"=r"(r3) : "r"(a));
}
__device__ __forceinline__ void mma_bf16(float* c, const u32* a, u32 b0, u32 b1){
    asm volatile("mma.sync.aligned.m16n8k16.row.col.f32.bf16.bf16.f32 "
        "{%0,%1,%2,%3},{%4,%5,%6,%7},{%8,%9},{%0,%1,%2,%3};"
        : "+f"(c[0]),"+f"(c[1]),"+f"(c[2]),"+f"(c[3])
        : "r"(a[0]),"r"(a[1]),"r"(a[2]),"r"(a[3]),"r"(b0),"r"(b1));
}
__device__ __forceinline__ u32 a_addr(u32 base, int row0, int k0, int lane, int sB){
    int g = lane >> 3, r = lane & 7;
    return base + (u32)((row0 + r + (g & 1)*8)*sB + (k0 + (g >> 1)*8)*2);
}
__device__ __forceinline__ u32 b_addr(u32 base, int n0, int k0, int lane, int sB){
    int g = lane >> 3, r = lane & 7;
    return base + (u32)((n0 + r + (g >> 1)*8)*sB + (k0 + (g & 1)*8)*2);
}
__device__ __forceinline__ void split_bf(float x, __nv_bfloat16 &h, __nv_bfloat16 &l){
    h = __float2bfloat16(x);
    l = __float2bfloat16(x - __bfloat162float(h));
}

// ---------------- scratch ----------------
__device__ float g_u   [NTOT*DD];
__device__ float g_u2  [NTOT*DD];
__device__ float g_base[NTOT*DD];
__device__ float g_proj[NTOT*DD];
__device__ float g_loc [NTOT*DD];
__device__ int   g_idx [NTOT*KK];
__device__ ull   g_skey[NTOT];     // sorted (coord_bits<<32|idx) per batch
__device__ int   g_pos [NTOT];     // original idx -> sorted position
__device__ __align__(16) ull g_wpack[15*64*128];             // node-gemm k-pair packs
__device__ __align__(16) __nv_bfloat16 g_spl[6*NTOT*DD];     // vh,vl,wh,wl,uh,ul
__device__ __align__(16) __nv_bfloat16 g_k2th[3*DD*DD];      // k2^T hi
__device__ __align__(16) __nv_bfloat16 g_k2tl[3*DD*DD];      // k2^T lo

// ---------------- Kernel 0a: scalar weight repack (node GEMMs) ----------------
struct WP { const float* p[15]; };
__global__ void __launch_bounds__(256) k_pack(WP wp, float2* __restrict__ dst){
    int m = blockIdx.y;
    const float* W = wp.p[m];
    int i = blockIdx.x*256 + threadIdx.x;     // 0..8191
    int kp = i >> 7, c = i & 127;
    dst[(size_t)m*8192 + i] = make_float2(W[(2*kp)*DD + c], W[(2*kp+1)*DD + c]);
}

// ---------------- Kernel 0b: k2 transposed + split to bf16 hi/lo --------------
__global__ void __launch_bounds__(256) k_packt(const float* __restrict__ k2w,
        __nv_bfloat16* __restrict__ th, __nv_bfloat16* __restrict__ tl){
    int lyr = blockIdx.y;
    int i = blockIdx.x*256 + threadIdx.x;     // 0..16383
    int c = i >> 7, k = i & 127;
    float v = k2w[(size_t)lyr*DD*DD + k*DD + c];
    __nv_bfloat16 h, l; split_bf(v, h, l);
    th[(size_t)lyr*DD*DD + c*DD + k] = h;
    tl[(size_t)lyr*DD*DD + c*DD + k] = l;
}

// ---------------- Kernel 0c: fp32 -> bf16 hi/lo split --------------------------
struct SP { const float* s[3]; };
__global__ void __launch_bounds__(256) k_split(SP sp, __nv_bfloat16* __restrict__ dst){
    int a = blockIdx.y;
    int i = (blockIdx.x*256 + threadIdx.x)*4;
    float4 v = *(const float4*)(sp.s[a] + i);
    __nv_bfloat16 h0,h1,h2,h3,l0,l1,l2,l3;
    split_bf(v.x,h0,l0); split_bf(v.y,h1,l1); split_bf(v.z,h2,l2); split_bf(v.w,h3,l3);
    __nv_bfloat162 hp0, hp1, lp0, lp1;
    hp0.x=h0; hp0.y=h1; hp1.x=h2; hp1.y=h3;
    lp0.x=l0; lp0.y=l1; lp1.x=l2; lp1.y=l3;
    __nv_bfloat162* H = (__nv_bfloat162*)(dst + (size_t)(2*a  )*NTOT*DD);
    __nv_bfloat162* L = (__nv_bfloat162*)(dst + (size_t)(2*a+1)*NTOT*DD);
    H[i/2] = hp0; H[i/2+1] = hp1;
    L[i/2] = lp0; L[i/2+1] = lp1;
}

// ---------------- Kernel 1: TemporalLift ----
__global__ void __launch_bounds__(128) k_lift(
    const float* __restrict__ spikes, const float* __restrict__ conv_w,
    const float* __restrict__ conv_b, const ull* __restrict__ fcp,
    const float* __restrict__ fc_b, float* __restrict__ u)
{
    __shared__ __align__(16) float sp[TT+8];
    __shared__ __align__(16) float xm[DD];
    int node = blockIdx.x;
    int h = threadIdx.x;
    const float* s = spikes + (size_t)node*TT;
    sp[2+h]      = s[h];
    sp[2+h+128]  = s[h+128];
    if (h < 2) sp[h] = 0.f;
    if (h < 6) sp[TT+2+h] = 0.f;
    __syncthreads();
    float w0 = conv_w[h*5+0], w1 = conv_w[h*5+1], w2 = conv_w[h*5+2],
          w3 = conv_w[h*5+3], w4 = conv_w[h*5+4];
    float bb = conv_b[h];
    float acc = 0.f;
    #pragma unroll 4
    for (int t = 0; t < TT; t += 4) {
        float4 a = *(const float4*)&sp[t];
        float4 b = *(const float4*)&sp[t+4];
        float o0 = fmaf(w4,b.x, fmaf(w3,a.w, fmaf(w2,a.z, fmaf(w1,a.y, fmaf(w0,a.x, bb)))));
        float o1 = fmaf(w4,b.y, fmaf(w3,b.x, fmaf(w2,a.w, fmaf(w1,a.z, fmaf(w0,a.y, bb)))));
        float o2 = fmaf(w4,b.z, fmaf(w3,b.y, fmaf(w2,b.x, fmaf(w1,a.w, fmaf(w0,a.z, bb)))));
        float o3 = fmaf(w4,b.w, fmaf(w3,b.z, fmaf(w2,b.y, fmaf(w1,b.x, fmaf(w0,a.w, bb)))));
        acc += fmaxf(o0,0.f) + fmaxf(o1,0.f) + fmaxf(o2,0.f) + fmaxf(o3,0.f);
    }
    xm[h] = acc * (1.f/(float)TT);
    __syncthreads();
    ull o2 = 0ull;
    #pragma unroll 8
    for (int kp = 0; kp < 64; kp++)
        o2 = ffma2(*(const ull*)&xm[2*kp], __ldg(&fcp[kp*DD + h]), o2);
    float o = usum(o2) + fc_b[h];
    u[(size_t)node*DD + h] = fmaxf(o, 0.f);
}

// ---------------- Kernel 2a: bitonic sort of (coord_bits<<32|idx) per batch ---
__global__ void __launch_bounds__(1024) k_sort(
    const float* __restrict__ coords, ull* __restrict__ skey, int* __restrict__ pos)
{
    __shared__ ull s[NN];
    int b = blockIdx.x;
    int t = threadIdx.x;
    const float* cb = coords + (size_t)b*NN;
    s[t]        = ((ull)__float_as_uint(cb[t])      << 32) | (u32)t;
    s[t + 1024] = ((ull)__float_as_uint(cb[t+1024]) << 32) | (u32)(t + 1024);
    __syncthreads();
    for (int k = 2; k <= NN; k <<= 1) {
        for (int j = k >> 1; j > 0; j >>= 1) {
            int i  = ((t & ~(j-1)) << 1) | (t & (j-1));
            int p2 = i | j;
            bool asc = ((i & k) == 0);
            ull a = s[i], c = s[p2];
            if ((a > c) == asc) { s[i] = c; s[p2] = a; }
            __syncthreads();
        }
    }
    #pragma unroll
    for (int q = 0; q < 2; q++) {
        int p = t + q*1024;
        ull v = s[p];
        skey[(size_t)b*NN + p] = v;
        pos[(size_t)b*NN + (int)(v & 0xffffffffull)] = p;
    }
}

// ---------------- Kernel 2b: kNN via two-pointer window in sorted order -------
// 1-D coords: k nearest = contiguous window. Frontier compare of packed
// (d2_bits<<32|j) keys reproduces top_k's (dist, index) tie-break.
__global__ void __launch_bounds__(256) k_knn2(
    const ull* __restrict__ skey, const int* __restrict__ pos, int* __restrict__ idx)
{
    __shared__ ull sk[NN];
    int b = blockIdx.y;
    for (int i = threadIdx.x; i < NN; i += 256) sk[i] = skey[(size_t)b*NN + i];
    __syncthreads();
    int i = blockIdx.x*256 + threadIdx.x;
    int p = pos[(size_t)b*NN + i];
    float ci = __uint_as_float((u32)(sk[p] >> 32));
    int lo = p, hi = p + 1;
    int* o = idx + ((size_t)b*NN + i)*KK;
    #pragma unroll
    for (int r = 0; r < KK; r++) {
        ull cl = ~0ull, ch = ~0ull;
        if (lo >= 0) {
            ull v = sk[lo];
            float d = __uint_as_float((u32)(v >> 32)) - ci;
            cl = ((ull)__float_as_uint(d*d) << 32) | (v & 0xffffffffull);
        }
        if (hi < NN) {
            ull v = sk[hi];
            float d = __uint_as_float((u32)(v >> 32)) - ci;
            ch = ((ull)__float_as_uint(d*d) << 32) | (v & 0xffffffffull);
        }
        if (cl <= ch) { o[r] = (int)(cl & 0xffffffffull); lo--; }
        else          { o[r] = (int)(ch & 0xffffffffull); hi++; }
    }
}

// ---------------- Kernel 3: fused node GEMM (scalar f32x2) -------------------
template<int NMAT, bool EX>
__global__ void __launch_bounds__(256, 4) k_node(
    const float* __restrict__ X,
    const ull* __restrict__ W0, const ull* __restrict__ W1, const ull* __restrict__ W2,
    const float* __restrict__ cb0, const float* __restrict__ cb2,
    const float* __restrict__ rv0, const float* __restrict__ rv1,
    const float* __restrict__ xs,
    float* __restrict__ Y0, float* __restrict__ Y1, float* __restrict__ Y2)
{
    __shared__ __align__(16) float Xs[8*DD];
    __shared__ float xc[8];
    int tid = threadIdx.x;
    int row0 = blockIdx.x*8;
    ((float4*)Xs)[tid] = ((const float4*)(X + (size_t)row0*DD))[tid];
    if (EX && tid < 8) xc[tid] = xs[row0 + tid];
    __syncthreads();

    int l = tid & 31, w = tid >> 5;
    int ch = w & 1, r0 = (w >> 1)*2;
    int coff = ch*64 + 2*l;
    const ull* Ws[3] = {W0, W1, (NMAT > 2) ? W2 : W0};
    ull acc[NMAT][2][2];
    #pragma unroll
    for (int m = 0; m < NMAT; m++)
        #pragma unroll
        for (int r = 0; r < 2; r++) { acc[m][r][0] = 0ull; acc[m][r][1] = 0ull; }

    #pragma unroll 2
    for (int kpp = 0; kpp < 32; kpp++) {
        ulonglong2 a0 = *(const ulonglong2*)&Xs[(r0  )*DD + 4*kpp];
        ulonglong2 a1 = *(const ulonglong2*)&Xs[(r0+1)*DD + 4*kpp];
        #pragma unroll
        for (int m = 0; m < NMAT; m++) {
            ulonglong2 b0 = *(const ulonglong2*)(Ws[m] + (size_t)(2*kpp)*DD + coff);
            ulonglong2 b1 = *(const ulonglong2*)(Ws[m] + (size_t)(2*kpp+1)*DD + coff);
            acc[m][0][0] = ffma2(a0.x, b0.x, acc[m][0][0]);
            acc[m][0][1] = ffma2(a0.x, b0.y, acc[m][0][1]);
            acc[m][0][0] = ffma2(a0.y, b1.x, acc[m][0][0]);
            acc[m][0][1] = ffma2(a0.y, b1.y, acc[m][0][1]);
            acc[m][1][0] = ffma2(a1.x, b0.x, acc[m][1][0]);
            acc[m][1][1] = ffma2(a1.x, b0.y, acc[m][1][1]);
            acc[m][1][0] = ffma2(a1.y, b1.x, acc[m][1][0]);
            acc[m][1][1] = ffma2(a1.y, b1.y, acc[m][1][1]);
        }
    }

    float2 cb0v = make_float2(0.f,0.f), cb2v = cb0v, r0v = cb0v, r1v = cb0v;
    if (EX) {
        cb0v = *(const float2*)(cb0 + coff);
        cb2v = *(const float2*)(cb2 + coff);
        r0v  = *(const float2*)(rv0 + coff);
        r1v  = *(const float2*)(rv1 + coff);
    }
    float* Ys[3] = {Y0, Y1, (NMAT > 2) ? Y2 : Y0};
    #pragma unroll
    for (int r = 0; r < 2; r++) {
        int n = row0 + r0 + r;
        float xv = EX ? xc[r0 + r] : 0.f;
        #pragma unroll
        for (int m = 0; m < NMAT; m++) {
            float s0 = usum(acc[m][r][0]);
            float s1 = usum(acc[m][r][1]);
            if (EX) {
                if (m == 0) { s0 += cb0v.x + xv*r0v.x; s1 += cb0v.y + xv*r0v.y; }
                if (m == 1) { s0 += xv*r1v.x;          s1 += xv*r1v.y; }
                if (m == 2) { s0 += cb2v.x;            s1 += cb2v.y; }
            }
            *(float2*)(Ys[m] + (size_t)n*DD + coff) = make_float2(s0, s1);
        }
    }
}

// ---------------- Kernel 4: edge MLP via tensor cores ------------------------
__global__ void __launch_bounds__(256) k_edge_mma(
    const float* __restrict__ u_in, float* __restrict__ u_out,
    const float* __restrict__ base_, const float* __restrict__ proj,
    const float* __restrict__ loc, const int* __restrict__ idx,
    const __nv_bfloat16* __restrict__ k2th, const __nv_bfloat16* __restrict__ k2tl,
    const float* __restrict__ k2b, const float* __restrict__ k3w,
    const float* __restrict__ k3b)
{
    extern __shared__ __align__(16) unsigned char dynraw[];
    __nv_bfloat16* sHh = (__nv_bfloat16*)dynraw;      // 64 x 72 (stride 144B)
    __nv_bfloat16* sHl = sHh + 64*72;
    __nv_bfloat16* sBh = sHl + 64*72;                 // 128 x 72
    __nv_bfloat16* sBl = sBh + 128*72;
    __shared__ __align__(16) float bss[4*DD];
    __shared__ int   js[64];
    __shared__ float kvp[64][2];
    __shared__ float kvv[64];

    int tid = threadIdx.x;
    int node0 = blockIdx.x*4;
    int bbase = node0 & ~(NN-1);
    if (tid < 128) ((float4*)bss)[tid] = ((const float4*)(base_ + (size_t)node0*DD))[tid];
    if (tid < 64) js[tid] = idx[node0*KK + tid];
    __syncthreads();

    int l = tid & 31, w = tid >> 5;
    int mg = w >> 1, nh = w & 1;
    int row0 = mg*16, n0 = nh*64;
    const int SBH = 144;
    u32 bH  = smaddr(sHh), bHl2 = smaddr(sHl);
    u32 bBh = smaddr(sBh), bBl  = smaddr(sBl);

    float C[8][4] = {};
    for (int kc = 0; kc < 128; kc += 64) {
        if (kc) __syncthreads();
        #pragma unroll
        for (int it = 0; it < 4; it++) {
            int id2 = tid + it*256;
            int e = id2 >> 4, q = id2 & 15;
            int j = js[e];
            float4 p = *(const float4*)(proj + (size_t)(bbase+j)*DD + kc + q*4);
            const float* bp = &bss[(e>>4)*DD + kc + q*4];
            float h0 = fmaxf(p.x + bp[0], 0.f);
            float h1 = fmaxf(p.y + bp[1], 0.f);
            float h2 = fmaxf(p.z + bp[2], 0.f);
            float h3 = fmaxf(p.w + bp[3], 0.f);
            __nv_bfloat16 a0,a1,a2,a3,c0,c1,c2,c3;
            split_bf(h0,a0,c0); split_bf(h1,a1,c1); split_bf(h2,a2,c2); split_bf(h3,a3,c3);
            __nv_bfloat162 hp0, hp1, lp0, lp1;
            hp0.x=a0; hp0.y=a1; hp1.x=a2; hp1.y=a3;
            lp0.x=c0; lp0.y=c1; lp1.x=c2; lp1.y=c3;
            __nv_bfloat162* dh = (__nv_bfloat162*)&sHh[e*72 + q*4];
            dh[0] = hp0; dh[1] = hp1;
            __nv_bfloat162* dl = (__nv_bfloat162*)&sHl[e*72 + q*4];
            dl[0] = lp0; dl[1] = lp1;
        }
        #pragma unroll
        for (int it = 0; it < 8; it++) {
            int id2 = tid + it*256;
            int c = id2 >> 4, q = id2 & 15;
            ((ull*)sBh)[c*18 + q] = *((const ull*)k2th + ((c*DD + kc) >> 2) + q);
            ((ull*)sBl)[c*18 + q] = *((const ull*)k2tl + ((c*DD + kc) >> 2) + q);
        }
        __syncthreads();
        #pragma unroll
        for (int k0 = 0; k0 < 64; k0 += 16) {
            u32 ah[4], al[4], bh[16], bl[16];
            ldsm4(ah[0],ah[1],ah[2],ah[3], a_addr(bH,   row0, k0, l, SBH));
            ldsm4(al[0],al[1],al[2],al[3], a_addr(bHl2, row0, k0, l, SBH));
            #pragma unroll
            for (int nc = 0; nc < 4; nc++) {
                ldsm4(bh[4*nc],bh[4*nc+1],bh[4*nc+2],bh[4*nc+3],
                      b_addr(bBh, n0 + nc*16, k0, l, SBH));
                ldsm4(bl[4*nc],bl[4*nc+1],bl[4*nc+2],bl[4*nc+3],
                      b_addr(bBl, n0 + nc*16, k0, l, SBH));
            }
            #pragma unroll
            for (int c = 0; c < 8; c++) {
                mma_bf16(C[c], ah, bh[2*c], bh[2*c+1]);
                mma_bf16(C[c], ah, bl[2*c], bl[2*c+1]);
                mma_bf16(C[c], al, bh[2*c], bh[2*c+1]);
            }
        }
    }

    float pr0 = 0.f, pr1 = 0.f;
    int ccl = 2*(l & 3);
    #pragma unroll
    for (int c = 0; c < 8; c++) {
        int col = n0 + c*8 + ccl;
        float b20 = __ldg(k2b+col), b21 = __ldg(k2b+col+1);
        float k30 = __ldg(k3w+col), k31 = __ldg(k3w+col+1);
        pr0 += fmaxf(C[c][0]+b20,0.f)*k30 + fmaxf(C[c][1]+b21,0.f)*k31;
        pr1 += fmaxf(C[c][2]+b20,0.f)*k30 + fmaxf(C[c][3]+b21,0.f)*k31;
    }
    pr0 += __shfl_xor_sync(0xffffffffu, pr0, 1);
    pr0 += __shfl_xor_sync(0xffffffffu, pr0, 2);
    pr1 += __shfl_xor_sync(0xffffffffu, pr1, 1);
    pr1 += __shfl_xor_sync(0xffffffffu, pr1, 2);
    if ((l & 3) == 0) {
        kvp[row0 + (l>>2)    ][nh] = pr0;
        kvp[row0 + (l>>2) + 8][nh] = pr1;
    }
    __syncthreads();
    if (tid < 64) kvv[tid] = (kvp[tid][0] + kvp[tid][1] + k3b[0])*0.25f;
    __syncthreads();

    int d = tid & 127;
    #pragma unroll
    for (int gg = 0; gg < 4; gg += 2) {
        int g = gg + (tid >> 7);
        int n = node0 + g;
        float a = 0.f;
        #pragma unroll
        for (int kk = 0; kk < KK; kk++)
            a = fmaf(kvv[g*KK+kk], u_in[(size_t)(bbase+js[g*KK+kk])*DD + d], a);
        float o = loc[(size_t)n*DD + d] + a + u_in[(size_t)n*DD + d];
        u_out[(size_t)n*DD + d] = fmaxf(o, 0.f);
    }
}

// ---------------- Kernel 5: decoder 64x64 tile via tensor cores --------------
__global__ void __launch_bounds__(256) k_dec_mma(
    const __nv_bfloat16* __restrict__ spl, float* __restrict__ out)
{
    extern __shared__ __align__(16) unsigned char dynraw[];
    __nv_bfloat16* sm = (__nv_bfloat16*)dynraw;   // 6 tiles of 64 x 136 (stride 272B)
    const int SB = 272;
    int tid = threadIdx.x;
    int bx = blockIdx.x, by = blockIdx.y, bz = blockIdx.z;
    size_t nb = (size_t)bz*NN;

    #pragma unroll
    for (int a2 = 0; a2 < 6; a2++) {
        size_t rowbase = nb + (size_t)((a2 < 4) ? by : bx)*64;
        const ull* src = (const ull*)(spl + (size_t)a2*NTOT*DD) + rowbase*32;
        ull* dst = (ull*)(sm + a2*64*136);
        #pragma unroll
        for (int it = 0; it < 8; it++) {
            int idx = tid + it*256;
            int r = idx >> 5, q = idx & 31;
            dst[r*34 + q] = src[r*32 + q];
        }
    }
    __syncthreads();

    int l = tid & 31, w = tid >> 5;
    int mg = w >> 1, nh = w & 1;
    int row0 = mg*16, n0 = nh*32;
    u32 base = smaddr(sm);
    u32 bVh = base, bVl = base + 17408, bWh = base + 2*17408,
        bWl = base + 3*17408, bUh = base + 4*17408, bUl = base + 5*17408;

    float cV[4][4] = {}, cW[4][4] = {};
    #pragma unroll
    for (int k0 = 0; k0 < 128; k0 += 16) {
        u32 vh[4], vl[4], wh[4], wl[4], uh[8], ul[8];
        ldsm4(vh[0],vh[1],vh[2],vh[3], a_addr(bVh, row0, k0, l, SB));
        ldsm4(vl[0],vl[1],vl[2],vl[3], a_addr(bVl, row0, k0, l, SB));
        ldsm4(wh[0],wh[1],wh[2],wh[3], a_addr(bWh, row0, k0, l, SB));
        ldsm4(wl[0],wl[1],wl[2],wl[3], a_addr(bWl, row0, k0, l, SB));
        ldsm4(uh[0],uh[1],uh[2],uh[3], b_addr(bUh, n0,    k0, l, SB));
        ldsm4(uh[4],uh[5],uh[6],uh[7], b_addr(bUh, n0+16, k0, l, SB));
        ldsm4(ul[0],ul[1],ul[2],ul[3], b_addr(bUl, n0,    k0, l, SB));
        ldsm4(ul[4],ul[5],ul[6],ul[7], b_addr(bUl, n0+16, k0, l, SB));
        #pragma unroll
        for (int c = 0; c < 4; c++) {
            mma_bf16(cV[c], vh, uh[2*c], uh[2*c+1]);
            mma_bf16(cV[c], vh, ul[2*c], ul[2*c+1]);
            mma_bf16(cV[c], vl, uh[2*c], uh[2*c+1]);
            mma_bf16(cW[c], wh, uh[2*c], uh[2*c+1]);
            mma_bf16(cW[c], wh, ul[2*c], ul[2*c+1]);
            mma_bf16(cW[c], wl, uh[2*c], uh[2*c+1]);
        }
    }

    size_t N2 = (size_t)NN*NN, S = (size_t)BB*N2;
    int r1 = by*64 + row0 + (l >> 2);
    int ccl = 2*(l & 3);
    #pragma unroll
    for (int c = 0; c < 4; c++) {
        int col = bx*64 + n0 + c*8 + ccl;
        #pragma unroll
        for (int hr = 0; hr < 2; hr++) {
            int row = r1 + hr*8;
            size_t o = (size_t)bz*N2 + (size_t)row*NN + col;
            float lg0 = cV[c][hr*2+0], lg1 = cV[c][hr*2+1];
            *(float2*)(out + o) = make_float2(lg0, lg1);
            float p0 = __fdividef(1.f, 1.f + __expf(-lg0));
            float p1 = __fdividef(1.f, 1.f + __expf(-lg1));
            *(float2*)(out + S + o) = make_float2(p0, p1);
            float w0 = cW[c][hr*2+0], w1 = cW[c][hr*2+1];
            float s0 = fmaxf(w0,0.f) + __logf(1.f + __expf(-fabsf(w0)));
            float s1 = fmaxf(w1,0.f) + __logf(1.f + __expf(-fabsf(w1)));
            *(float2*)(out + 2*S + o) = make_float2(s0, s1);
        }
    }
}

// ---------------- launch -----------------------------------------------------
extern "C" void kernel_launch(void* const* d_in, const int* in_sizes, int n_in,
                              void* d_out, int out_size)
{
    const float* spikes   = (const float*)d_in[0];
    const float* coords   = (const float*)d_in[1];
    const float* conv_w   = (const float*)d_in[2];
    const float* conv_b   = (const float*)d_in[3];
    const float* fc_w     = (const float*)d_in[4];
    const float* fc_b     = (const float*)d_in[5];
    const float* local_w  = (const float*)d_in[6];
    const float* local_b  = (const float*)d_in[7];
    const float* k1_w     = (const float*)d_in[8];
    const float* k1_b     = (const float*)d_in[9];
    const float* k2_w     = (const float*)d_in[10];
    const float* k2_b     = (const float*)d_in[11];
    const float* k3_w     = (const float*)d_in[12];
    const float* k3_b     = (const float*)d_in[13];
    const float* W_logits = (const float*)d_in[14];
    const float* W_weight = (const float*)d_in[15];
    float* out = (float*)d_out;

    float *u0, *u1, *pb, *pp, *pl; int *pix, *ppos; ull *wpk, *pskey;
    __nv_bfloat16 *spl, *k2th, *k2tl;
    cudaGetSymbolAddress((void**)&u0,    g_u);
    cudaGetSymbolAddress((void**)&u1,    g_u2);
    cudaGetSymbolAddress((void**)&pb,    g_base);
    cudaGetSymbolAddress((void**)&pp,    g_proj);
    cudaGetSymbolAddress((void**)&pl,    g_loc);
    cudaGetSymbolAddress((void**)&pix,   g_idx);
    cudaGetSymbolAddress((void**)&ppos,  g_pos);
    cudaGetSymbolAddress((void**)&pskey, g_skey);
    cudaGetSymbolAddress((void**)&wpk,   g_wpack);
    cudaGetSymbolAddress((void**)&spl,   g_spl);
    cudaGetSymbolAddress((void**)&k2th,  g_k2th);
    cudaGetSymbolAddress((void**)&k2tl,  g_k2tl);

    cudaFuncSetAttribute(k_edge_mma, cudaFuncAttributeMaxDynamicSharedMemorySize, 55296);
    cudaFuncSetAttribute(k_dec_mma,  cudaFuncAttributeMaxDynamicSharedMemorySize, 104448);

    // packs
    WP wp;
    for (int lyr = 0; lyr < 3; lyr++) {
        wp.p[4*lyr+0] = k1_w + (size_t)lyr*258*DD + 2*DD;
        wp.p[4*lyr+1] = k1_w + (size_t)lyr*258*DD + 130*DD;
        wp.p[4*lyr+2] = local_w + (size_t)lyr*DD*DD;
        wp.p[4*lyr+3] = k2_w + (size_t)lyr*DD*DD;
    }
    wp.p[12] = W_logits;
    wp.p[13] = W_weight;
    wp.p[14] = fc_w;
    k_pack<<<dim3(32,15), 256>>>(wp, (float2*)wpk);
    k_packt<<<dim3(64,3), 256>>>(k2_w, k2th, k2tl);

    k_lift<<<NTOT, 128>>>(spikes, conv_w, conv_b, wpk + (size_t)14*8192, fc_b, u0);
    k_sort<<<BB, 1024>>>(coords, pskey, ppos);
    k_knn2<<<dim3(NN/256, BB), 256>>>(pskey, ppos, pix);

    float* ucur = u0;
    float* unext = u1;
    for (int lyr = 0; lyr < 3; lyr++) {
        const float* W1 = k1_w + (size_t)lyr*258*DD;
        k_node<3, true><<<NTOT/8, 256>>>(ucur,
            wpk + (size_t)(4*lyr+0)*8192, wpk + (size_t)(4*lyr+1)*8192,
            wpk + (size_t)(4*lyr+2)*8192,
            k1_b + lyr*DD, local_b + lyr*DD,
            W1, W1 + DD, coords,
            pb, pp, pl);
        k_edge_mma<<<NTOT/4, 256, 55296>>>(ucur, unext, pb, pp, pl, pix,
            k2th + (size_t)lyr*DD*DD, k2tl + (size_t)lyr*DD*DD,
            k2_b + lyr*DD, k3_w + (size_t)lyr*DD, k3_b + lyr);
        float* t = ucur; ucur = unext; unext = t;
    }

    k_node<2, false><<<NTOT/8, 256>>>(ucur,
        wpk + (size_t)12*8192, wpk + (size_t)13*8192, wpk,
        nullptr, nullptr, nullptr, nullptr, nullptr,
        pb, pp, pb);
    SP sp; sp.s[0] = pb; sp.s[1] = pp; sp.s[2] = ucur;
    k_split<<<dim3(NTOT*DD/1024, 3), 256>>>(sp, spl);
    k_dec_mma<<<dim3(NN/64, NN/64, BB), 256, 104448>>>(spl, out);
}

// round 8
// speedup vs baseline: 4.4955x; 1.1289x over previous
#include <cuda_runtime.h>
#include <cuda_bf16.h>
#include <math.h>

#define BB 2
#define NN 2048
#define TT 256
#define DD 128
#define KK 16
#define NTOT (BB*NN)

typedef unsigned long long ull;
typedef unsigned int u32;

// ---------------- scalar f32x2 helpers ----------------
__device__ __forceinline__ ull ffma2(ull a, ull b, ull c){
    ull d; asm("fma.rn.f32x2 %0, %1, %2, %3;" : "=l"(d) : "l"(a), "l"(b), "l"(c));
    return d;
}
__device__ __forceinline__ float usum(ull v){
    float lo, hi; asm("mov.b64 {%0,%1}, %2;" : "=f"(lo), "=f"(hi) : "l"(v));
    return lo + hi;
}

// ---------------- mma helpers ----------------
__device__ __forceinline__ u32 smaddr(const void* p){
    return (u32)__cvta_generic_to_shared(p);
}
__device__ __forceinline__ void ldsm4(u32 &r0,u32 &r1,u32 &r2,u32 &r3, u32 a){
    asm volatile("ldmatrix.sync.aligned.m8n8.x4.shared.b16 {%0,%1,%2,%3}, [%4];"
                 : "=r"(r0),"=r"(r1),"=r"(r2),"=r"(r3) : "r"(a));
}
__device__ __forceinline__ void mma_bf16(float* c, const u32* a, u32 b0, u32 b1){
    asm volatile("mma.sync.aligned.m16n8k16.row.col.f32.bf16.bf16.f32 "
        "{%0,%1,%2,%3},{%4,%5,%6,%7},{%8,%9},{%0,%1,%2,%3};"
        : "+f"(c[0]),"+f"(c[1]),"+f"(c[2]),"+f"(c[3])
        : "r"(a[0]),"r"(a[1]),"r"(a[2]),"r"(a[3]),"r"(b0),"r"(b1));
}
__device__ __forceinline__ u32 a_addr(u32 base, int row0, int k0, int lane, int sB){
    int g = lane >> 3, r = lane & 7;
    return base + (u32)((row0 + r + (g & 1)*8)*sB + (k0 + (g >> 1)*8)*2);
}
__device__ __forceinline__ void split_bf(float x, __nv_bfloat16 &h, __nv_bfloat16 &l){
    h = __float2bfloat16(x);
    l = __float2bfloat16(x - __bfloat162float(h));
}
__device__ __forceinline__ u32 bfpack(__nv_bfloat16 a, __nv_bfloat16 b){
    __nv_bfloat162 t; t.x = a; t.y = b; return *(u32*)&t;
}

// ---------------- scratch ----------------
__device__ float g_u   [NTOT*DD];
__device__ float g_u2  [NTOT*DD];
__device__ float g_base[NTOT*DD];
__device__ float g_proj[NTOT*DD];
__device__ float g_loc [NTOT*DD];
__device__ int   g_idx [NTOT*KK];
__device__ ull   g_skey[NTOT];
__device__ int   g_pos [NTOT];
__device__ __align__(16) ull g_wpack[64*128];                // fc_w k-pair pack
__device__ __align__(16) uint4 g_wfrag[14*4096];             // mma B-fragment packs
__device__ __align__(16) __nv_bfloat16 g_spl[6*NTOT*DD];     // vh,vl,wh,wl,uh,ul

// ---------------- Kernel 0a: fc_w k-pair pack (for k_lift) -------------------
__global__ void __launch_bounds__(256) k_packfc(const float* __restrict__ W,
                                                float2* __restrict__ dst){
    int i = blockIdx.x*256 + threadIdx.x;     // 0..8191
    int kp = i >> 7, c = i & 127;
    dst[i] = make_float2(W[(2*kp)*DD + c], W[(2*kp+1)*DD + c]);
}

// ---------------- Kernel 0b: weights -> mma B-fragment layout ----------------
// For W[k][n] row-major (128x128), produce per (n8-chunk c, k16-step s, lane l)
// uint4 {hi_b0, hi_b1, lo_b0, lo_b1} matching m16n8k16 col-major B fragments.
struct WF { const float* p[14]; };
__global__ void __launch_bounds__(128) k_packfrag(WF wf, uint4* __restrict__ dst){
    int m = blockIdx.y;
    const float* W = wf.p[m];
    int l = threadIdx.x & 31;
    int pair = blockIdx.x*4 + (threadIdx.x >> 5);   // 0..127 = c*8+s
    int c = pair >> 3, s = pair & 7;
    int kk = s*16 + 2*(l & 3);
    int nn = c*8 + (l >> 2);
    float w00 = W[(size_t)kk*DD + nn],     w01 = W[(size_t)(kk+1)*DD + nn];
    float w10 = W[(size_t)(kk+8)*DD + nn], w11 = W[(size_t)(kk+9)*DD + nn];
    __nv_bfloat16 h00,h01,h10,h11,l00,l01,l10,l11;
    split_bf(w00,h00,l00); split_bf(w01,h01,l01);
    split_bf(w10,h10,l10); split_bf(w11,h11,l11);
    uint4 q;
    q.x = bfpack(h00,h01); q.y = bfpack(h10,h11);
    q.z = bfpack(l00,l01); q.w = bfpack(l10,l11);
    dst[(size_t)m*4096 + pair*32 + l] = q;
}

// ---------------- Kernel 1: TemporalLift ----
__global__ void __launch_bounds__(128) k_lift(
    const float* __restrict__ spikes, const float* __restrict__ conv_w,
    const float* __restrict__ conv_b, const ull* __restrict__ fcp,
    const float* __restrict__ fc_b, float* __restrict__ u)
{
    __shared__ __align__(16) float sp[TT+8];
    __shared__ __align__(16) float xm[DD];
    int node = blockIdx.x;
    int h = threadIdx.x;
    const float* s = spikes + (size_t)node*TT;
    sp[2+h]      = s[h];
    sp[2+h+128]  = s[h+128];
    if (h < 2) sp[h] = 0.f;
    if (h < 6) sp[TT+2+h] = 0.f;
    __syncthreads();
    float w0 = conv_w[h*5+0], w1 = conv_w[h*5+1], w2 = conv_w[h*5+2],
          w3 = conv_w[h*5+3], w4 = conv_w[h*5+4];
    float bb = conv_b[h];
    float acc = 0.f;
    #pragma unroll 4
    for (int t = 0; t < TT; t += 4) {
        float4 a = *(const float4*)&sp[t];
        float4 b = *(const float4*)&sp[t+4];
        float o0 = fmaf(w4,b.x, fmaf(w3,a.w, fmaf(w2,a.z, fmaf(w1,a.y, fmaf(w0,a.x, bb)))));
        float o1 = fmaf(w4,b.y, fmaf(w3,b.x, fmaf(w2,a.w, fmaf(w1,a.z, fmaf(w0,a.y, bb)))));
        float o2 = fmaf(w4,b.z, fmaf(w3,b.y, fmaf(w2,b.x, fmaf(w1,a.w, fmaf(w0,a.z, bb)))));
        float o3 = fmaf(w4,b.w, fmaf(w3,b.z, fmaf(w2,b.y, fmaf(w1,b.x, fmaf(w0,a.w, bb)))));
        acc += fmaxf(o0,0.f) + fmaxf(o1,0.f) + fmaxf(o2,0.f) + fmaxf(o3,0.f);
    }
    xm[h] = acc * (1.f/(float)TT);
    __syncthreads();
    ull o2 = 0ull;
    #pragma unroll 8
    for (int kp = 0; kp < 64; kp++)
        o2 = ffma2(*(const ull*)&xm[2*kp], __ldg(&fcp[kp*DD + h]), o2);
    float o = usum(o2) + fc_b[h];
    u[(size_t)node*DD + h] = fmaxf(o, 0.f);
}

// ---------------- Kernel 2a: bitonic sort of (coord_bits<<32|idx) per batch ---
__global__ void __launch_bounds__(1024) k_sort(
    const float* __restrict__ coords, ull* __restrict__ skey, int* __restrict__ pos)
{
    __shared__ ull s[NN];
    int b = blockIdx.x;
    int t = threadIdx.x;
    const float* cb = coords + (size_t)b*NN;
    s[t]        = ((ull)__float_as_uint(cb[t])      << 32) | (u32)t;
    s[t + 1024] = ((ull)__float_as_uint(cb[t+1024]) << 32) | (u32)(t + 1024);
    __syncthreads();
    for (int k = 2; k <= NN; k <<= 1) {
        for (int j = k >> 1; j > 0; j >>= 1) {
            int i  = ((t & ~(j-1)) << 1) | (t & (j-1));
            int p2 = i | j;
            bool asc = ((i & k) == 0);
            ull a = s[i], c = s[p2];
            if ((a > c) == asc) { s[i] = c; s[p2] = a; }
            __syncthreads();
        }
    }
    #pragma unroll
    for (int q = 0; q < 2; q++) {
        int p = t + q*1024;
        ull v = s[p];
        skey[(size_t)b*NN + p] = v;
        pos[(size_t)b*NN + (int)(v & 0xffffffffull)] = p;
    }
}

// ---------------- Kernel 2b: kNN via two-pointer window in sorted order -------
__global__ void __launch_bounds__(256) k_knn2(
    const ull* __restrict__ skey, const int* __restrict__ pos, int* __restrict__ idx)
{
    __shared__ ull sk[NN];
    int b = blockIdx.y;
    for (int i = threadIdx.x; i < NN; i += 256) sk[i] = skey[(size_t)b*NN + i];
    __syncthreads();
    int i = blockIdx.x*256 + threadIdx.x;
    int p = pos[(size_t)b*NN + i];
    float ci = __uint_as_float((u32)(sk[p] >> 32));
    int lo = p, hi = p + 1;
    int* o = idx + ((size_t)b*NN + i)*KK;
    #pragma unroll
    for (int r = 0; r < KK; r++) {
        ull cl = ~0ull, ch = ~0ull;
        if (lo >= 0) {
            ull v = sk[lo];
            float d = __uint_as_float((u32)(v >> 32)) - ci;
            cl = ((ull)__float_as_uint(d*d) << 32) | (v & 0xffffffffull);
        }
        if (hi < NN) {
            ull v = sk[hi];
            float d = __uint_as_float((u32)(v >> 32)) - ci;
            ch = ((ull)__float_as_uint(d*d) << 32) | (v & 0xffffffffull);
        }
        if (cl <= ch) { o[r] = (int)(cl & 0xffffffffull); lo--; }
        else          { o[r] = (int)(ch & 0xffffffffull); hi++; }
    }
}

// ---------------- Kernel 3: node GEMMs via tensor cores ----------------------
// Block = 32 rows x 128 cols, up to 3 B matrices (fragment-packed in global).
// A (=X rows) split to bf16 hi/lo in smem; B frags via direct coalesced LDG.128.
template<int NMAT, bool EX, bool OUTBF>
__global__ void __launch_bounds__(256) k_node_mma(
    const float* __restrict__ X,
    const uint4* __restrict__ F0, const uint4* __restrict__ F1,
    const uint4* __restrict__ F2,
    const float* __restrict__ cb0, const float* __restrict__ cb2,
    const float* __restrict__ rv0, const float* __restrict__ rv1,
    const float* __restrict__ xs,
    float* __restrict__ Y0, float* __restrict__ Y1, float* __restrict__ Y2,
    __nv_bfloat16* __restrict__ spl)
{
    __shared__ __align__(16) __nv_bfloat16 sAh[32*136];
    __shared__ __align__(16) __nv_bfloat16 sAl[32*136];
    __shared__ float xc[32];
    int tid = threadIdx.x;
    int row0 = blockIdx.x*32;

    #pragma unroll
    for (int it = 0; it < 4; it++) {
        int idx = tid + it*256;
        int r = idx >> 5, q = idx & 31;
        float4 v = *(const float4*)(X + (size_t)(row0+r)*DD + q*4);
        __nv_bfloat16 h0,h1,h2,h3,l0,l1,l2,l3;
        split_bf(v.x,h0,l0); split_bf(v.y,h1,l1);
        split_bf(v.z,h2,l2); split_bf(v.w,h3,l3);
        *(u32*)&sAh[r*136 + q*4]     = bfpack(h0,h1);
        *(u32*)&sAh[r*136 + q*4 + 2] = bfpack(h2,h3);
        *(u32*)&sAl[r*136 + q*4]     = bfpack(l0,l1);
        *(u32*)&sAl[r*136 + q*4 + 2] = bfpack(l2,l3);
    }
    if (EX && tid < 32) xc[tid] = xs[row0 + tid];
    __syncthreads();

    int l = tid & 31, w = tid >> 5;
    int mg = w >> 2, nh = w & 3;
    int rw = mg*16;
    const uint4* Fs[3] = {F0, F1, (NMAT > 2) ? F2 : F0};
    float C[NMAT][4][4];
    #pragma unroll
    for (int m = 0; m < NMAT; m++)
        #pragma unroll
        for (int cc = 0; cc < 4; cc++)
            #pragma unroll
            for (int t = 0; t < 4; t++) C[m][cc][t] = 0.f;

    u32 bAh = smaddr(sAh), bAl = smaddr(sAl);
    #pragma unroll
    for (int s = 0; s < 8; s++) {
        int k0 = s*16;
        u32 ah[4], al[4];
        ldsm4(ah[0],ah[1],ah[2],ah[3], a_addr(bAh, rw, k0, l, 272));
        ldsm4(al[0],al[1],al[2],al[3], a_addr(bAl, rw, k0, l, 272));
        #pragma unroll
        for (int m = 0; m < NMAT; m++) {
            #pragma unroll
            for (int cc = 0; cc < 4; cc++) {
                uint4 q = __ldg(&Fs[m][((nh*4+cc)*8 + s)*32 + l]);
                mma_bf16(C[m][cc], ah, q.x, q.y);
                mma_bf16(C[m][cc], ah, q.z, q.w);
                mma_bf16(C[m][cc], al, q.x, q.y);
            }
        }
    }

    float* Ys[3] = {Y0, Y1, (NMAT > 2) ? Y2 : Y0};
    #pragma unroll
    for (int m = 0; m < NMAT; m++) {
        #pragma unroll
        for (int cc = 0; cc < 4; cc++) {
            int col = nh*32 + cc*8 + 2*(l & 3);
            #pragma unroll
            for (int hr = 0; hr < 2; hr++) {
                int r = rw + (l >> 2) + hr*8;
                float v0 = C[m][cc][hr*2], v1 = C[m][cc][hr*2+1];
                if (EX) {
                    float xv = xc[r];
                    if (m == 0) { v0 += cb0[col]   + xv*rv0[col];
                                  v1 += cb0[col+1] + xv*rv0[col+1]; }
                    if (m == 1) { v0 += xv*rv1[col]; v1 += xv*rv1[col+1]; }
                    if (m == 2) { v0 += cb2[col];    v1 += cb2[col+1]; }
                }
                if (OUTBF) {
                    __nv_bfloat16 h0,l0,h1,l1;
                    split_bf(v0,h0,l0); split_bf(v1,h1,l1);
                    size_t o = (size_t)(row0+r)*DD + col;
                    *(u32*)(spl + (size_t)(2*m  )*NTOT*DD + o) = bfpack(h0,h1);
                    *(u32*)(spl + (size_t)(2*m+1)*NTOT*DD + o) = bfpack(l0,l1);
                } else {
                    *(float2*)(Ys[m] + (size_t)(row0+r)*DD + col) = make_float2(v0,v1);
                }
            }
        }
    }
}

// ---------------- Kernel 0c: fp32 -> bf16 hi/lo split (u only) ----------------
__global__ void __launch_bounds__(256) k_split1(const float* __restrict__ s,
        __nv_bfloat16* __restrict__ H, __nv_bfloat16* __restrict__ L)
{
    int i = (blockIdx.x*256 + threadIdx.x)*4;
    float4 v = *(const float4*)(s + i);
    __nv_bfloat16 h0,h1,h2,h3,l0,l1,l2,l3;
    split_bf(v.x,h0,l0); split_bf(v.y,h1,l1); split_bf(v.z,h2,l2); split_bf(v.w,h3,l3);
    *(u32*)(H + i)     = bfpack(h0,h1);
    *(u32*)(H + i + 2) = bfpack(h2,h3);
    *(u32*)(L + i)     = bfpack(l0,l1);
    *(u32*)(L + i + 2) = bfpack(l2,l3);
}

// ---------------- Kernel 4: edge MLP via tensor cores ------------------------
// Block = 4 nodes (64 edges). h1 staged hi/lo in smem; k2 B-frags direct LDG.
__global__ void __launch_bounds__(256) k_edge_mma(
    const float* __restrict__ u_in, float* __restrict__ u_out,
    const float* __restrict__ base_, const float* __restrict__ proj,
    const float* __restrict__ loc, const int* __restrict__ idx,
    const uint4* __restrict__ F, const float* __restrict__ k2b,
    const float* __restrict__ k3w, const float* __restrict__ k3b)
{
    __shared__ __align__(16) __nv_bfloat16 sHh[64*136];
    __shared__ __align__(16) __nv_bfloat16 sHl[64*136];
    __shared__ __align__(16) float bss[4*DD];
    __shared__ int   js[64];
    __shared__ float kvp[64][2];
    __shared__ float kvv[64];

    int tid = threadIdx.x;
    int node0 = blockIdx.x*4;
    int bbase = node0 & ~(NN-1);
    if (tid < 128) ((float4*)bss)[tid] = ((const float4*)(base_ + (size_t)node0*DD))[tid];
    if (tid < 64) js[tid] = idx[node0*KK + tid];
    __syncthreads();

    #pragma unroll
    for (int it = 0; it < 8; it++) {
        int id2 = tid + it*256;
        int e = id2 >> 5, q = id2 & 31;
        int j = js[e];
        float4 p = *(const float4*)(proj + (size_t)(bbase+j)*DD + q*4);
        const float* bp = &bss[(e>>4)*DD + q*4];
        float h0 = fmaxf(p.x + bp[0], 0.f);
        float h1 = fmaxf(p.y + bp[1], 0.f);
        float h2 = fmaxf(p.z + bp[2], 0.f);
        float h3 = fmaxf(p.w + bp[3], 0.f);
        __nv_bfloat16 a0,a1,a2,a3,c0,c1,c2,c3;
        split_bf(h0,a0,c0); split_bf(h1,a1,c1); split_bf(h2,a2,c2); split_bf(h3,a3,c3);
        *(u32*)&sHh[e*136 + q*4]     = bfpack(a0,a1);
        *(u32*)&sHh[e*136 + q*4 + 2] = bfpack(a2,a3);
        *(u32*)&sHl[e*136 + q*4]     = bfpack(c0,c1);
        *(u32*)&sHl[e*136 + q*4 + 2] = bfpack(c2,c3);
    }
    __syncthreads();

    int l = tid & 31, w = tid >> 5;
    int mg = w >> 1, nh = w & 1;
    int rw = mg*16, n0 = nh*64;
    float C[8][4];
    #pragma unroll
    for (int cc = 0; cc < 8; cc++)
        #pragma unroll
        for (int t = 0; t < 4; t++) C[cc][t] = 0.f;

    u32 bH = smaddr(sHh), bL = smaddr(sHl);
    #pragma unroll
    for (int s = 0; s < 8; s++) {
        int k0 = s*16;
        u32 ah[4], al[4];
        ldsm4(ah[0],ah[1],ah[2],ah[3], a_addr(bH, rw, k0, l, 272));
        ldsm4(al[0],al[1],al[2],al[3], a_addr(bL, rw, k0, l, 272));
        #pragma unroll
        for (int cc = 0; cc < 8; cc++) {
            uint4 q = __ldg(&F[((nh*8+cc)*8 + s)*32 + l]);
            mma_bf16(C[cc], ah, q.x, q.y);
            mma_bf16(C[cc], ah, q.z, q.w);
            mma_bf16(C[cc], al, q.x, q.y);
        }
    }

    float pr0 = 0.f, pr1 = 0.f;
    int ccl = 2*(l & 3);
    #pragma unroll
    for (int c = 0; c < 8; c++) {
        int col = n0 + c*8 + ccl;
        float b20 = __ldg(k2b+col), b21 = __ldg(k2b+col+1);
        float k30 = __ldg(k3w+col), k31 = __ldg(k3w+col+1);
        pr0 += fmaxf(C[c][0]+b20,0.f)*k30 + fmaxf(C[c][1]+b21,0.f)*k31;
        pr1 += fmaxf(C[c][2]+b20,0.f)*k30 + fmaxf(C[c][3]+b21,0.f)*k31;
    }
    pr0 += __shfl_xor_sync(0xffffffffu, pr0, 1);
    pr0 += __shfl_xor_sync(0xffffffffu, pr0, 2);
    pr1 += __shfl_xor_sync(0xffffffffu, pr1, 1);
    pr1 += __shfl_xor_sync(0xffffffffu, pr1, 2);
    if ((l & 3) == 0) {
        kvp[rw + (l>>2)    ][nh] = pr0;
        kvp[rw + (l>>2) + 8][nh] = pr1;
    }
    __syncthreads();
    if (tid < 64) kvv[tid] = (kvp[tid][0] + kvp[tid][1] + k3b[0])*0.25f;
    __syncthreads();

    int d = tid & 127;
    #pragma unroll
    for (int gg = 0; gg < 4; gg += 2) {
        int g = gg + (tid >> 7);
        int n = node0 + g;
        float a = 0.f;
        #pragma unroll
        for (int kk = 0; kk < KK; kk++)
            a = fmaf(kvv[g*KK+kk], u_in[(size_t)(bbase+js[g*KK+kk])*DD + d], a);
        float o = loc[(size_t)n*DD + d] + a + u_in[(size_t)n*DD + d];
        u_out[(size_t)n*DD + d] = fmaxf(o, 0.f);
    }
}

// ---------------- Kernel 5: decoder 64x64 tile via tensor cores --------------
__global__ void __launch_bounds__(256) k_dec_mma(
    const __nv_bfloat16* __restrict__ spl, float* __restrict__ out)
{
    extern __shared__ __align__(16) unsigned char dynraw[];
    __nv_bfloat16* sm = (__nv_bfloat16*)dynraw;   // 6 tiles of 64 x 136
    const int SB = 272;
    int tid = threadIdx.x;
    int bx = blockIdx.x, by = blockIdx.y, bz = blockIdx.z;
    size_t nb = (size_t)bz*NN;

    #pragma unroll
    for (int a2 = 0; a2 < 6; a2++) {
        size_t rowbase = nb + (size_t)((a2 < 4) ? by : bx)*64;
        const ull* src = (const ull*)(spl + (size_t)a2*NTOT*DD) + rowbase*32;
        ull* dst = (ull*)(sm + a2*64*136);
        #pragma unroll
        for (int it = 0; it < 8; it++) {
            int idx = tid + it*256;
            int r = idx >> 5, q = idx & 31;
            dst[r*34 + q] = src[r*32 + q];
        }
    }
    __syncthreads();

    int l = tid & 31, w = tid >> 5;
    int mg = w >> 1, nh = w & 1;
    int row0 = mg*16, n0 = nh*32;
    u32 base = smaddr(sm);
    u32 bVh = base, bVl = base + 17408, bWh = base + 2*17408,
        bWl = base + 3*17408, bUh = base + 4*17408, bUl = base + 5*17408;

    float cV[4][4] = {}, cW[4][4] = {};
    #pragma unroll
    for (int k0 = 0; k0 < 128; k0 += 16) {
        u32 vh[4], vl[4], wh[4], wl[4], uh[8], ul[8];
        ldsm4(vh[0],vh[1],vh[2],vh[3], a_addr(bVh, row0, k0, l, SB));
        ldsm4(vl[0],vl[1],vl[2],vl[3], a_addr(bVl, row0, k0, l, SB));
        ldsm4(wh[0],wh[1],wh[2],wh[3], a_addr(bWh, row0, k0, l, SB));
        ldsm4(wl[0],wl[1],wl[2],wl[3], a_addr(bWl, row0, k0, l, SB));
        {
            int g = l >> 3, r = l & 7;
            u32 addr0 = bUh + (u32)((n0 + r + (g >> 1)*8)*SB + (k0 + (g & 1)*8)*2);
            u32 addr1 = bUh + (u32)((n0 + 16 + r + (g >> 1)*8)*SB + (k0 + (g & 1)*8)*2);
            ldsm4(uh[0],uh[1],uh[2],uh[3], addr0);
            ldsm4(uh[4],uh[5],uh[6],uh[7], addr1);
            u32 addr2 = bUl + (u32)((n0 + r + (g >> 1)*8)*SB + (k0 + (g & 1)*8)*2);
            u32 addr3 = bUl + (u32)((n0 + 16 + r + (g >> 1)*8)*SB + (k0 + (g & 1)*8)*2);
            ldsm4(ul[0],ul[1],ul[2],ul[3], addr2);
            ldsm4(ul[4],ul[5],ul[6],ul[7], addr3);
        }
        #pragma unroll
        for (int c = 0; c < 4; c++) {
            mma_bf16(cV[c], vh, uh[2*c], uh[2*c+1]);
            mma_bf16(cV[c], vh, ul[2*c], ul[2*c+1]);
            mma_bf16(cV[c], vl, uh[2*c], uh[2*c+1]);
            mma_bf16(cW[c], wh, uh[2*c], uh[2*c+1]);
            mma_bf16(cW[c], wh, ul[2*c], ul[2*c+1]);
            mma_bf16(cW[c], wl, uh[2*c], uh[2*c+1]);
        }
    }

    size_t N2 = (size_t)NN*NN, S = (size_t)BB*N2;
    int r1 = by*64 + row0 + (l >> 2);
    int ccl = 2*(l & 3);
    #pragma unroll
    for (int c = 0; c < 4; c++) {
        int col = bx*64 + n0 + c*8 + ccl;
        #pragma unroll
        for (int hr = 0; hr < 2; hr++) {
            int row = r1 + hr*8;
            size_t o = (size_t)bz*N2 + (size_t)row*NN + col;
            float lg0 = cV[c][hr*2+0], lg1 = cV[c][hr*2+1];
            *(float2*)(out + o) = make_float2(lg0, lg1);
            float p0 = __fdividef(1.f, 1.f + __expf(-lg0));
            float p1 = __fdividef(1.f, 1.f + __expf(-lg1));
            *(float2*)(out + S + o) = make_float2(p0, p1);
            float w0 = cW[c][hr*2+0], w1 = cW[c][hr*2+1];
            float s0 = fmaxf(w0,0.f) + __logf(1.f + __expf(-fabsf(w0)));
            float s1 = fmaxf(w1,0.f) + __logf(1.f + __expf(-fabsf(w1)));
            *(float2*)(out + 2*S + o) = make_float2(s0, s1);
        }
    }
}

// ---------------- launch -----------------------------------------------------
extern "C" void kernel_launch(void* const* d_in, const int* in_sizes, int n_in,
                              void* d_out, int out_size)
{
    const float* spikes   = (const float*)d_in[0];
    const float* coords   = (const float*)d_in[1];
    const float* conv_w   = (const float*)d_in[2];
    const float* conv_b   = (const float*)d_in[3];
    const float* fc_w     = (const float*)d_in[4];
    const float* fc_b     = (const float*)d_in[5];
    const float* local_w  = (const float*)d_in[6];
    const float* local_b  = (const float*)d_in[7];
    const float* k1_w     = (const float*)d_in[8];
    const float* k1_b     = (const float*)d_in[9];
    const float* k2_w     = (const float*)d_in[10];
    const float* k2_b     = (const float*)d_in[11];
    const float* k3_w     = (const float*)d_in[12];
    const float* k3_b     = (const float*)d_in[13];
    const float* W_logits = (const float*)d_in[14];
    const float* W_weight = (const float*)d_in[15];
    float* out = (float*)d_out;

    float *u0, *u1, *pb, *pp, *pl; int *pix, *ppos; ull *wpk, *pskey;
    __nv_bfloat16 *spl; uint4 *wfrag;
    cudaGetSymbolAddress((void**)&u0,    g_u);
    cudaGetSymbolAddress((void**)&u1,    g_u2);
    cudaGetSymbolAddress((void**)&pb,    g_base);
    cudaGetSymbolAddress((void**)&pp,    g_proj);
    cudaGetSymbolAddress((void**)&pl,    g_loc);
    cudaGetSymbolAddress((void**)&pix,   g_idx);
    cudaGetSymbolAddress((void**)&ppos,  g_pos);
    cudaGetSymbolAddress((void**)&pskey, g_skey);
    cudaGetSymbolAddress((void**)&wpk,   g_wpack);
    cudaGetSymbolAddress((void**)&spl,   g_spl);
    cudaGetSymbolAddress((void**)&wfrag, g_wfrag);

    cudaFuncSetAttribute(k_dec_mma, cudaFuncAttributeMaxDynamicSharedMemorySize, 104448);

    // fragment packs: per layer l: [4l+0]=Wui, [4l+1]=Wuj, [4l+2]=local, [4l+3]=k2
    //                 [12]=W_logits, [13]=W_weight
    WF wf;
    for (int lyr = 0; lyr < 3; lyr++) {
        wf.p[4*lyr+0] = k1_w + (size_t)lyr*258*DD + 2*DD;
        wf.p[4*lyr+1] = k1_w + (size_t)lyr*258*DD + 130*DD;
        wf.p[4*lyr+2] = local_w + (size_t)lyr*DD*DD;
        wf.p[4*lyr+3] = k2_w + (size_t)lyr*DD*DD;
    }
    wf.p[12] = W_logits;
    wf.p[13] = W_weight;
    k_packfrag<<<dim3(32,14), 128>>>(wf, wfrag);
    k_packfc<<<32, 256>>>(fc_w, (float2*)wpk);

    k_lift<<<NTOT, 128>>>(spikes, conv_w, conv_b, wpk, fc_b, u0);
    k_sort<<<BB, 1024>>>(coords, pskey, ppos);
    k_knn2<<<dim3(NN/256, BB), 256>>>(pskey, ppos, pix);

    float* ucur = u0;
    float* unext = u1;
    for (int lyr = 0; lyr < 3; lyr++) {
        const float* W1 = k1_w + (size_t)lyr*258*DD;
        k_node_mma<3, true, false><<<NTOT/32, 256>>>(ucur,
            wfrag + (size_t)(4*lyr+0)*4096, wfrag + (size_t)(4*lyr+1)*4096,
            wfrag + (size_t)(4*lyr+2)*4096,
            k1_b + lyr*DD, local_b + lyr*DD,
            W1, W1 + DD, coords,
            pb, pp, pl, nullptr);
        k_edge_mma<<<NTOT/4, 256>>>(ucur, unext, pb, pp, pl, pix,
            wfrag + (size_t)(4*lyr+3)*4096,
            k2_b + lyr*DD, k3_w + (size_t)lyr*DD, k3_b + lyr);
        float* t = ucur; ucur = unext; unext = t;
    }

    // decoder stage 1: v = u@W_logits, w = u@W_weight -> directly split bf16
    k_node_mma<2, false, true><<<NTOT/32, 256>>>(ucur,
        wfrag + (size_t)12*4096, wfrag + (size_t)13*4096, wfrag,
        nullptr, nullptr, nullptr, nullptr, nullptr,
        nullptr, nullptr, nullptr, spl);
    // split u only
    k_split1<<<NTOT*DD/1024, 256>>>(ucur, spl + (size_t)4*NTOT*DD,
                                    spl + (size_t)5*NTOT*DD);
    k_dec_mma<<<dim3(NN/64, NN/64, BB), 256, 104448>>>(spl, out);
}